// round 4
// baseline (speedup 1.0000x reference)
#include <cuda_runtime.h>
#include <cstdint>

// ---------------- problem constants ----------------
// conv1: 3 -> 128, 128x128 -> 64x64, k3 s2 p1
// conv2: 128 -> 256, 64x64 -> 32x32, k3 s2 p1  (input = relu(bn(conv1)), fused)
// pre:   256 -> 64 (1x1)
// VQ:    512 codes x 64 dims
// post:  64 -> 256 (1x1)
// dec1:  convT 256 -> 128, 32x32 -> 64x64, k3 s2 p1 op1
// dec2:  convT 128 -> 3,  64x64 -> 128x128, k3 s2 p1 op1 (input = relu(bn(dec1)), fused)

#define H1_ELEMS (64*128*64*64)
#define H2_ELEMS (64*256*32*32)
#define Z_ELEMS  (64*64*32*32)
#define D_ELEMS  (64*256*32*32)
#define D1_ELEMS (64*128*64*64)

#define RECON_ELEMS (64*3*128*128)
#define VQ_DIM 64
#define NCODE 512

__device__ float g_h1[H1_ELEMS];
__device__ float g_h2[H2_ELEMS];
__device__ float g_z[Z_ELEMS];
__device__ float g_q[Z_ELEMS];
__device__ float g_d[D_ELEMS];
__device__ float g_d1[D1_ELEMS];
__device__ float g_psum[128*64];
__device__ float g_psq[128*64];
__device__ float g_scale[128];
__device__ float g_shift[128];
__device__ float g_losspart[256];

// ---------------- conv1: 3->128, s2, 128->64 ----------------
// grid (4,4,64); block 256 = one thread per output px; weights float4 from smem.
__global__ void conv1_kernel(const float* __restrict__ x,
                             const float* __restrict__ w,
                             const float* __restrict__ bias,
                             float* __restrict__ out)
{
    __shared__ float w_s[128*28];     // padded stride 28 (16B aligned rows)
    __shared__ float in_s[3*33*33];
    int n = blockIdx.z;
    int OH0 = blockIdx.y * 16, OW0 = blockIdx.x * 16;
    int tid = threadIdx.x;

    for (int i = tid; i < 128*27; i += 256) {
        int co = i / 27, t = i - co*27;
        w_s[co*28 + t] = w[i];
    }
    for (int co = tid; co < 128; co += 256) w_s[co*28 + 27] = 0.f;

    int IH0 = OH0*2 - 1, IW0 = OW0*2 - 1;
    for (int i = tid; i < 3*33*33; i += 256) {
        int ci = i / 1089; int r = (i % 1089) / 33; int c = i % 33;
        int ih = IH0 + r, iw = IW0 + c;
        float v = 0.f;
        if (ih >= 0 && ih < 128 && iw >= 0 && iw < 128)
            v = x[((n*3 + ci)*128 + ih)*128 + iw];
        in_s[i] = v;
    }
    __syncthreads();

    int ty = tid >> 4, tx = tid & 15;
    float in_r[28];
#pragma unroll
    for (int ci = 0; ci < 3; ci++)
#pragma unroll
        for (int kh = 0; kh < 3; kh++)
#pragma unroll
            for (int kw = 0; kw < 3; kw++)
                in_r[ci*9 + kh*3 + kw] = in_s[ci*1089 + (ty*2+kh)*33 + (tx*2+kw)];
    in_r[27] = 0.f;

    int oh = OH0 + ty, ow = OW0 + tx;
    float* outp = out + (size_t)n*128*4096 + oh*64 + ow;
    const float4* w4p = reinterpret_cast<const float4*>(w_s);
    for (int co = 0; co < 128; co++) {
        float acc = bias[co];
#pragma unroll
        for (int u = 0; u < 7; u++) {
            float4 w4 = w4p[co*7 + u];
            acc += w4.x * in_r[u*4+0];
            acc += w4.y * in_r[u*4+1];
            acc += w4.z * in_r[u*4+2];
            acc += w4.w * in_r[u*4+3];
        }
        outp[(size_t)co*4096] = acc;
    }
}

// ---------------- BN stats (float4) / finalize ----------------
// x laid out (N, C, 4096). One channel per blockIdx.x, nblk partial blocks.
__global__ void bn_stats_kernel(const float* __restrict__ x,
                                float* __restrict__ psum, float* __restrict__ psq,
                                int C, int nblk)
{
    int c = blockIdx.x, blk = blockIdx.y;
    float s = 0.f, sq = 0.f;
    // per channel: 64 planes of 1024 float4
    int total4 = 64 * 1024;
    for (int i = blk*256 + threadIdx.x; i < total4; i += nblk*256) {
        int n = i >> 10, off = i & 1023;
        const float4* p = reinterpret_cast<const float4*>(x + ((size_t)(n*C + c))*4096);
        float4 v = p[off];
        s  += v.x + v.y + v.z + v.w;
        sq += v.x*v.x + v.y*v.y + v.z*v.z + v.w*v.w;
    }
    __shared__ float rs[256], rq[256];
    rs[threadIdx.x] = s; rq[threadIdx.x] = sq;
    __syncthreads();
    for (int o = 128; o > 0; o >>= 1) {
        if (threadIdx.x < o) { rs[threadIdx.x] += rs[threadIdx.x+o]; rq[threadIdx.x] += rq[threadIdx.x+o]; }
        __syncthreads();
    }
    if (threadIdx.x == 0) { psum[c*nblk + blk] = rs[0]; psq[c*nblk + blk] = rq[0]; }
}

__global__ void bn_finalize_kernel(const float* __restrict__ psum, const float* __restrict__ psq,
                                   const float* __restrict__ g, const float* __restrict__ b,
                                   float* __restrict__ scale, float* __restrict__ shift,
                                   int nblk, float inv_count)
{
    int c = threadIdx.x;
    float s = 0.f, sq = 0.f;
    for (int i = 0; i < nblk; i++) { s += psum[c*nblk + i]; sq += psq[c*nblk + i]; }
    float mean = s * inv_count;
    float var = sq * inv_count - mean*mean;
    float r = rsqrtf(var + 1e-5f);
    float sc = g[c] * r;
    scale[c] = sc;
    shift[c] = b[c] - mean * sc;
}

// ---------------- conv2: 128->256, s2, 64->32, fused BN+ReLU on input ----------------
// grid (coB=4, tile=16, n=64); block 256; thread: 4 ow x 4 co.
__global__ void conv2_kernel(const float* __restrict__ in,
                             const float* __restrict__ w,
                             const float* __restrict__ bias,
                             const float* __restrict__ scale,
                             const float* __restrict__ shift,
                             float* __restrict__ out)
{
    extern __shared__ float sm[];
    float* w_s  = sm;            // [ci16][t9][co64] = 9216
    float* in_s = sm + 9216;     // 16 * 17 * 17 = 4624
    float* sc_s = sm + 9216 + 4624;       // 128
    float* sh_s = sc_s + 128;             // 128
    int n = blockIdx.z;
    int coB = blockIdx.x;
    int tile = blockIdx.y;
    int OH0 = (tile >> 2) * 8, OW0 = (tile & 3) * 8;
    int tid = threadIdx.x;
    int pxg = tid & 15;
    int cog = tid >> 4;        // 0..15, 4 co each
    int r = pxg >> 1;
    int seg = pxg & 1;
    int IH0 = OH0*2 - 1, IW0 = OW0*2 - 1;

    for (int i = tid; i < 128; i += 256) { sc_s[i] = scale[i]; sh_s[i] = shift[i]; }

    float acc[4][4];
#pragma unroll
    for (int j = 0; j < 4; j++)
#pragma unroll
        for (int p = 0; p < 4; p++) acc[j][p] = 0.f;

    for (int ci0 = 0; ci0 < 128; ci0 += 16) {
        __syncthreads();
        // weights transposed: w_s[(ci*9 + t)*64 + co]
        for (int i = tid; i < 16*9*64; i += 256) {
            int ci = i / 576; int rem = i - ci*576; int t = rem >> 6; int co = rem & 63;
            w_s[i] = w[((size_t)(coB*64 + co)*128 + ci0 + ci)*9 + t];
        }
        for (int i = tid; i < 16*289; i += 256) {
            int ci = i / 289; int rr = (i % 289) / 17; int cc = i % 17;
            int ih = IH0 + rr, iw = IW0 + cc;
            float v = 0.f;
            if (ih >= 0 && ih < 64 && iw >= 0 && iw < 64) {
                float raw = in[((size_t)(n*128 + ci0 + ci)*64 + ih)*64 + iw];
                v = fmaxf(fmaf(raw, sc_s[ci0 + ci], sh_s[ci0 + ci]), 0.f);
            }
            in_s[i] = v;
        }
        __syncthreads();

        for (int ci = 0; ci < 16; ci++) {
            float in_r[3][9];
#pragma unroll
            for (int kh = 0; kh < 3; kh++)
#pragma unroll
                for (int q = 0; q < 9; q++)
                    in_r[kh][q] = in_s[ci*289 + (r*2 + kh)*17 + seg*8 + q];
#pragma unroll
            for (int kh = 0; kh < 3; kh++)
#pragma unroll
                for (int kw = 0; kw < 3; kw++) {
                    int t = kh*3 + kw;
                    float4 w4 = *reinterpret_cast<const float4*>(&w_s[(ci*9 + t)*64 + cog*4]);
                    float wv[4] = {w4.x, w4.y, w4.z, w4.w};
#pragma unroll
                    for (int j = 0; j < 4; j++)
#pragma unroll
                        for (int p = 0; p < 4; p++)
                            acc[j][p] += wv[j] * in_r[kh][p*2 + kw];
                }
        }
    }
    int oh = OH0 + r;
#pragma unroll
    for (int j = 0; j < 4; j++) {
        int co = coB*64 + cog*4 + j;
        float bv = bias[co];
#pragma unroll
        for (int p = 0; p < 4; p++) {
            int ow = OW0 + seg*4 + p;
            out[((size_t)(n*256 + co)*32 + oh)*32 + ow] = acc[j][p] + bv;
        }
    }
}

// ---------------- pre 1x1: 256->64 ----------------
// grid (4 s-tiles, 2 co-halves, 64 n); block 256; thread: 1 px, 32 co.
__global__ void pre_kernel(const float* __restrict__ in,
                           const float* __restrict__ w,
                           const float* __restrict__ bias,
                           float* __restrict__ out)
{
    __shared__ float w_t[256*32];   // [ci][co]
    int n = blockIdx.z, coH = blockIdx.y;
    int s = blockIdx.x * 256 + threadIdx.x;
    for (int i = threadIdx.x; i < 256*32; i += 256) {
        int ci = i >> 5, co = i & 31;
        w_t[i] = w[(size_t)(coH*32 + co)*256 + ci];
    }
    __syncthreads();
    float acc[32];
#pragma unroll
    for (int co = 0; co < 32; co++) acc[co] = 0.f;
    const float* ip = in + (size_t)n*256*1024 + s;
    const float4* w4p = reinterpret_cast<const float4*>(w_t);
    for (int ci = 0; ci < 256; ci++) {
        float v = ip[(size_t)ci*1024];
#pragma unroll
        for (int k = 0; k < 8; k++) {
            float4 w4 = w4p[ci*8 + k];
            acc[k*4+0] += w4.x * v;
            acc[k*4+1] += w4.y * v;
            acc[k*4+2] += w4.z * v;
            acc[k*4+3] += w4.w * v;
        }
    }
    float* op = out + (size_t)n*64*1024 + (size_t)coH*32*1024 + s;
#pragma unroll
    for (int co = 0; co < 32; co++) op[(size_t)co*1024] = acc[co] + bias[coH*32 + co];
}

// ---------------- VQ (float4 codebook) ----------------
__global__ void vq_kernel(const float* __restrict__ z,
                          const float* __restrict__ cb,
                          float* __restrict__ q,
                          float* __restrict__ idx_out,
                          float* __restrict__ losspart)
{
    extern __shared__ float sm[];
    float* cb_s = sm;                 // 512*64
    float* csq  = sm + NCODE*VQ_DIM;  // 512
    int tid = threadIdx.x;
    for (int i = tid; i < NCODE*VQ_DIM; i += 256) cb_s[i] = cb[i];
    __syncthreads();
    for (int k = tid; k < NCODE; k += 256) {
        float s = 0.f;
#pragma unroll
        for (int d = 0; d < VQ_DIM; d++) { float c = cb_s[k*VQ_DIM + d]; s += c*c; }
        csq[k] = s;
    }
    __syncthreads();

    int sidx = blockIdx.x * 256 + tid;
    int b = sidx >> 10, hw = sidx & 1023;
    const float* zp = z + (size_t)b*64*1024 + hw;
    float zv[VQ_DIM];
    float zsq = 0.f;
#pragma unroll
    for (int d = 0; d < VQ_DIM; d++) { zv[d] = zp[(size_t)d*1024]; zsq += zv[d]*zv[d]; }

    const float4* cb4 = reinterpret_cast<const float4*>(cb_s);
    float best = 3.4e38f; int bidx = 0;
    for (int k = 0; k < NCODE; k++) {
        float dot = 0.f;
#pragma unroll
        for (int u = 0; u < 16; u++) {
            float4 c4 = cb4[k*16 + u];
            dot += zv[u*4+0] * c4.x;
            dot += zv[u*4+1] * c4.y;
            dot += zv[u*4+2] * c4.z;
            dot += zv[u*4+3] * c4.w;
        }
        float d2 = zsq - 2.f*dot + csq[k];
        if (d2 < best) { best = d2; bidx = k; }
    }

    float lsum = 0.f;
    float* qp = q + (size_t)b*64*1024 + hw;
#pragma unroll
    for (int d = 0; d < VQ_DIM; d++) {
        float c = cb_s[bidx*VQ_DIM + d];
        qp[(size_t)d*1024] = c;
        float df = zv[d] - c;
        lsum += df*df;
    }
    idx_out[sidx] = (float)bidx;

    __shared__ float red[256];
    red[tid] = lsum; __syncthreads();
    for (int o = 128; o > 0; o >>= 1) {
        if (tid < o) red[tid] += red[tid + o];
        __syncthreads();
    }
    if (tid == 0) losspart[blockIdx.x] = red[0];
}

__global__ void loss_finalize_kernel(const float* __restrict__ losspart,
                                     float* __restrict__ out_losses)
{
    __shared__ float red[256];
    red[threadIdx.x] = losspart[threadIdx.x];
    __syncthreads();
    for (int o = 128; o > 0; o >>= 1) {
        if (threadIdx.x < o) red[threadIdx.x] += red[threadIdx.x + o];
        __syncthreads();
    }
    if (threadIdx.x == 0) {
        float m = red[0] / (65536.f * 64.f);
        out_losses[0] = m;
        out_losses[1] = m;
    }
}

// ---------------- post 1x1: 64->256 ----------------
// grid (4 s-tiles, 4 coB, 64 n); block 256; thread: 1 px, 64 co.
__global__ void post_kernel(const float* __restrict__ in,
                            const float* __restrict__ w,
                            const float* __restrict__ bias,
                            float* __restrict__ out)
{
    __shared__ float w_t[64*64];    // [ci][co]
    int n = blockIdx.z, coB = blockIdx.y;
    int s = blockIdx.x * 256 + threadIdx.x;
    for (int i = threadIdx.x; i < 64*64; i += 256) {
        int ci = i >> 6, co = i & 63;
        w_t[i] = w[(size_t)(coB*64 + co)*64 + ci];
    }
    __syncthreads();
    float acc[64];
#pragma unroll
    for (int co = 0; co < 64; co++) acc[co] = 0.f;
    const float* ip = in + (size_t)n*64*1024 + s;
    const float4* w4p = reinterpret_cast<const float4*>(w_t);
    for (int ci = 0; ci < 64; ci++) {
        float v = ip[(size_t)ci*1024];
#pragma unroll
        for (int k = 0; k < 16; k++) {
            float4 w4 = w4p[ci*16 + k];
            acc[k*4+0] += w4.x * v;
            acc[k*4+1] += w4.y * v;
            acc[k*4+2] += w4.z * v;
            acc[k*4+3] += w4.w * v;
        }
    }
    float* op = out + (size_t)n*256*1024 + (size_t)coB*64*1024 + s;
#pragma unroll
    for (int co = 0; co < 64; co++) op[(size_t)co*1024] = acc[co] + bias[coB*64 + co];
}

// ---------------- dec1 transpose conv: 256->128, 32->64 ----------------
// grid (coB=4, tile=16, n=64); block 256; parity-classed; thread: 4 px x 8 co.
__global__ void dec1_kernel(const float* __restrict__ in,
                            const float* __restrict__ w,   // (256,128,3,3)
                            const float* __restrict__ bias,
                            float* __restrict__ out)
{
    extern __shared__ float sm[];
    float* w_s  = sm;          // [ci32][t9][co32] = 9216
    float* in_s = sm + 9216;   // 32 * 9 * 9 = 2592
    int n = blockIdx.z, coB = blockIdx.x, tile = blockIdx.y;
    int OH0 = (tile >> 2) * 16, OW0 = (tile & 3) * 16;
    int IH0 = OH0 >> 1, IW0 = OW0 >> 1;
    int tid = threadIdx.x;
    int cls = tid >> 6;
    int pe_h = cls >> 1, pe_w = cls & 1;
    int cog = (tid >> 4) & 3;    // 8 co each
    int t3 = tid & 15;
    int r8 = t3 >> 1;
    int c2 = t3 & 1;

    float acc[8][4];
#pragma unroll
    for (int j = 0; j < 8; j++)
#pragma unroll
        for (int i = 0; i < 4; i++) acc[j][i] = 0.f;

    for (int ci0 = 0; ci0 < 256; ci0 += 32) {
        __syncthreads();
        // weights transposed: w_s[(ci*9 + t)*32 + co]
        for (int i = tid; i < 32*9*32; i += 256) {
            int ci = i / 288; int rem = i - ci*288; int t = rem >> 5; int co = rem & 31;
            w_s[i] = w[((size_t)(ci0 + ci)*128 + coB*32 + co)*9 + t];
        }
        for (int i = tid; i < 32*81; i += 256) {
            int ci = i / 81; int rr = (i % 81) / 9; int cc = i % 9;
            int ih = IH0 + rr, iw = IW0 + cc;
            float v = 0.f;
            if (ih < 32 && iw < 32)
                v = in[((size_t)(n*256 + ci0 + ci)*32 + ih)*32 + iw];
            in_s[i] = v;
        }
        __syncthreads();

        for (int ci = 0; ci < 32; ci++) {
            const float* base = &in_s[ci*81];
            float row0[5], row1[5];
#pragma unroll
            for (int qq = 0; qq < 5; qq++) {
                row0[qq] = base[r8*9 + c2*4 + qq];
                row1[qq] = base[(r8+1)*9 + c2*4 + qq];
            }
            auto do_tap = [&](int kh, int kw, const float* rowv, int off) {
                int t = kh*3 + kw;
                const float4* wp4 = reinterpret_cast<const float4*>(&w_s[(ci*9 + t)*32 + cog*8]);
                float4 wa = wp4[0], wb = wp4[1];
                float wv[8] = {wa.x, wa.y, wa.z, wa.w, wb.x, wb.y, wb.z, wb.w};
#pragma unroll
                for (int j = 0; j < 8; j++)
#pragma unroll
                    for (int i = 0; i < 4; i++)
                        acc[j][i] += wv[j] * rowv[i + off];
            };
            if (pe_h == 0) {
                if (pe_w == 0) { do_tap(1,1,row0,0); }
                else           { do_tap(1,0,row0,1); do_tap(1,2,row0,0); }
            } else {
                if (pe_w == 0) { do_tap(0,1,row1,0); do_tap(2,1,row0,0); }
                else           { do_tap(0,0,row1,1); do_tap(0,2,row1,0);
                                 do_tap(2,0,row0,1); do_tap(2,2,row0,0); }
            }
        }
    }
    int oh = OH0 + r8*2 + pe_h;
#pragma unroll
    for (int j = 0; j < 8; j++) {
        int co = coB*32 + cog*8 + j;
        float bv = bias[co];
#pragma unroll
        for (int i = 0; i < 4; i++) {
            int ow = OW0 + (c2*4 + i)*2 + pe_w;
            out[((size_t)(n*128 + co)*64 + oh)*64 + ow] = acc[j][i] + bv;
        }
    }
}

// ---------------- dec2 transpose conv: 128->3, 64->128, fused BN+ReLU in, tanh out ----------------
// grid (64 tiles, 64 n); block 256.
__global__ void dec2_kernel(const float* __restrict__ in,
                            const float* __restrict__ w,   // (128,3,3,3)
                            const float* __restrict__ bias,
                            const float* __restrict__ scale,
                            const float* __restrict__ shift,
                            float* __restrict__ out)
{
    extern __shared__ float sm[];
    float* w_s  = sm;           // 128*27 = 3456
    float* in_s = sm + 3456;    // 128*81 = 10368
    float* sc_s = sm + 3456 + 10368;  // 128
    float* sh_s = sc_s + 128;         // 128
    int n = blockIdx.y; int tile = blockIdx.x;
    int OH0 = (tile >> 3) * 16, OW0 = (tile & 7) * 16;
    int IH0 = OH0 >> 1, IW0 = OW0 >> 1;
    int tid = threadIdx.x;
    for (int i = tid; i < 3456; i += 256) w_s[i] = w[i];
    for (int i = tid; i < 128; i += 256) { sc_s[i] = scale[i]; sh_s[i] = shift[i]; }
    __syncthreads();
    for (int i = tid; i < 128*81; i += 256) {
        int ci = i / 81; int rr = (i % 81) / 9; int cc = i % 9;
        int ih = IH0 + rr, iw = IW0 + cc;
        float v = 0.f;
        if (ih < 64 && iw < 64) {
            float raw = in[((size_t)(n*128 + ci)*64 + ih)*64 + iw];
            v = fmaxf(fmaf(raw, sc_s[ci], sh_s[ci]), 0.f);
        }
        in_s[i] = v;
    }
    __syncthreads();

    int cls = tid >> 6; int pe_h = cls >> 1, pe_w = cls & 1;
    int t3 = tid & 63; int r8 = t3 >> 3, c8 = t3 & 7;
    float acc[3] = {0.f, 0.f, 0.f};

    for (int ci = 0; ci < 128; ci++) {
        const float* base = &in_s[ci*81];
        float v00 = base[r8*9 + c8];
        float v01 = base[r8*9 + c8 + 1];
        float v10 = base[(r8+1)*9 + c8];
        float v11 = base[(r8+1)*9 + c8 + 1];
        const float* wp = &w_s[ci*27];
        if (pe_h == 0) {
            if (pe_w == 0) {
#pragma unroll
                for (int co = 0; co < 3; co++) acc[co] += wp[co*9 + 4] * v00;
            } else {
#pragma unroll
                for (int co = 0; co < 3; co++) acc[co] += wp[co*9 + 3] * v01 + wp[co*9 + 5] * v00;
            }
        } else {
            if (pe_w == 0) {
#pragma unroll
                for (int co = 0; co < 3; co++) acc[co] += wp[co*9 + 1] * v10 + wp[co*9 + 7] * v00;
            } else {
#pragma unroll
                for (int co = 0; co < 3; co++)
                    acc[co] += wp[co*9 + 0] * v11 + wp[co*9 + 2] * v10
                             + wp[co*9 + 6] * v01 + wp[co*9 + 8] * v00;
            }
        }
    }
    int oh = OH0 + r8*2 + pe_h, ow = OW0 + c8*2 + pe_w;
#pragma unroll
    for (int co = 0; co < 3; co++)
        out[((size_t)(n*3 + co)*128 + oh)*128 + ow] = tanhf(acc[co] + bias[co]);
}

// ---------------- host launch ----------------
static float* sym_addr(const void* sym)
{
    void* p = nullptr;
    cudaGetSymbolAddress(&p, sym);
    return (float*)p;
}

extern "C" void kernel_launch(void* const* d_in, const int* in_sizes, int n_in,
                              void* d_out, int out_size)
{
    const float* x       = (const float*)d_in[0];
    const float* enc1_w  = (const float*)d_in[1];
    const float* enc1_b  = (const float*)d_in[2];
    const float* bn1_g   = (const float*)d_in[3];
    const float* bn1_b   = (const float*)d_in[4];
    const float* enc2_w  = (const float*)d_in[5];
    const float* enc2_b  = (const float*)d_in[6];
    const float* pre_w   = (const float*)d_in[7];
    const float* pre_b   = (const float*)d_in[8];
    const float* codebook= (const float*)d_in[9];
    const float* post_w  = (const float*)d_in[10];
    const float* post_b  = (const float*)d_in[11];
    const float* dec1_w  = (const float*)d_in[12];
    const float* dec1_b  = (const float*)d_in[13];
    const float* dbn1_g  = (const float*)d_in[14];
    const float* dbn1_b  = (const float*)d_in[15];
    const float* dec2_w  = (const float*)d_in[16];
    const float* dec2_b  = (const float*)d_in[17];

    float* out = (float*)d_out;
    float* out_losses = out + RECON_ELEMS;
    float* out_idx    = out + RECON_ELEMS + 2;

    float* h1 = sym_addr(g_h1);
    float* h2 = sym_addr(g_h2);
    float* z  = sym_addr(g_z);
    float* q  = sym_addr(g_q);
    float* d  = sym_addr(g_d);
    float* d1 = sym_addr(g_d1);
    float* psum = sym_addr(g_psum);
    float* psq  = sym_addr(g_psq);
    float* sc   = sym_addr(g_scale);
    float* sh   = sym_addr(g_shift);
    float* lp   = sym_addr(g_losspart);

    cudaFuncSetAttribute(conv2_kernel, cudaFuncAttributeMaxDynamicSharedMemorySize, 57344);
    cudaFuncSetAttribute(vq_kernel,    cudaFuncAttributeMaxDynamicSharedMemorySize, 133120);
    cudaFuncSetAttribute(dec1_kernel,  cudaFuncAttributeMaxDynamicSharedMemorySize, 47232);
    cudaFuncSetAttribute(dec2_kernel,  cudaFuncAttributeMaxDynamicSharedMemorySize, 57344);

    const float inv_cnt = 1.f / 262144.f;  // N*H*W for both BN layers
    const int NBLK = 32;

    // encoder
    conv1_kernel<<<dim3(4,4,64), 256>>>(x, enc1_w, enc1_b, h1);
    bn_stats_kernel<<<dim3(128,NBLK), 256>>>(h1, psum, psq, 128, NBLK);
    bn_finalize_kernel<<<1,128>>>(psum, psq, bn1_g, bn1_b, sc, sh, NBLK, inv_cnt);
    conv2_kernel<<<dim3(4,16,64), 256, 57344>>>(h1, enc2_w, enc2_b, sc, sh, h2);
    pre_kernel<<<dim3(4,2,64), 256>>>(h2, pre_w, pre_b, z);

    // VQ
    vq_kernel<<<256, 256, 133120>>>(z, codebook, q, out_idx, lp);
    loss_finalize_kernel<<<1,256>>>(lp, out_losses);

    // decoder
    post_kernel<<<dim3(4,4,64), 256>>>(q, post_w, post_b, d);
    dec1_kernel<<<dim3(4,16,64), 256, 47232>>>(d, dec1_w, dec1_b, d1);
    bn_stats_kernel<<<dim3(128,NBLK), 256>>>(d1, psum, psq, 128, NBLK);
    bn_finalize_kernel<<<1,128>>>(psum, psq, dbn1_g, dbn1_b, sc, sh, NBLK, inv_cnt);
    dec2_kernel<<<dim3(64,64), 256, 57344>>>(d1, dec2_w, dec2_b, sc, sh, out);

    (void)in_sizes; (void)n_in; (void)out_size;
}

// round 5
// speedup vs baseline: 1.0756x; 1.0756x over previous
#include <cuda_runtime.h>
#include <cstdint>

#define H1_ELEMS (64*128*64*64)
#define H2_ELEMS (64*256*32*32)
#define Z_ELEMS  (64*64*32*32)
#define D_ELEMS  (64*256*32*32)
#define D1_ELEMS (64*128*64*64)
#define RECON_ELEMS (64*3*128*128)
#define VQ_DIM 64
#define NCODE 512

__device__ float g_h1[H1_ELEMS];
__device__ float g_h2[H2_ELEMS];
__device__ float g_z[Z_ELEMS];
__device__ float g_q[Z_ELEMS];
__device__ float g_d[D_ELEMS];
__device__ float g_d1[D1_ELEMS];
__device__ float g_psum[128*64];
__device__ float g_psq[128*64];
__device__ float g_scale[128];
__device__ float g_shift[128];
__device__ float g_losspart[256];

typedef unsigned long long u64;
__device__ __forceinline__ u64 pack2(float a, float b) {
    u64 r; asm("mov.b64 %0, {%1,%2};" : "=l"(r) : "f"(a), "f"(b)); return r;
}
__device__ __forceinline__ u64 fma2(u64 a, u64 b, u64 c) {
    u64 d; asm("fma.rn.f32x2 %0, %1, %2, %3;" : "=l"(d) : "l"(a), "l"(b), "l"(c)); return d;
}
__device__ __forceinline__ u64 add2(u64 a, u64 b) {
    u64 d; asm("add.rn.f32x2 %0, %1, %2;" : "=l"(d) : "l"(a), "l"(b)); return d;
}
__device__ __forceinline__ float2 unpack2(u64 a) {
    float lo, hi; asm("mov.b64 {%0,%1}, %2;" : "=f"(lo), "=f"(hi) : "l"(a));
    return make_float2(lo, hi);
}

// ---------------- conv1: 3->128, s2 ----------------
__global__ void conv1_kernel(const float* __restrict__ x, const float* __restrict__ w,
                             const float* __restrict__ bias, float* __restrict__ out)
{
    __shared__ float w_s[128*28];
    __shared__ float in_s[3*33*33];
    int n = blockIdx.z;
    int OH0 = blockIdx.y * 16, OW0 = blockIdx.x * 16;
    int tid = threadIdx.x;
    for (int i = tid; i < 128*27; i += 256) { int co = i / 27, t = i - co*27; w_s[co*28 + t] = w[i]; }
    for (int co = tid; co < 128; co += 256) w_s[co*28 + 27] = 0.f;
    int IH0 = OH0*2 - 1, IW0 = OW0*2 - 1;
    for (int i = tid; i < 3*33*33; i += 256) {
        int ci = i / 1089; int r = (i % 1089) / 33; int c = i % 33;
        int ih = IH0 + r, iw = IW0 + c;
        float v = 0.f;
        if (ih >= 0 && ih < 128 && iw >= 0 && iw < 128) v = x[((n*3 + ci)*128 + ih)*128 + iw];
        in_s[i] = v;
    }
    __syncthreads();
    int ty = tid >> 4, tx = tid & 15;
    float in_r[28];
#pragma unroll
    for (int ci = 0; ci < 3; ci++)
#pragma unroll
        for (int kh = 0; kh < 3; kh++)
#pragma unroll
            for (int kw = 0; kw < 3; kw++)
                in_r[ci*9 + kh*3 + kw] = in_s[ci*1089 + (ty*2+kh)*33 + (tx*2+kw)];
    in_r[27] = 0.f;
    int oh = OH0 + ty, ow = OW0 + tx;
    float* outp = out + (size_t)n*128*4096 + oh*64 + ow;
    const float4* w4p = reinterpret_cast<const float4*>(w_s);
    for (int co = 0; co < 128; co++) {
        float acc = bias[co];
#pragma unroll
        for (int u = 0; u < 7; u++) {
            float4 w4 = w4p[co*7 + u];
            acc += w4.x*in_r[u*4] + w4.y*in_r[u*4+1] + w4.z*in_r[u*4+2] + w4.w*in_r[u*4+3];
        }
        outp[(size_t)co*4096] = acc;
    }
}

// ---------------- BN stats / finalize ----------------
__global__ void bn_stats_kernel(const float* __restrict__ x, float* __restrict__ psum,
                                float* __restrict__ psq, int C, int nblk)
{
    int c = blockIdx.x, blk = blockIdx.y;
    float s = 0.f, sq = 0.f;
    int total4 = 64 * 1024;
    for (int i = blk*256 + threadIdx.x; i < total4; i += nblk*256) {
        int n = i >> 10, off = i & 1023;
        const float4* p = reinterpret_cast<const float4*>(x + ((size_t)(n*C + c))*4096);
        float4 v = p[off];
        s  += v.x + v.y + v.z + v.w;
        sq += v.x*v.x + v.y*v.y + v.z*v.z + v.w*v.w;
    }
    __shared__ float rs[256], rq[256];
    rs[threadIdx.x] = s; rq[threadIdx.x] = sq;
    __syncthreads();
    for (int o = 128; o > 0; o >>= 1) {
        if (threadIdx.x < o) { rs[threadIdx.x] += rs[threadIdx.x+o]; rq[threadIdx.x] += rq[threadIdx.x+o]; }
        __syncthreads();
    }
    if (threadIdx.x == 0) { psum[c*nblk + blk] = rs[0]; psq[c*nblk + blk] = rq[0]; }
}

__global__ void bn_finalize_kernel(const float* __restrict__ psum, const float* __restrict__ psq,
                                   const float* __restrict__ g, const float* __restrict__ b,
                                   float* __restrict__ scale, float* __restrict__ shift,
                                   int nblk, float inv_count)
{
    int c = threadIdx.x;
    float s = 0.f, sq = 0.f;
    for (int i = 0; i < nblk; i++) { s += psum[c*nblk + i]; sq += psq[c*nblk + i]; }
    float mean = s * inv_count;
    float var = sq * inv_count - mean*mean;
    float r = rsqrtf(var + 1e-5f);
    float sc = g[c] * r;
    scale[c] = sc;
    shift[c] = b[c] - mean * sc;
}

// ---------------- conv2: 128->256, s2, fused BN+ReLU in, f32x2 ----------------
// grid (coB=4, tile=8 [4 oh-blk x 2 ow-blk], n=64); block 256 = 8 warps (co-groups).
__global__ void __launch_bounds__(256, 2) conv2_kernel(
        const float* __restrict__ in, const float* __restrict__ w,
        const float* __restrict__ bias, const float* __restrict__ scale,
        const float* __restrict__ shift, float* __restrict__ out)
{
    extern __shared__ float sm[];
    float* w_s  = sm;                 // [8ci][9t][64co] = 4608
    float* in_s = sm + 4608;          // [8ci][17*35] = 4760
    float* sc_s = sm + 9368;          // 128
    float* sh_s = sm + 9496;          // 128
    int n = blockIdx.z, coB = blockIdx.x;
    int OH0 = (blockIdx.y >> 1) * 8, OW0 = (blockIdx.y & 1) * 16;
    int tid = threadIdx.x;
    int cog = tid >> 5, lane = tid & 31;
    int r = lane >> 2, seg = lane & 3;
    int IH0 = OH0*2 - 1, IW0 = OW0*2 - 1;

    for (int i = tid; i < 128; i += 256) { sc_s[i] = scale[i]; sh_s[i] = shift[i]; }

    u64 acc[4][4];
#pragma unroll
    for (int a = 0; a < 4; a++)
#pragma unroll
        for (int b = 0; b < 4; b++) acc[a][b] = 0ull;

    for (int ci0 = 0; ci0 < 128; ci0 += 8) {
        __syncthreads();
        for (int i = tid; i < 4608; i += 256) {
            int ci = i / 576; int rem = i - ci*576; int t = rem >> 6; int co = rem & 63;
            w_s[i] = w[((size_t)(coB*64 + co)*128 + ci0 + ci)*9 + t];
        }
        for (int i = tid; i < 4760; i += 256) {
            int ci = i / 595; int rem = i - ci*595; int rr = rem / 35; int cc = rem - rr*35;
            int ih = IH0 + rr, iw = IW0 + cc;
            float v = 0.f;
            if (cc < 33 && ih >= 0 && ih < 64 && iw >= 0 && iw < 64) {
                float raw = in[((size_t)(n*128 + ci0 + ci)*64 + ih)*64 + iw];
                v = fmaxf(fmaf(raw, sc_s[ci0 + ci], sh_s[ci0 + ci]), 0.f);
            }
            in_s[i] = v;
        }
        __syncthreads();
#pragma unroll 2
        for (int ci = 0; ci < 8; ci++) {
            const float* ib = in_s + ci*595;
            const float* wb = w_s + ci*576 + cog*8;
#pragma unroll
            for (int kh = 0; kh < 3; kh++) {
                int base = (2*r + kh)*35 + seg*8;
                u64 pv[9];
#pragma unroll
                for (int q = 0; q < 9; q++) { float v = ib[base + q]; pv[q] = pack2(v, v); }
#pragma unroll
                for (int kw = 0; kw < 3; kw++) {
                    const float* wt = wb + (kh*3 + kw)*64;
                    ulonglong2 wA = *reinterpret_cast<const ulonglong2*>(wt);
                    ulonglong2 wB = *reinterpret_cast<const ulonglong2*>(wt + 4);
#pragma unroll
                    for (int p = 0; p < 4; p++) {
                        u64 v = pv[kw + 2*p];
                        acc[0][p] = fma2(wA.x, v, acc[0][p]);
                        acc[1][p] = fma2(wA.y, v, acc[1][p]);
                        acc[2][p] = fma2(wB.x, v, acc[2][p]);
                        acc[3][p] = fma2(wB.y, v, acc[3][p]);
                    }
                }
            }
        }
    }
    int oh = OH0 + r;
#pragma unroll
    for (int cp = 0; cp < 4; cp++) {
        int co0 = coB*64 + cog*8 + cp*2;
        float b0 = bias[co0], b1 = bias[co0+1];
        float2 v0 = unpack2(acc[cp][0]), v1 = unpack2(acc[cp][1]);
        float2 v2 = unpack2(acc[cp][2]), v3 = unpack2(acc[cp][3]);
        size_t base0 = ((size_t)(n*256 + co0)*32 + oh)*32 + OW0 + seg*4;
        *reinterpret_cast<float4*>(out + base0) = make_float4(v0.x+b0, v1.x+b0, v2.x+b0, v3.x+b0);
        *reinterpret_cast<float4*>(out + base0 + 1024) = make_float4(v0.y+b1, v1.y+b1, v2.y+b1, v3.y+b1);
    }
}

// ---------------- pre 1x1: 256->64, f32x2 ----------------
__global__ void pre_kernel(const float* __restrict__ in, const float* __restrict__ w,
                           const float* __restrict__ bias, float* __restrict__ out)
{
    __shared__ float w_t[256*32];   // [ci][co]
    int n = blockIdx.z, coH = blockIdx.y;
    int s = blockIdx.x * 256 + threadIdx.x;
    for (int i = threadIdx.x; i < 256*32; i += 256) {
        int ci = i >> 5, co = i & 31;
        w_t[i] = w[(size_t)(coH*32 + co)*256 + ci];
    }
    __syncthreads();
    u64 acc[16];
#pragma unroll
    for (int k = 0; k < 16; k++) acc[k] = 0ull;
    const float* ip = in + (size_t)n*256*1024 + s;
#pragma unroll 4
    for (int ci = 0; ci < 256; ci++) {
        float v = ip[(size_t)ci*1024];
        u64 pv = pack2(v, v);
        const ulonglong2* wp = reinterpret_cast<const ulonglong2*>(w_t + ci*32);
#pragma unroll
        for (int k = 0; k < 8; k++) {
            ulonglong2 ww = wp[k];
            acc[2*k]   = fma2(ww.x, pv, acc[2*k]);
            acc[2*k+1] = fma2(ww.y, pv, acc[2*k+1]);
        }
    }
    float* op = out + (size_t)n*64*1024 + (size_t)coH*32*1024 + s;
#pragma unroll
    for (int k = 0; k < 16; k++) {
        float2 v = unpack2(acc[k]);
        op[(size_t)(2*k  )*1024] = v.x + bias[coH*32 + 2*k];
        op[(size_t)(2*k+1)*1024] = v.y + bias[coH*32 + 2*k+1];
    }
}

// ---------------- VQ (f32x2) ----------------
__global__ void vq_kernel(const float* __restrict__ z, const float* __restrict__ cb,
                          float* __restrict__ q, float* __restrict__ idx_out,
                          float* __restrict__ losspart)
{
    extern __shared__ float sm[];
    float* cb_s = sm;
    float* csq  = sm + NCODE*VQ_DIM;
    int tid = threadIdx.x;
    for (int i = tid; i < NCODE*VQ_DIM; i += 256) cb_s[i] = cb[i];
    __syncthreads();
    for (int k = tid; k < NCODE; k += 256) {
        float s = 0.f;
#pragma unroll
        for (int d = 0; d < VQ_DIM; d++) { float c = cb_s[k*VQ_DIM + d]; s += c*c; }
        csq[k] = s;
    }
    __syncthreads();

    int sidx = blockIdx.x * 256 + tid;
    int b = sidx >> 10, hw = sidx & 1023;
    const float* zp = z + (size_t)b*64*1024 + hw;
    u64 zv2[32];
    float zsq = 0.f;
#pragma unroll
    for (int u = 0; u < 32; u++) {
        float a = zp[(size_t)(2*u)*1024];
        float bb = zp[(size_t)(2*u+1)*1024];
        zsq += a*a + bb*bb;
        zv2[u] = pack2(a, bb);
    }

    float best = 3.4e38f; int bidx = 0;
    for (int k = 0; k < NCODE; k++) {
        const ulonglong2* cp2 = reinterpret_cast<const ulonglong2*>(cb_s + k*VQ_DIM);
        u64 d0 = 0ull, d1 = 0ull, d2 = 0ull, d3 = 0ull;
#pragma unroll
        for (int u = 0; u < 8; u++) {
            ulonglong2 ca = cp2[2*u], cbv = cp2[2*u+1];
            d0 = fma2(ca.x,  zv2[4*u],   d0);
            d1 = fma2(ca.y,  zv2[4*u+1], d1);
            d2 = fma2(cbv.x, zv2[4*u+2], d2);
            d3 = fma2(cbv.y, zv2[4*u+3], d3);
        }
        float2 dd = unpack2(add2(add2(d0, d1), add2(d2, d3)));
        float dot = dd.x + dd.y;
        float dist = zsq - 2.f*dot + csq[k];
        if (dist < best) { best = dist; bidx = k; }
    }

    float lsum = 0.f;
    float* qp = q + (size_t)b*64*1024 + hw;
#pragma unroll
    for (int u = 0; u < 32; u++) {
        float c0 = cb_s[bidx*VQ_DIM + 2*u];
        float c1 = cb_s[bidx*VQ_DIM + 2*u+1];
        qp[(size_t)(2*u)*1024]   = c0;
        qp[(size_t)(2*u+1)*1024] = c1;
        float2 zz = unpack2(zv2[u]);
        float df0 = zz.x - c0, df1 = zz.y - c1;
        lsum += df0*df0 + df1*df1;
    }
    idx_out[sidx] = (float)bidx;

    __shared__ float red[256];
    red[tid] = lsum; __syncthreads();
    for (int o = 128; o > 0; o >>= 1) {
        if (tid < o) red[tid] += red[tid + o];
        __syncthreads();
    }
    if (tid == 0) losspart[blockIdx.x] = red[0];
}

__global__ void loss_finalize_kernel(const float* __restrict__ losspart,
                                     float* __restrict__ out_losses)
{
    __shared__ float red[256];
    red[threadIdx.x] = losspart[threadIdx.x];
    __syncthreads();
    for (int o = 128; o > 0; o >>= 1) {
        if (threadIdx.x < o) red[threadIdx.x] += red[threadIdx.x + o];
        __syncthreads();
    }
    if (threadIdx.x == 0) {
        float m = red[0] / (65536.f * 64.f);
        out_losses[0] = m;
        out_losses[1] = m;
    }
}

// ---------------- post 1x1: 64->256, f32x2 ----------------
__global__ void post_kernel(const float* __restrict__ in, const float* __restrict__ w,
                            const float* __restrict__ bias, float* __restrict__ out)
{
    __shared__ float w_t[64*64];    // [ci][co]
    int n = blockIdx.z, coB = blockIdx.y;
    int s = blockIdx.x * 256 + threadIdx.x;
    for (int i = threadIdx.x; i < 64*64; i += 256) {
        int ci = i >> 6, co = i & 63;
        w_t[i] = w[(size_t)(coB*64 + co)*64 + ci];
    }
    __syncthreads();
    u64 acc[32];
#pragma unroll
    for (int k = 0; k < 32; k++) acc[k] = 0ull;
    const float* ip = in + (size_t)n*64*1024 + s;
#pragma unroll 2
    for (int ci = 0; ci < 64; ci++) {
        float v = ip[(size_t)ci*1024];
        u64 pv = pack2(v, v);
        const ulonglong2* wp = reinterpret_cast<const ulonglong2*>(w_t + ci*64);
#pragma unroll
        for (int k = 0; k < 16; k++) {
            ulonglong2 ww = wp[k];
            acc[2*k]   = fma2(ww.x, pv, acc[2*k]);
            acc[2*k+1] = fma2(ww.y, pv, acc[2*k+1]);
        }
    }
    float* op = out + (size_t)n*256*1024 + (size_t)coB*64*1024 + s;
#pragma unroll
    for (int k = 0; k < 32; k++) {
        float2 v = unpack2(acc[k]);
        op[(size_t)(2*k  )*1024] = v.x + bias[coB*64 + 2*k];
        op[(size_t)(2*k+1)*1024] = v.y + bias[coB*64 + 2*k+1];
    }
}

// ---------------- dec1 transpose conv 256->128, quad-centric, f32x2 ----------------
// grid (coB=4, tile=16, n=64); block 256 = 8 warps (4 co each = 2 co-pairs).
// lane: qy=lane>>2 (quad row 0..7), qxh=lane&3; quads at qx=qxh and qxh+4.
__global__ void __launch_bounds__(256, 2) dec1_kernel(
        const float* __restrict__ in, const float* __restrict__ w,   // (256,128,3,3)
        const float* __restrict__ bias, float* __restrict__ out)
{
    __shared__ float w_s[2304];   // [8ci][9t][32co]
    __shared__ float in_s[800];   // [8ci][9r x stride 11], ci stride 100
    int n = blockIdx.z, coB = blockIdx.x, tile = blockIdx.y;
    int OH0 = (tile >> 2) * 16, OW0 = (tile & 3) * 16;
    int IH0 = OH0 >> 1, IW0 = OW0 >> 1;
    int tid = threadIdx.x;
    int wid = tid >> 5, lane = tid & 31;
    int qy = lane >> 2, qxh = lane & 3;

    u64 acc[16];   // [cp2][qd2][px4]
#pragma unroll
    for (int i = 0; i < 16; i++) acc[i] = 0ull;

    for (int ci0 = 0; ci0 < 256; ci0 += 8) {
        __syncthreads();
        for (int i = tid; i < 2304; i += 256) {
            int ci = i / 288; int rem = i - ci*288; int t = rem >> 5; int co = rem & 31;
            w_s[i] = w[((size_t)(ci0 + ci)*128 + coB*32 + co)*9 + t];
        }
        for (int i = tid; i < 648; i += 256) {
            int ci = i / 81; int rem = i - ci*81; int rr = rem / 9; int cc = rem - rr*9;
            int ih = IH0 + rr, iw = IW0 + cc;
            float v = 0.f;
            if (ih < 32 && iw < 32) v = in[((size_t)(n*256 + ci0 + ci)*32 + ih)*32 + iw];
            in_s[ci*100 + rr*11 + cc] = v;
        }
        __syncthreads();
#pragma unroll 2
        for (int ci = 0; ci < 8; ci++) {
            const float* ib = in_s + ci*100 + qy*11 + qxh;
            float A00 = ib[0],  A01 = ib[1],  A10 = ib[11], A11 = ib[12];
            float B00 = ib[4],  B01 = ib[5],  B10 = ib[15], B11 = ib[16];
            u64 a00 = pack2(A00,A00), a01 = pack2(A01,A01), a10 = pack2(A10,A10), a11 = pack2(A11,A11);
            u64 b00 = pack2(B00,B00), b01 = pack2(B01,B01), b10 = pack2(B10,B10), b11 = pack2(B11,B11);
            const float* wb = w_s + ci*288 + wid*4;
            auto tap = [&](int t, u64 vA, u64 vB, int px) {
                ulonglong2 wv = *reinterpret_cast<const ulonglong2*>(wb + t*32);
                acc[px]      = fma2(wv.x, vA, acc[px]);
                acc[4 + px]  = fma2(wv.x, vB, acc[4 + px]);
                acc[8 + px]  = fma2(wv.y, vA, acc[8 + px]);
                acc[12 + px] = fma2(wv.y, vB, acc[12 + px]);
            };
            tap(4, a00, b00, 0);                          // out00: w(1,1)*v00
            tap(3, a01, b01, 1); tap(5, a00, b00, 1);     // out01: w(1,0)*v01 + w(1,2)*v00
            tap(1, a10, b10, 2); tap(7, a00, b00, 2);     // out10: w(0,1)*v10 + w(2,1)*v00
            tap(0, a11, b11, 3); tap(2, a10, b10, 3);     // out11: w(0,0)*v11 + w(0,2)*v10
            tap(6, a01, b01, 3); tap(8, a00, b00, 3);     //        + w(2,0)*v01 + w(2,2)*v00
        }
    }
    int oh0 = OH0 + qy*2;
#pragma unroll
    for (int cp = 0; cp < 2; cp++) {
        int co0 = coB*32 + wid*4 + cp*2;
        float b0 = bias[co0], b1 = bias[co0+1];
#pragma unroll
        for (int qd = 0; qd < 2; qd++) {
            int ow0 = OW0 + (qxh + qd*4)*2;
            float2 p0 = unpack2(acc[cp*8 + qd*4 + 0]);
            float2 p1 = unpack2(acc[cp*8 + qd*4 + 1]);
            float2 p2 = unpack2(acc[cp*8 + qd*4 + 2]);
            float2 p3 = unpack2(acc[cp*8 + qd*4 + 3]);
            float* o0 = out + ((size_t)(n*128 + co0)*64 + oh0)*64 + ow0;
            float* o1 = out + ((size_t)(n*128 + co0+1)*64 + oh0)*64 + ow0;
            *reinterpret_cast<float2*>(o0)      = make_float2(p0.x + b0, p1.x + b0);
            *reinterpret_cast<float2*>(o0 + 64) = make_float2(p2.x + b0, p3.x + b0);
            *reinterpret_cast<float2*>(o1)      = make_float2(p0.y + b1, p1.y + b1);
            *reinterpret_cast<float2*>(o1 + 64) = make_float2(p2.y + b1, p3.y + b1);
        }
    }
}

// ---------------- dec2 transpose conv 128->3, fused BN+ReLU in, tanh out ----------------
__global__ void dec2_kernel(const float* __restrict__ in, const float* __restrict__ w,
                            const float* __restrict__ bias, const float* __restrict__ scale,
                            const float* __restrict__ shift, float* __restrict__ out)
{
    extern __shared__ float sm[];
    float* w_s  = sm;                 // 3456
    float* in_s = sm + 3456;          // 10368
    float* sc_s = sm + 13824;         // 128
    float* sh_s = sm + 13952;         // 128
    int n = blockIdx.y; int tile = blockIdx.x;
    int OH0 = (tile >> 3) * 16, OW0 = (tile & 7) * 16;
    int IH0 = OH0 >> 1, IW0 = OW0 >> 1;
    int tid = threadIdx.x;
    for (int i = tid; i < 3456; i += 256) w_s[i] = w[i];
    for (int i = tid; i < 128; i += 256) { sc_s[i] = scale[i]; sh_s[i] = shift[i]; }
    __syncthreads();
    for (int i = tid; i < 128*81; i += 256) {
        int ci = i / 81; int rr = (i % 81) / 9; int cc = i % 9;
        int ih = IH0 + rr, iw = IW0 + cc;
        float v = 0.f;
        if (ih < 64 && iw < 64) {
            float raw = in[((size_t)(n*128 + ci)*64 + ih)*64 + iw];
            v = fmaxf(fmaf(raw, sc_s[ci], sh_s[ci]), 0.f);
        }
        in_s[i] = v;
    }
    __syncthreads();

    int cls = tid >> 6; int pe_h = cls >> 1, pe_w = cls & 1;
    int t3 = tid & 63; int r8 = t3 >> 3, c8 = t3 & 7;
    float acc[3] = {0.f, 0.f, 0.f};
    for (int ci = 0; ci < 128; ci++) {
        const float* base = &in_s[ci*81];
        float v00 = base[r8*9 + c8];
        float v01 = base[r8*9 + c8 + 1];
        float v10 = base[(r8+1)*9 + c8];
        float v11 = base[(r8+1)*9 + c8 + 1];
        const float* wp = &w_s[ci*27];
        if (pe_h == 0) {
            if (pe_w == 0) {
#pragma unroll
                for (int co = 0; co < 3; co++) acc[co] += wp[co*9 + 4] * v00;
            } else {
#pragma unroll
                for (int co = 0; co < 3; co++) acc[co] += wp[co*9 + 3] * v01 + wp[co*9 + 5] * v00;
            }
        } else {
            if (pe_w == 0) {
#pragma unroll
                for (int co = 0; co < 3; co++) acc[co] += wp[co*9 + 1] * v10 + wp[co*9 + 7] * v00;
            } else {
#pragma unroll
                for (int co = 0; co < 3; co++)
                    acc[co] += wp[co*9 + 0]*v11 + wp[co*9 + 2]*v10 + wp[co*9 + 6]*v01 + wp[co*9 + 8]*v00;
            }
        }
    }
    int oh = OH0 + r8*2 + pe_h, ow = OW0 + c8*2 + pe_w;
#pragma unroll
    for (int co = 0; co < 3; co++)
        out[((size_t)(n*3 + co)*128 + oh)*128 + ow] = tanhf(acc[co] + bias[co]);
}

// ---------------- host launch ----------------
static float* sym_addr(const void* sym)
{
    void* p = nullptr;
    cudaGetSymbolAddress(&p, sym);
    return (float*)p;
}

extern "C" void kernel_launch(void* const* d_in, const int* in_sizes, int n_in,
                              void* d_out, int out_size)
{
    const float* x       = (const float*)d_in[0];
    const float* enc1_w  = (const float*)d_in[1];
    const float* enc1_b  = (const float*)d_in[2];
    const float* bn1_g   = (const float*)d_in[3];
    const float* bn1_b   = (const float*)d_in[4];
    const float* enc2_w  = (const float*)d_in[5];
    const float* enc2_b  = (const float*)d_in[6];
    const float* pre_w   = (const float*)d_in[7];
    const float* pre_b   = (const float*)d_in[8];
    const float* codebook= (const float*)d_in[9];
    const float* post_w  = (const float*)d_in[10];
    const float* post_b  = (const float*)d_in[11];
    const float* dec1_w  = (const float*)d_in[12];
    const float* dec1_b  = (const float*)d_in[13];
    const float* dbn1_g  = (const float*)d_in[14];
    const float* dbn1_b  = (const float*)d_in[15];
    const float* dec2_w  = (const float*)d_in[16];
    const float* dec2_b  = (const float*)d_in[17];

    float* out = (float*)d_out;
    float* out_losses = out + RECON_ELEMS;
    float* out_idx    = out + RECON_ELEMS + 2;

    float* h1 = sym_addr(g_h1);
    float* h2 = sym_addr(g_h2);
    float* z  = sym_addr(g_z);
    float* q  = sym_addr(g_q);
    float* d  = sym_addr(g_d);
    float* d1 = sym_addr(g_d1);
    float* psum = sym_addr(g_psum);
    float* psq  = sym_addr(g_psq);
    float* sc   = sym_addr(g_scale);
    float* sh   = sym_addr(g_shift);
    float* lp   = sym_addr(g_losspart);

    cudaFuncSetAttribute(conv2_kernel, cudaFuncAttributeMaxDynamicSharedMemorySize, 38496);
    cudaFuncSetAttribute(vq_kernel,    cudaFuncAttributeMaxDynamicSharedMemorySize, 133120);
    cudaFuncSetAttribute(dec2_kernel,  cudaFuncAttributeMaxDynamicSharedMemorySize, 57344);

    const float inv_cnt = 1.f / 262144.f;
    const int NBLK = 32;

    conv1_kernel<<<dim3(4,4,64), 256>>>(x, enc1_w, enc1_b, h1);
    bn_stats_kernel<<<dim3(128,NBLK), 256>>>(h1, psum, psq, 128, NBLK);
    bn_finalize_kernel<<<1,128>>>(psum, psq, bn1_g, bn1_b, sc, sh, NBLK, inv_cnt);
    conv2_kernel<<<dim3(4,8,64), 256, 38496>>>(h1, enc2_w, enc2_b, sc, sh, h2);
    pre_kernel<<<dim3(4,2,64), 256>>>(h2, pre_w, pre_b, z);

    vq_kernel<<<256, 256, 133120>>>(z, codebook, q, out_idx, lp);
    loss_finalize_kernel<<<1,256>>>(lp, out_losses);

    post_kernel<<<dim3(4,4,64), 256>>>(q, post_w, post_b, d);
    dec1_kernel<<<dim3(4,16,64), 256>>>(d, dec1_w, dec1_b, d1);
    bn_stats_kernel<<<dim3(128,NBLK), 256>>>(d1, psum, psq, 128, NBLK);
    bn_finalize_kernel<<<1,128>>>(psum, psq, dbn1_g, dbn1_b, sc, sh, NBLK, inv_cnt);
    dec2_kernel<<<dim3(64,64), 256, 57344>>>(d1, dec2_w, dec2_b, sc, sh, out);

    (void)in_sizes; (void)n_in; (void)out_size;
}

// round 6
// speedup vs baseline: 1.4703x; 1.3669x over previous
#include <cuda_runtime.h>
#include <cstdint>

#define H1_ELEMS (64*128*64*64)
#define H2_ELEMS (64*256*32*32)
#define Z_ELEMS  (64*64*32*32)
#define D_ELEMS  (64*256*32*32)
#define D1_ELEMS (64*128*64*64)
#define RECON_ELEMS (64*3*128*128)
#define VQ_DIM 64
#define NCODE 512

__device__ float g_h1[H1_ELEMS];
__device__ float g_h1b[H1_ELEMS];
__device__ float g_h2[H2_ELEMS];
__device__ float g_z[Z_ELEMS];
__device__ float g_q[Z_ELEMS];
__device__ float g_d[D_ELEMS];
__device__ float g_d1[D1_ELEMS];
__device__ float g_w2c[128*9*256];
__device__ float g_w2d[256*9*128];
__device__ float g_psum[128*64];
__device__ float g_psq[128*64];
__device__ float g_scale[128];
__device__ float g_shift[128];
__device__ float g_losspart[256];

typedef unsigned long long u64;
__device__ __forceinline__ u64 pack2(float a, float b) {
    u64 r; asm("mov.b64 %0, {%1,%2};" : "=l"(r) : "f"(a), "f"(b)); return r;
}
__device__ __forceinline__ u64 fma2(u64 a, u64 b, u64 c) {
    u64 d; asm("fma.rn.f32x2 %0, %1, %2, %3;" : "=l"(d) : "l"(a), "l"(b), "l"(c)); return d;
}
__device__ __forceinline__ u64 add2(u64 a, u64 b) {
    u64 d; asm("add.rn.f32x2 %0, %1, %2;" : "=l"(d) : "l"(a), "l"(b)); return d;
}
__device__ __forceinline__ float2 unpack2(u64 a) {
    float lo, hi; asm("mov.b64 {%0,%1}, %2;" : "=f"(lo), "=f"(hi) : "l"(a));
    return make_float2(lo, hi);
}
__device__ __forceinline__ void cp4(uint32_t saddr, const float* gaddr, int srcsize) {
    asm volatile("cp.async.ca.shared.global [%0], [%1], 4, %2;" :: "r"(saddr), "l"(gaddr), "r"(srcsize));
}
__device__ __forceinline__ void cp16(uint32_t saddr, const float* gaddr) {
    asm volatile("cp.async.cg.shared.global [%0], [%1], 16;" :: "r"(saddr), "l"(gaddr));
}
#define CP_COMMIT() asm volatile("cp.async.commit_group;")
#define CP_WAIT(n)  asm volatile("cp.async.wait_group %0;" :: "n"(n))

// ---------------- weight transposers: OIHW -> [ci][t][co] ----------------
__global__ void wtrans_conv2(const float* __restrict__ w, float* __restrict__ w2)
{
    int i = blockIdx.x * 256 + threadIdx.x;
    if (i >= 128*9*256) return;
    int co = i & 255; int rest = i >> 8; int t = rest % 9; int ci = rest / 9;
    w2[i] = w[((size_t)co*128 + ci)*9 + t];
}
__global__ void wtrans_dec1(const float* __restrict__ w, float* __restrict__ w2)
{
    int i = blockIdx.x * 256 + threadIdx.x;
    if (i >= 256*9*128) return;
    int co = i & 127; int rest = i >> 7; int t = rest % 9; int ci = rest / 9;
    w2[i] = w[((size_t)ci*128 + co)*9 + t];
}

// ---------------- conv1: 3->128, s2 ----------------
__global__ void conv1_kernel(const float* __restrict__ x, const float* __restrict__ w,
                             const float* __restrict__ bias, float* __restrict__ out)
{
    __shared__ float w_s[128*28];
    __shared__ float in_s[3*33*33];
    int n = blockIdx.z;
    int OH0 = blockIdx.y * 16, OW0 = blockIdx.x * 16;
    int tid = threadIdx.x;
    for (int i = tid; i < 128*27; i += 256) { int co = i / 27, t = i - co*27; w_s[co*28 + t] = w[i]; }
    for (int co = tid; co < 128; co += 256) w_s[co*28 + 27] = 0.f;
    int IH0 = OH0*2 - 1, IW0 = OW0*2 - 1;
    for (int i = tid; i < 3*33*33; i += 256) {
        int ci = i / 1089; int r = (i % 1089) / 33; int c = i % 33;
        int ih = IH0 + r, iw = IW0 + c;
        float v = 0.f;
        if (ih >= 0 && ih < 128 && iw >= 0 && iw < 128) v = x[((n*3 + ci)*128 + ih)*128 + iw];
        in_s[i] = v;
    }
    __syncthreads();
    int ty = tid >> 4, tx = tid & 15;
    float in_r[28];
#pragma unroll
    for (int ci = 0; ci < 3; ci++)
#pragma unroll
        for (int kh = 0; kh < 3; kh++)
#pragma unroll
            for (int kw = 0; kw < 3; kw++)
                in_r[ci*9 + kh*3 + kw] = in_s[ci*1089 + (ty*2+kh)*33 + (tx*2+kw)];
    in_r[27] = 0.f;
    int oh = OH0 + ty, ow = OW0 + tx;
    float* outp = out + (size_t)n*128*4096 + oh*64 + ow;
    const float4* w4p = reinterpret_cast<const float4*>(w_s);
    for (int co = 0; co < 128; co++) {
        float acc = bias[co];
#pragma unroll
        for (int u = 0; u < 7; u++) {
            float4 w4 = w4p[co*7 + u];
            acc += w4.x*in_r[u*4] + w4.y*in_r[u*4+1] + w4.z*in_r[u*4+2] + w4.w*in_r[u*4+3];
        }
        outp[(size_t)co*4096] = acc;
    }
}

// ---------------- BN stats / finalize / apply ----------------
__global__ void bn_stats_kernel(const float* __restrict__ x, float* __restrict__ psum,
                                float* __restrict__ psq, int C, int nblk)
{
    int c = blockIdx.x, blk = blockIdx.y;
    float s = 0.f, sq = 0.f;
    int total4 = 64 * 1024;
    for (int i = blk*256 + threadIdx.x; i < total4; i += nblk*256) {
        int n = i >> 10, off = i & 1023;
        const float4* p = reinterpret_cast<const float4*>(x + ((size_t)(n*C + c))*4096);
        float4 v = p[off];
        s  += v.x + v.y + v.z + v.w;
        sq += v.x*v.x + v.y*v.y + v.z*v.z + v.w*v.w;
    }
    __shared__ float rs[256], rq[256];
    rs[threadIdx.x] = s; rq[threadIdx.x] = sq;
    __syncthreads();
    for (int o = 128; o > 0; o >>= 1) {
        if (threadIdx.x < o) { rs[threadIdx.x] += rs[threadIdx.x+o]; rq[threadIdx.x] += rq[threadIdx.x+o]; }
        __syncthreads();
    }
    if (threadIdx.x == 0) { psum[c*nblk + blk] = rs[0]; psq[c*nblk + blk] = rq[0]; }
}

__global__ void bn_finalize_kernel(const float* __restrict__ psum, const float* __restrict__ psq,
                                   const float* __restrict__ g, const float* __restrict__ b,
                                   float* __restrict__ scale, float* __restrict__ shift,
                                   int nblk, float inv_count)
{
    int c = threadIdx.x;
    float s = 0.f, sq = 0.f;
    for (int i = 0; i < nblk; i++) { s += psum[c*nblk + i]; sq += psq[c*nblk + i]; }
    float mean = s * inv_count;
    float var = sq * inv_count - mean*mean;
    float r = rsqrtf(var + 1e-5f);
    float sc = g[c] * r;
    scale[c] = sc;
    shift[c] = b[c] - mean * sc;
}

// y = relu(x*scale[c] + shift[c]), float4 grid-stride; layout (N,128,4096)
__global__ void bnrelu_kernel(const float* __restrict__ x, float* __restrict__ y,
                              const float* __restrict__ sc, const float* __restrict__ sh)
{
    long i = (long)blockIdx.x * 256 + threadIdx.x;   // float4 index, total 8388608
    if (i >= 8388608L) return;
    int c = (int)((i >> 10) & 127);
    float s = sc[c], t = sh[c];
    float4 v = reinterpret_cast<const float4*>(x)[i];
    v.x = fmaxf(fmaf(v.x, s, t), 0.f);
    v.y = fmaxf(fmaf(v.y, s, t), 0.f);
    v.z = fmaxf(fmaf(v.z, s, t), 0.f);
    v.w = fmaxf(fmaf(v.w, s, t), 0.f);
    reinterpret_cast<float4*>(y)[i] = v;
}

// ---------------- conv2: 128->256, s2, cp.async double-buffered, f32x2 ----------------
// grid (coB=4, tile=8, n=64); block 256 = 8 warps (co-groups of 8). Buffer = 9368 floats.
#define C2_WB 4608
#define C2_IB 4760
#define C2_BUF (C2_WB + C2_IB)
__global__ void __launch_bounds__(256, 2) conv2_kernel(
        const float* __restrict__ in, const float* __restrict__ w2,
        const float* __restrict__ bias, float* __restrict__ out)
{
    extern __shared__ float sm[];
    int n = blockIdx.z, coB = blockIdx.x;
    int OH0 = (blockIdx.y >> 1) * 8, OW0 = (blockIdx.y & 1) * 16;
    int tid = threadIdx.x;
    int cog = tid >> 5, lane = tid & 31;
    int r = lane >> 2, seg = lane & 3;
    int IH0 = OH0*2 - 1, IW0 = OW0*2 - 1;

    uint32_t smaddr = (uint32_t)__cvta_generic_to_shared(sm);

    auto fill = [&](int it, int buf) {
        int ci0 = it * 8;
        uint32_t wdst = smaddr + (buf*C2_BUF)*4;
        const float* wsrc = w2 + ci0*9*256 + coB*64;
        for (int i = tid; i < 1152; i += 256) {       // (ci,t,c4): 8*9*16
            int cit = i >> 4, c4 = i & 15;            // cit = ci*9+t
            cp16(wdst + (cit*64 + c4*4)*4, wsrc + cit*256 + c4*4);
        }
        uint32_t idst = smaddr + (buf*C2_BUF + C2_WB)*4;
        for (int i = tid; i < C2_IB; i += 256) {
            int ci = i / 595; int rem = i - ci*595; int rr = rem / 35; int cc = rem - rr*35;
            int ih = IH0 + rr, iw = IW0 + cc;
            bool ok = (cc < 33) && (ih >= 0) && (ih < 64) && (iw >= 0) && (iw < 64);
            const float* src = ok ? (in + ((size_t)(n*128 + ci0 + ci)*64 + ih)*64 + iw) : in;
            cp4(idst + i*4, src, ok ? 4 : 0);
        }
    };

    u64 acc[4][4];
#pragma unroll
    for (int a = 0; a < 4; a++)
#pragma unroll
        for (int b = 0; b < 4; b++) acc[a][b] = 0ull;

    fill(0, 0); CP_COMMIT();
    for (int it = 0; it < 16; it++) {
        if (it < 15) { fill(it+1, (it+1)&1); CP_COMMIT(); CP_WAIT(1); }
        else         { CP_WAIT(0); }
        __syncthreads();
        const float* w_s  = sm + (it&1)*C2_BUF;
        const float* in_b = w_s + C2_WB;
#pragma unroll 2
        for (int ci = 0; ci < 8; ci++) {
            const float* ib = in_b + ci*595;
            const float* wb = w_s + ci*576 + cog*8;
#pragma unroll
            for (int kh = 0; kh < 3; kh++) {
                int base = (2*r + kh)*35 + seg*8;
                u64 pv[9];
#pragma unroll
                for (int q = 0; q < 9; q++) { float v = ib[base + q]; pv[q] = pack2(v, v); }
#pragma unroll
                for (int kw = 0; kw < 3; kw++) {
                    const float* wt = wb + (kh*3 + kw)*64;
                    ulonglong2 wA = *reinterpret_cast<const ulonglong2*>(wt);
                    ulonglong2 wB = *reinterpret_cast<const ulonglong2*>(wt + 4);
#pragma unroll
                    for (int p = 0; p < 4; p++) {
                        u64 v = pv[kw + 2*p];
                        acc[0][p] = fma2(wA.x, v, acc[0][p]);
                        acc[1][p] = fma2(wA.y, v, acc[1][p]);
                        acc[2][p] = fma2(wB.x, v, acc[2][p]);
                        acc[3][p] = fma2(wB.y, v, acc[3][p]);
                    }
                }
            }
        }
        __syncthreads();
    }
    int oh = OH0 + r;
#pragma unroll
    for (int cp = 0; cp < 4; cp++) {
        int co0 = coB*64 + cog*8 + cp*2;
        float b0 = bias[co0], b1 = bias[co0+1];
        float2 v0 = unpack2(acc[cp][0]), v1 = unpack2(acc[cp][1]);
        float2 v2 = unpack2(acc[cp][2]), v3 = unpack2(acc[cp][3]);
        size_t base0 = ((size_t)(n*256 + co0)*32 + oh)*32 + OW0 + seg*4;
        *reinterpret_cast<float4*>(out + base0) = make_float4(v0.x+b0, v1.x+b0, v2.x+b0, v3.x+b0);
        *reinterpret_cast<float4*>(out + base0 + 1024) = make_float4(v0.y+b1, v1.y+b1, v2.y+b1, v3.y+b1);
    }
}

// ---------------- pre 1x1: 256->64, f32x2 ----------------
__global__ void pre_kernel(const float* __restrict__ in, const float* __restrict__ w,
                           const float* __restrict__ bias, float* __restrict__ out)
{
    __shared__ float w_t[256*32];
    int n = blockIdx.z, coH = blockIdx.y;
    int s = blockIdx.x * 256 + threadIdx.x;
    for (int i = threadIdx.x; i < 256*32; i += 256) {
        int ci = i >> 5, co = i & 31;
        w_t[i] = w[(size_t)(coH*32 + co)*256 + ci];
    }
    __syncthreads();
    u64 acc[16];
#pragma unroll
    for (int k = 0; k < 16; k++) acc[k] = 0ull;
    const float* ip = in + (size_t)n*256*1024 + s;
#pragma unroll 4
    for (int ci = 0; ci < 256; ci++) {
        float v = ip[(size_t)ci*1024];
        u64 pv = pack2(v, v);
        const ulonglong2* wp = reinterpret_cast<const ulonglong2*>(w_t + ci*32);
#pragma unroll
        for (int k = 0; k < 8; k++) {
            ulonglong2 ww = wp[k];
            acc[2*k]   = fma2(ww.x, pv, acc[2*k]);
            acc[2*k+1] = fma2(ww.y, pv, acc[2*k+1]);
        }
    }
    float* op = out + (size_t)n*64*1024 + (size_t)coH*32*1024 + s;
#pragma unroll
    for (int k = 0; k < 16; k++) {
        float2 v = unpack2(acc[k]);
        op[(size_t)(2*k  )*1024] = v.x + bias[coH*32 + 2*k];
        op[(size_t)(2*k+1)*1024] = v.y + bias[coH*32 + 2*k+1];
    }
}

// ---------------- VQ (f32x2) ----------------
__global__ void vq_kernel(const float* __restrict__ z, const float* __restrict__ cb,
                          float* __restrict__ q, float* __restrict__ idx_out,
                          float* __restrict__ losspart)
{
    extern __shared__ float sm[];
    float* cb_s = sm;
    float* csq  = sm + NCODE*VQ_DIM;
    int tid = threadIdx.x;
    for (int i = tid; i < NCODE*VQ_DIM; i += 256) cb_s[i] = cb[i];
    __syncthreads();
    for (int k = tid; k < NCODE; k += 256) {
        float s = 0.f;
#pragma unroll
        for (int d = 0; d < VQ_DIM; d++) { float c = cb_s[k*VQ_DIM + d]; s += c*c; }
        csq[k] = s;
    }
    __syncthreads();

    int sidx = blockIdx.x * 256 + tid;
    int b = sidx >> 10, hw = sidx & 1023;
    const float* zp = z + (size_t)b*64*1024 + hw;
    u64 zv2[32];
    float zsq = 0.f;
#pragma unroll
    for (int u = 0; u < 32; u++) {
        float a = zp[(size_t)(2*u)*1024];
        float bb = zp[(size_t)(2*u+1)*1024];
        zsq += a*a + bb*bb;
        zv2[u] = pack2(a, bb);
    }
    float best = 3.4e38f; int bidx = 0;
    for (int k = 0; k < NCODE; k++) {
        const ulonglong2* cp2 = reinterpret_cast<const ulonglong2*>(cb_s + k*VQ_DIM);
        u64 d0 = 0ull, d1 = 0ull, d2 = 0ull, d3 = 0ull;
#pragma unroll
        for (int u = 0; u < 8; u++) {
            ulonglong2 ca = cp2[2*u], cbv = cp2[2*u+1];
            d0 = fma2(ca.x,  zv2[4*u],   d0);
            d1 = fma2(ca.y,  zv2[4*u+1], d1);
            d2 = fma2(cbv.x, zv2[4*u+2], d2);
            d3 = fma2(cbv.y, zv2[4*u+3], d3);
        }
        float2 dd = unpack2(add2(add2(d0, d1), add2(d2, d3)));
        float dot = dd.x + dd.y;
        float dist = zsq - 2.f*dot + csq[k];
        if (dist < best) { best = dist; bidx = k; }
    }
    float lsum = 0.f;
    float* qp = q + (size_t)b*64*1024 + hw;
#pragma unroll
    for (int u = 0; u < 32; u++) {
        float c0 = cb_s[bidx*VQ_DIM + 2*u];
        float c1 = cb_s[bidx*VQ_DIM + 2*u+1];
        qp[(size_t)(2*u)*1024]   = c0;
        qp[(size_t)(2*u+1)*1024] = c1;
        float2 zz = unpack2(zv2[u]);
        float df0 = zz.x - c0, df1 = zz.y - c1;
        lsum += df0*df0 + df1*df1;
    }
    idx_out[sidx] = (float)bidx;

    __shared__ float red[256];
    red[tid] = lsum; __syncthreads();
    for (int o = 128; o > 0; o >>= 1) {
        if (tid < o) red[tid] += red[tid + o];
        __syncthreads();
    }
    if (tid == 0) losspart[blockIdx.x] = red[0];
}

__global__ void loss_finalize_kernel(const float* __restrict__ losspart,
                                     float* __restrict__ out_losses)
{
    __shared__ float red[256];
    red[threadIdx.x] = losspart[threadIdx.x];
    __syncthreads();
    for (int o = 128; o > 0; o >>= 1) {
        if (threadIdx.x < o) red[threadIdx.x] += red[threadIdx.x + o];
        __syncthreads();
    }
    if (threadIdx.x == 0) {
        float m = red[0] / (65536.f * 64.f);
        out_losses[0] = m;
        out_losses[1] = m;
    }
}

// ---------------- post 1x1: 64->256, f32x2 ----------------
__global__ void post_kernel(const float* __restrict__ in, const float* __restrict__ w,
                            const float* __restrict__ bias, float* __restrict__ out)
{
    __shared__ float w_t[64*64];
    int n = blockIdx.z, coB = blockIdx.y;
    int s = blockIdx.x * 256 + threadIdx.x;
    for (int i = threadIdx.x; i < 64*64; i += 256) {
        int ci = i >> 6, co = i & 63;
        w_t[i] = w[(size_t)(coB*64 + co)*64 + ci];
    }
    __syncthreads();
    u64 acc[32];
#pragma unroll
    for (int k = 0; k < 32; k++) acc[k] = 0ull;
    const float* ip = in + (size_t)n*64*1024 + s;
#pragma unroll 2
    for (int ci = 0; ci < 64; ci++) {
        float v = ip[(size_t)ci*1024];
        u64 pv = pack2(v, v);
        const ulonglong2* wp = reinterpret_cast<const ulonglong2*>(w_t + ci*64);
#pragma unroll
        for (int k = 0; k < 16; k++) {
            ulonglong2 ww = wp[k];
            acc[2*k]   = fma2(ww.x, pv, acc[2*k]);
            acc[2*k+1] = fma2(ww.y, pv, acc[2*k+1]);
        }
    }
    float* op = out + (size_t)n*256*1024 + (size_t)coB*64*1024 + s;
#pragma unroll
    for (int k = 0; k < 32; k++) {
        float2 v = unpack2(acc[k]);
        op[(size_t)(2*k  )*1024] = v.x + bias[coB*64 + 2*k];
        op[(size_t)(2*k+1)*1024] = v.y + bias[coB*64 + 2*k+1];
    }
}

// ---------------- dec1 transpose conv 256->128, cp.async double-buffered ----------------
// grid (coB=4, tile=16, n=64); block 256 = 8 warps (4 co each = 2 co-pairs).
// smem buffer: weights [8ci][9t][32co]=2304 + inputs [8ci][9r x stride12]=864.
#define D1_WB 2304
#define D1_IB 864
#define D1_BUF (D1_WB + D1_IB)
__global__ void __launch_bounds__(256, 2) dec1_kernel(
        const float* __restrict__ in, const float* __restrict__ w2,
        const float* __restrict__ bias, float* __restrict__ out)
{
    __shared__ float sm[2*D1_BUF];
    int n = blockIdx.z, coB = blockIdx.x, tile = blockIdx.y;
    int OH0 = (tile >> 2) * 16, OW0 = (tile & 3) * 16;
    int IH0 = OH0 >> 1, IW0 = OW0 >> 1;
    int tid = threadIdx.x;
    int wid = tid >> 5, lane = tid & 31;
    int qy = lane >> 2, qxh = lane & 3;

    uint32_t smaddr = (uint32_t)__cvta_generic_to_shared(sm);

    auto fill = [&](int it, int buf) {
        int ci0 = it * 8;
        uint32_t wdst = smaddr + (buf*D1_BUF)*4;
        const float* wsrc = w2 + ci0*9*128 + coB*32;
        for (int i = tid; i < 576; i += 256) {      // (ci*9+t, c4): 72*8
            int cit = i >> 3, c4 = i & 7;
            cp16(wdst + (cit*32 + c4*4)*4, wsrc + cit*128 + c4*4);
        }
        uint32_t idst = smaddr + (buf*D1_BUF + D1_WB)*4;
        for (int i = tid; i < D1_IB; i += 256) {
            int ci = i / 108; int rem = i - ci*108; int rr = rem / 12; int cc = rem - rr*12;
            int ih = IH0 + rr, iw = IW0 + cc;
            bool ok = (cc < 9) && (ih < 32) && (iw < 32);
            const float* src = ok ? (in + ((size_t)(n*256 + ci0 + ci)*32 + ih)*32 + iw) : in;
            cp4(idst + i*4, src, ok ? 4 : 0);
        }
    };

    u64 acc[16];
#pragma unroll
    for (int i = 0; i < 16; i++) acc[i] = 0ull;

    fill(0, 0); CP_COMMIT();
    for (int it = 0; it < 32; it++) {
        if (it < 31) { fill(it+1, (it+1)&1); CP_COMMIT(); CP_WAIT(1); }
        else         { CP_WAIT(0); }
        __syncthreads();
        const float* w_s  = sm + (it&1)*D1_BUF;
        const float* in_b = w_s + D1_WB;
#pragma unroll 2
        for (int ci = 0; ci < 8; ci++) {
            const float* ib = in_b + ci*108 + qy*12 + qxh;
            float A00 = ib[0], A01 = ib[1], A10 = ib[12], A11 = ib[13];
            float B00 = ib[4], B01 = ib[5], B10 = ib[16], B11 = ib[17];
            u64 a00 = pack2(A00,A00), a01 = pack2(A01,A01), a10 = pack2(A10,A10), a11 = pack2(A11,A11);
            u64 b00 = pack2(B00,B00), b01 = pack2(B01,B01), b10 = pack2(B10,B10), b11 = pack2(B11,B11);
            const float* wb = w_s + ci*288 + wid*4;
            auto tap = [&](int t, u64 vA, u64 vB, int px) {
                ulonglong2 wv = *reinterpret_cast<const ulonglong2*>(wb + t*32);
                acc[px]      = fma2(wv.x, vA, acc[px]);
                acc[4 + px]  = fma2(wv.x, vB, acc[4 + px]);
                acc[8 + px]  = fma2(wv.y, vA, acc[8 + px]);
                acc[12 + px] = fma2(wv.y, vB, acc[12 + px]);
            };
            tap(4, a00, b00, 0);
            tap(3, a01, b01, 1); tap(5, a00, b00, 1);
            tap(1, a10, b10, 2); tap(7, a00, b00, 2);
            tap(0, a11, b11, 3); tap(2, a10, b10, 3);
            tap(6, a01, b01, 3); tap(8, a00, b00, 3);
        }
        __syncthreads();
    }
    int oh0 = OH0 + qy*2;
#pragma unroll
    for (int cp = 0; cp < 2; cp++) {
        int co0 = coB*32 + wid*4 + cp*2;
        float b0 = bias[co0], b1 = bias[co0+1];
#pragma unroll
        for (int qd = 0; qd < 2; qd++) {
            int ow0 = OW0 + (qxh + qd*4)*2;
            float2 p0 = unpack2(acc[cp*8 + qd*4 + 0]);
            float2 p1 = unpack2(acc[cp*8 + qd*4 + 1]);
            float2 p2 = unpack2(acc[cp*8 + qd*4 + 2]);
            float2 p3 = unpack2(acc[cp*8 + qd*4 + 3]);
            float* o0 = out + ((size_t)(n*128 + co0)*64 + oh0)*64 + ow0;
            float* o1 = out + ((size_t)(n*128 + co0+1)*64 + oh0)*64 + ow0;
            *reinterpret_cast<float2*>(o0)      = make_float2(p0.x + b0, p1.x + b0);
            *reinterpret_cast<float2*>(o0 + 64) = make_float2(p2.x + b0, p3.x + b0);
            *reinterpret_cast<float2*>(o1)      = make_float2(p0.y + b1, p1.y + b1);
            *reinterpret_cast<float2*>(o1 + 64) = make_float2(p2.y + b1, p3.y + b1);
        }
    }
}

// ---------------- dec2 transpose conv 128->3, fused BN+ReLU in, tanh out ----------------
// in_s padded to stride 12 (conflict-free banks).
__global__ void dec2_kernel(const float* __restrict__ in, const float* __restrict__ w,
                            const float* __restrict__ bias, const float* __restrict__ scale,
                            const float* __restrict__ shift, float* __restrict__ out)
{
    extern __shared__ float sm[];
    float* w_s  = sm;                 // 3456
    float* in_s = sm + 3456;          // 128*108 = 13824
    float* sc_s = sm + 17280;         // 128
    float* sh_s = sm + 17408;         // 128
    int n = blockIdx.y; int tile = blockIdx.x;
    int OH0 = (tile >> 3) * 16, OW0 = (tile & 7) * 16;
    int IH0 = OH0 >> 1, IW0 = OW0 >> 1;
    int tid = threadIdx.x;
    for (int i = tid; i < 3456; i += 256) w_s[i] = w[i];
    for (int i = tid; i < 128; i += 256) { sc_s[i] = scale[i]; sh_s[i] = shift[i]; }
    __syncthreads();
    for (int i = tid; i < 128*108; i += 256) {
        int ci = i / 108; int rem = i - ci*108; int rr = rem / 12; int cc = rem - rr*12;
        int ih = IH0 + rr, iw = IW0 + cc;
        float v = 0.f;
        if (cc < 9 && ih < 64 && iw < 64) {
            float raw = in[((size_t)(n*128 + ci)*64 + ih)*64 + iw];
            v = fmaxf(fmaf(raw, sc_s[ci], sh_s[ci]), 0.f);
        }
        in_s[i] = v;
    }
    __syncthreads();

    int cls = tid >> 6; int pe_h = cls >> 1, pe_w = cls & 1;
    int t3 = tid & 63; int r8 = t3 >> 3, c8 = t3 & 7;
    float acc[3] = {0.f, 0.f, 0.f};
    for (int ci = 0; ci < 128; ci++) {
        const float* base = &in_s[ci*108];
        float v00 = base[r8*12 + c8];
        float v01 = base[r8*12 + c8 + 1];
        float v10 = base[(r8+1)*12 + c8];
        float v11 = base[(r8+1)*12 + c8 + 1];
        const float* wp = &w_s[ci*27];
        if (pe_h == 0) {
            if (pe_w == 0) {
#pragma unroll
                for (int co = 0; co < 3; co++) acc[co] += wp[co*9 + 4] * v00;
            } else {
#pragma unroll
                for (int co = 0; co < 3; co++) acc[co] += wp[co*9 + 3] * v01 + wp[co*9 + 5] * v00;
            }
        } else {
            if (pe_w == 0) {
#pragma unroll
                for (int co = 0; co < 3; co++) acc[co] += wp[co*9 + 1] * v10 + wp[co*9 + 7] * v00;
            } else {
#pragma unroll
                for (int co = 0; co < 3; co++)
                    acc[co] += wp[co*9 + 0]*v11 + wp[co*9 + 2]*v10 + wp[co*9 + 6]*v01 + wp[co*9 + 8]*v00;
            }
        }
    }
    int oh = OH0 + r8*2 + pe_h, ow = OW0 + c8*2 + pe_w;
#pragma unroll
    for (int co = 0; co < 3; co++)
        out[((size_t)(n*3 + co)*128 + oh)*128 + ow] = tanhf(acc[co] + bias[co]);
}

// ---------------- host launch ----------------
static float* sym_addr(const void* sym)
{
    void* p = nullptr;
    cudaGetSymbolAddress(&p, sym);
    return (float*)p;
}

extern "C" void kernel_launch(void* const* d_in, const int* in_sizes, int n_in,
                              void* d_out, int out_size)
{
    const float* x       = (const float*)d_in[0];
    const float* enc1_w  = (const float*)d_in[1];
    const float* enc1_b  = (const float*)d_in[2];
    const float* bn1_g   = (const float*)d_in[3];
    const float* bn1_b   = (const float*)d_in[4];
    const float* enc2_w  = (const float*)d_in[5];
    const float* enc2_b  = (const float*)d_in[6];
    const float* pre_w   = (const float*)d_in[7];
    const float* pre_b   = (const float*)d_in[8];
    const float* codebook= (const float*)d_in[9];
    const float* post_w  = (const float*)d_in[10];
    const float* post_b  = (const float*)d_in[11];
    const float* dec1_w  = (const float*)d_in[12];
    const float* dec1_b  = (const float*)d_in[13];
    const float* dbn1_g  = (const float*)d_in[14];
    const float* dbn1_b  = (const float*)d_in[15];
    const float* dec2_w  = (const float*)d_in[16];
    const float* dec2_b  = (const float*)d_in[17];

    float* out = (float*)d_out;
    float* out_losses = out + RECON_ELEMS;
    float* out_idx    = out + RECON_ELEMS + 2;

    float* h1  = sym_addr(g_h1);
    float* h1b = sym_addr(g_h1b);
    float* h2  = sym_addr(g_h2);
    float* z   = sym_addr(g_z);
    float* q   = sym_addr(g_q);
    float* d   = sym_addr(g_d);
    float* d1  = sym_addr(g_d1);
    float* w2c = sym_addr(g_w2c);
    float* w2d = sym_addr(g_w2d);
    float* psum = sym_addr(g_psum);
    float* psq  = sym_addr(g_psq);
    float* sc   = sym_addr(g_scale);
    float* sh   = sym_addr(g_shift);
    float* lp   = sym_addr(g_losspart);

    cudaFuncSetAttribute(conv2_kernel, cudaFuncAttributeMaxDynamicSharedMemorySize, 2*C2_BUF*4);
    cudaFuncSetAttribute(vq_kernel,    cudaFuncAttributeMaxDynamicSharedMemorySize, 133120);
    cudaFuncSetAttribute(dec2_kernel,  cudaFuncAttributeMaxDynamicSharedMemorySize, 70144);

    const float inv_cnt = 1.f / 262144.f;
    const int NBLK = 32;

    // weight pre-transposes (small)
    wtrans_conv2<<<1152, 256>>>(enc2_w, w2c);
    wtrans_dec1<<<1152, 256>>>(dec1_w, w2d);

    // encoder
    conv1_kernel<<<dim3(4,4,64), 256>>>(x, enc1_w, enc1_b, h1);
    bn_stats_kernel<<<dim3(128,NBLK), 256>>>(h1, psum, psq, 128, NBLK);
    bn_finalize_kernel<<<1,128>>>(psum, psq, bn1_g, bn1_b, sc, sh, NBLK, inv_cnt);
    bnrelu_kernel<<<32768, 256>>>(h1, h1b, sc, sh);
    conv2_kernel<<<dim3(4,8,64), 256, 2*C2_BUF*4>>>(h1b, w2c, enc2_b, h2);
    pre_kernel<<<dim3(4,2,64), 256>>>(h2, pre_w, pre_b, z);

    // VQ
    vq_kernel<<<256, 256, 133120>>>(z, codebook, q, out_idx, lp);
    loss_finalize_kernel<<<1,256>>>(lp, out_losses);

    // decoder
    post_kernel<<<dim3(4,4,64), 256>>>(q, post_w, post_b, d);
    dec1_kernel<<<dim3(4,16,64), 256>>>(d, w2d, dec1_b, d1);
    bn_stats_kernel<<<dim3(128,NBLK), 256>>>(d1, psum, psq, 128, NBLK);
    bn_finalize_kernel<<<1,128>>>(psum, psq, dbn1_g, dbn1_b, sc, sh, NBLK, inv_cnt);
    dec2_kernel<<<dim3(64,64), 256, 70144>>>(d1, dec2_w, dec2_b, sc, sh, out);

    (void)in_sizes; (void)n_in; (void)out_size;
}

// round 8
// speedup vs baseline: 1.8092x; 1.2305x over previous
#include <cuda_runtime.h>
#include <cuda_bf16.h>
#include <cstdint>

#define H1_ELEMS (64*128*64*64)
#define H2_ELEMS (64*256*32*32)
#define Z_ELEMS  (64*64*32*32)
#define D_ELEMS  (64*256*32*32)
#define D1_ELEMS (64*128*64*64)
#define RECON_ELEMS (64*3*128*128)
#define VQ_DIM 64
#define NCODE 512

__device__ float g_h1[H1_ELEMS];                 // NHWC fp32
__device__ __nv_bfloat16 g_h1hi[H1_ELEMS];       // NHWC bf16 hi
__device__ __nv_bfloat16 g_h1lo[H1_ELEMS];       // NHWC bf16 lo
__device__ float g_h2[H2_ELEMS];
__device__ float g_z[Z_ELEMS];
__device__ float g_q[Z_ELEMS];
__device__ float g_d[D_ELEMS];
__device__ float g_d1[D1_ELEMS];
__device__ __nv_bfloat16 g_w2chi[256*1152];      // [co][t][ci] bf16 hi
__device__ __nv_bfloat16 g_w2clo[256*1152];      // [co][t][ci] bf16 lo
__device__ float g_w2d[256*9*128];
__device__ float g_psum[128*256];
__device__ float g_psq[128*256];
__device__ float g_scale[128];
__device__ float g_shift[128];
__device__ float g_losspart[256];

typedef unsigned long long u64;
__device__ __forceinline__ u64 pack2(float a, float b) {
    u64 r; asm("mov.b64 %0, {%1,%2};" : "=l"(r) : "f"(a), "f"(b)); return r;
}
__device__ __forceinline__ u64 fma2(u64 a, u64 b, u64 c) {
    u64 d; asm("fma.rn.f32x2 %0, %1, %2, %3;" : "=l"(d) : "l"(a), "l"(b), "l"(c)); return d;
}
__device__ __forceinline__ u64 add2(u64 a, u64 b) {
    u64 d; asm("add.rn.f32x2 %0, %1, %2;" : "=l"(d) : "l"(a), "l"(b)); return d;
}
__device__ __forceinline__ float2 unpack2(u64 a) {
    float lo, hi; asm("mov.b64 {%0,%1}, %2;" : "=f"(lo), "=f"(hi) : "l"(a));
    return make_float2(lo, hi);
}
__device__ __forceinline__ void cp4(uint32_t saddr, const float* gaddr, int srcsize) {
    asm volatile("cp.async.ca.shared.global [%0], [%1], 4, %2;" :: "r"(saddr), "l"(gaddr), "r"(srcsize));
}
__device__ __forceinline__ void cp16(uint32_t saddr, const void* gaddr) {
    asm volatile("cp.async.cg.shared.global [%0], [%1], 16;" :: "r"(saddr), "l"(gaddr));
}
__device__ __forceinline__ void cp16z(uint32_t saddr, const void* gaddr, bool ok) {
    int sz = ok ? 16 : 0;
    asm volatile("cp.async.cg.shared.global [%0], [%1], 16, %2;" :: "r"(saddr), "l"(gaddr), "r"(sz));
}
#define CP_COMMIT() asm volatile("cp.async.commit_group;")
#define CP_WAIT(n)  asm volatile("cp.async.wait_group %0;" :: "n"(n))

#define SWZ(o) ((o) ^ ((((uint32_t)(o)) >> 3) & 0x70))

__device__ __forceinline__ void ldsm4(uint32_t* r, uint32_t addr) {
    asm volatile("ldmatrix.sync.aligned.m8n8.x4.shared.b16 {%0,%1,%2,%3}, [%4];"
                 : "=r"(r[0]), "=r"(r[1]), "=r"(r[2]), "=r"(r[3]) : "r"(addr));
}
__device__ __forceinline__ void mma16816(float* c, const uint32_t* a, const uint32_t* b) {
    asm volatile(
        "mma.sync.aligned.m16n8k16.row.col.f32.bf16.bf16.f32 "
        "{%0,%1,%2,%3}, {%4,%5,%6,%7}, {%8,%9}, {%0,%1,%2,%3};"
        : "+f"(c[0]), "+f"(c[1]), "+f"(c[2]), "+f"(c[3])
        : "r"(a[0]), "r"(a[1]), "r"(a[2]), "r"(a[3]), "r"(b[0]), "r"(b[1]));
}

// ---------------- weight transposers ----------------
__global__ void wtrans_conv2_bf16(const float* __restrict__ w,
                                  __nv_bfloat16* __restrict__ whi, __nv_bfloat16* __restrict__ wlo)
{
    int i = blockIdx.x * 256 + threadIdx.x;
    if (i >= 256*1152) return;
    int co = i / 1152; int rem = i - co*1152; int t = rem >> 7; int ci = rem & 127;
    float v = w[((size_t)co*128 + ci)*9 + t];
    __nv_bfloat16 h = __float2bfloat16(v);
    float l = v - __bfloat162float(h);
    whi[i] = h;
    wlo[i] = __float2bfloat16(l);
}
__global__ void wtrans_dec1(const float* __restrict__ w, float* __restrict__ w2)
{
    int i = blockIdx.x * 256 + threadIdx.x;
    if (i >= 256*9*128) return;
    int co = i & 127; int rest = i >> 7; int t = rest % 9; int ci = rest / 9;
    w2[i] = w[((size_t)ci*128 + co)*9 + t];
}

// ---------------- conv1: 3->128, s2, NHWC output ----------------
__global__ void conv1_kernel(const float* __restrict__ x, const float* __restrict__ w,
                             const float* __restrict__ bias, float* __restrict__ out)
{
    __shared__ float w_s[128*28];
    __shared__ float in_s[3*33*33];
    int n = blockIdx.z;
    int OH0 = blockIdx.y * 16, OW0 = blockIdx.x * 16;
    int tid = threadIdx.x;
    for (int i = tid; i < 128*27; i += 256) { int co = i / 27, t = i - co*27; w_s[co*28 + t] = w[i]; }
    for (int co = tid; co < 128; co += 256) w_s[co*28 + 27] = 0.f;
    int IH0 = OH0*2 - 1, IW0 = OW0*2 - 1;
    for (int i = tid; i < 3*33*33; i += 256) {
        int ci = i / 1089; int r = (i % 1089) / 33; int c = i % 33;
        int ih = IH0 + r, iw = IW0 + c;
        float v = 0.f;
        if (ih >= 0 && ih < 128 && iw >= 0 && iw < 128) v = x[((n*3 + ci)*128 + ih)*128 + iw];
        in_s[i] = v;
    }
    __syncthreads();
    int ty = tid >> 4, tx = tid & 15;
    float in_r[28];
#pragma unroll
    for (int ci = 0; ci < 3; ci++)
#pragma unroll
        for (int kh = 0; kh < 3; kh++)
#pragma unroll
            for (int kw = 0; kw < 3; kw++)
                in_r[ci*9 + kh*3 + kw] = in_s[ci*1089 + (ty*2+kh)*33 + (tx*2+kw)];
    in_r[27] = 0.f;
    int oh = OH0 + ty, ow = OW0 + tx;
    float* outp = out + (((size_t)n*64 + oh)*64 + ow)*128;
    const float4* w4p = reinterpret_cast<const float4*>(w_s);
    for (int cg = 0; cg < 32; cg++) {
        float4 res;
        float* rp = &res.x;
#pragma unroll
        for (int j = 0; j < 4; j++) {
            int co = cg*4 + j;
            float acc = bias[co];
#pragma unroll
            for (int u = 0; u < 7; u++) {
                float4 w4 = w4p[co*7 + u];
                acc += w4.x*in_r[u*4] + w4.y*in_r[u*4+1] + w4.z*in_r[u*4+2] + w4.w*in_r[u*4+3];
            }
            rp[j] = acc;
        }
        reinterpret_cast<float4*>(outp)[cg] = res;
    }
}

// ---------------- BN stats NHWC (for h1) ----------------
__global__ void bn_stats_nhwc(const float* __restrict__ x, float* __restrict__ psum,
                              float* __restrict__ psq, int nblk)
{
    int blk = blockIdx.x;
    int cg = threadIdx.x & 31;
    int rg = threadIdx.x >> 5;
    float4 s = make_float4(0,0,0,0), sq = make_float4(0,0,0,0);
    for (int r = blk*8 + rg; r < 262144; r += nblk*8) {
        float4 v = *reinterpret_cast<const float4*>(x + (size_t)r*128 + cg*4);
        s.x += v.x; s.y += v.y; s.z += v.z; s.w += v.w;
        sq.x += v.x*v.x; sq.y += v.y*v.y; sq.z += v.z*v.z; sq.w += v.w*v.w;
    }
    __shared__ float ss[256*4], qs[256*4];
    reinterpret_cast<float4*>(ss)[threadIdx.x] = s;
    reinterpret_cast<float4*>(qs)[threadIdx.x] = sq;
    __syncthreads();
    if (threadIdx.x < 128) {
        int c = threadIdx.x;
        int cgi = c >> 2, j = c & 3;
        float a = 0.f, b = 0.f;
        for (int g = 0; g < 8; g++) { a += ss[(g*32+cgi)*4 + j]; b += qs[(g*32+cgi)*4 + j]; }
        psum[c*nblk + blk] = a;
        psq[c*nblk + blk] = b;
    }
}

// ---------------- BN stats NCHW (for d1) ----------------
__global__ void bn_stats_kernel(const float* __restrict__ x, float* __restrict__ psum,
                                float* __restrict__ psq, int C, int nblk)
{
    int c = blockIdx.x, blk = blockIdx.y;
    float s = 0.f, sq = 0.f;
    int total4 = 64 * 1024;
    for (int i = blk*256 + threadIdx.x; i < total4; i += nblk*256) {
        int n = i >> 10, off = i & 1023;
        const float4* p = reinterpret_cast<const float4*>(x + ((size_t)(n*C + c))*4096);
        float4 v = p[off];
        s  += v.x + v.y + v.z + v.w;
        sq += v.x*v.x + v.y*v.y + v.z*v.z + v.w*v.w;
    }
    __shared__ float rs[256], rq[256];
    rs[threadIdx.x] = s; rq[threadIdx.x] = sq;
    __syncthreads();
    for (int o = 128; o > 0; o >>= 1) {
        if (threadIdx.x < o) { rs[threadIdx.x] += rs[threadIdx.x+o]; rq[threadIdx.x] += rq[threadIdx.x+o]; }
        __syncthreads();
    }
    if (threadIdx.x == 0) { psum[c*nblk + blk] = rs[0]; psq[c*nblk + blk] = rq[0]; }
}

__global__ void bn_finalize_kernel(const float* __restrict__ psum, const float* __restrict__ psq,
                                   const float* __restrict__ g, const float* __restrict__ b,
                                   float* __restrict__ scale, float* __restrict__ shift,
                                   int nblk, float inv_count)
{
    int c = threadIdx.x;
    float s = 0.f, sq = 0.f;
    for (int i = 0; i < nblk; i++) { s += psum[c*nblk + i]; sq += psq[c*nblk + i]; }
    float mean = s * inv_count;
    float var = sq * inv_count - mean*mean;
    float r = rsqrtf(var + 1e-5f);
    float sc = g[c] * r;
    scale[c] = sc;
    shift[c] = b[c] - mean * sc;
}

// ---------------- BN+ReLU + bf16 split (NHWC fp32 -> NHWC bf16 hi/lo) ----------------
__global__ void bnrelu_split_kernel(const float* __restrict__ x,
                                    __nv_bfloat16* __restrict__ hi, __nv_bfloat16* __restrict__ lo,
                                    const float* __restrict__ sc, const float* __restrict__ sh)
{
    long i = (long)blockIdx.x * 256 + threadIdx.x;   // float4 index
    if (i >= 8388608L) return;
    int c = (int)(i & 31) * 4;
    float4 v = reinterpret_cast<const float4*>(x)[i];
    float r0 = fmaxf(fmaf(v.x, sc[c+0], sh[c+0]), 0.f);
    float r1 = fmaxf(fmaf(v.y, sc[c+1], sh[c+1]), 0.f);
    float r2 = fmaxf(fmaf(v.z, sc[c+2], sh[c+2]), 0.f);
    float r3 = fmaxf(fmaf(v.w, sc[c+3], sh[c+3]), 0.f);
    __nv_bfloat16 h0 = __float2bfloat16(r0), h1 = __float2bfloat16(r1);
    __nv_bfloat16 h2 = __float2bfloat16(r2), h3 = __float2bfloat16(r3);
    __nv_bfloat16 l0 = __float2bfloat16(r0 - __bfloat162float(h0));
    __nv_bfloat16 l1 = __float2bfloat16(r1 - __bfloat162float(h1));
    __nv_bfloat16 l2 = __float2bfloat16(r2 - __bfloat162float(h2));
    __nv_bfloat16 l3 = __float2bfloat16(r3 - __bfloat162float(h3));
    __nv_bfloat162* hp = reinterpret_cast<__nv_bfloat162*>(hi);
    __nv_bfloat162* lp = reinterpret_cast<__nv_bfloat162*>(lo);
    hp[2*i]   = __nv_bfloat162(h0, h1);
    hp[2*i+1] = __nv_bfloat162(h2, h3);
    lp[2*i]   = __nv_bfloat162(l0, l1);
    lp[2*i+1] = __nv_bfloat162(l2, l3);
}

// ---------------- conv2 via mma.sync bf16: M=128 px, N=128 co, K=1152, split ----------------
// grid (mt=8, Nt=2, n=64); block 256 = 8 warps (4x2: each M=32 x N=64).
#define MM_SPLIT 16384u                    // 128 rows x 128B
#define MM_STAGE (4u*MM_SPLIT)             // Ah, Al, Bh, Bl = 65536 B
__global__ void __launch_bounds__(256, 1) conv2_mma_kernel(
        const __nv_bfloat16* __restrict__ inhi, const __nv_bfloat16* __restrict__ inlo,
        const __nv_bfloat16* __restrict__ whi, const __nv_bfloat16* __restrict__ wlo,
        const float* __restrict__ bias, float* __restrict__ out)
{
    extern __shared__ char dsm[];
    __shared__ float bias_s[128];
    int mt = blockIdx.x, Nt = blockIdx.y, n = blockIdx.z;
    int OH0 = mt * 4;
    int tid = threadIdx.x, wid = tid >> 5, lane = tid & 31;
    int mrow = (wid >> 1) * 32;
    int ncol = (wid & 1) * 64;

    uint32_t base0 = ((uint32_t)__cvta_generic_to_shared(dsm) + 1023u) & ~1023u;
    for (int i = tid; i < 128; i += 256) bias_s[i] = bias[Nt*128 + i];

    auto fill = [&](int kc, int buf) {
        int t = kc >> 1, ci0 = (kc & 1) << 6;
        int kh = t / 3, kw = t - (t/3)*3;
        uint32_t Ah = base0 + buf*MM_STAGE;
        uint32_t Al = Ah + MM_SPLIT;
        uint32_t Bh = Al + MM_SPLIT;
        uint32_t Bl = Bh + MM_SPLIT;
        for (int i = tid; i < 1024; i += 256) {
            int px = i >> 3, c16 = i & 7;
            int oh = OH0 + (px >> 5), ow = px & 31;
            int ih = 2*oh - 1 + kh, iw = 2*ow - 1 + kw;
            bool ok = (ih >= 0) && (ih < 64) && (iw >= 0) && (iw < 64);
            long off = ((long)(n*64 + (ok ? ih : 0))*64 + (ok ? iw : 0))*128 + ci0 + c16*8;
            uint32_t d = SWZ(px*128 + c16*16);
            cp16z(Ah + d, inhi + off, ok);
            cp16z(Al + d, inlo + off, ok);
        }
        for (int i = tid; i < 1024; i += 256) {
            int co = i >> 3, c16 = i & 7;
            long off = (long)(Nt*128 + co)*1152 + t*128 + ci0 + c16*8;
            uint32_t d = SWZ(co*128 + c16*16);
            cp16(Bh + d, whi + off);
            cp16(Bl + d, wlo + off);
        }
    };

    float acc[2][8][4];
#pragma unroll
    for (int a = 0; a < 2; a++)
#pragma unroll
        for (int b = 0; b < 8; b++)
#pragma unroll
            for (int c = 0; c < 4; c++) acc[a][b][c] = 0.f;

    fill(0, 0); CP_COMMIT();
    for (int s = 0; s < 18; s++) {
        if (s < 17) { fill(s+1, (s+1)&1); CP_COMMIT(); CP_WAIT(1); }
        else        { CP_WAIT(0); }
        __syncthreads();
        uint32_t Ah = base0 + (s&1)*MM_STAGE;
        uint32_t Al = Ah + MM_SPLIT;
        uint32_t Bh = Al + MM_SPLIT;
        uint32_t Bl = Bh + MM_SPLIT;
#pragma unroll
        for (int ks = 0; ks < 4; ks++) {
            uint32_t ah[2][4], al[2][4], bh[4][4], bl[4][4];
#pragma unroll
            for (int mi = 0; mi < 2; mi++) {
                int row = mrow + mi*16 + (lane & 15);
                uint32_t ao = SWZ(row*128 + ks*32 + (lane >> 4)*16);
                ldsm4(ah[mi], Ah + ao);
                ldsm4(al[mi], Al + ao);
            }
#pragma unroll
            for (int nb = 0; nb < 4; nb++) {
                int g = lane >> 3, r = lane & 7;
                int co_l = ncol + nb*16 + ((g >> 1) << 3) + r;
                uint32_t bo = SWZ(co_l*128 + ks*32 + (g & 1)*16);
                ldsm4(bh[nb], Bh + bo);
                ldsm4(bl[nb], Bl + bo);
            }
#pragma unroll
            for (int mi = 0; mi < 2; mi++)
#pragma unroll
                for (int nt = 0; nt < 8; nt++) {
                    const uint32_t* pbh = &bh[nt >> 1][(nt & 1)*2];
                    const uint32_t* pbl = &bl[nt >> 1][(nt & 1)*2];
                    mma16816(acc[mi][nt], ah[mi], pbh);
                    mma16816(acc[mi][nt], ah[mi], pbl);
                    mma16816(acc[mi][nt], al[mi], pbh);
                }
        }
        __syncthreads();
    }

    // epilogue: acc -> smem [co][px+pad] -> coalesced float4 NCHW stores
    float* osm = reinterpret_cast<float*>(dsm);
#pragma unroll
    for (int mi = 0; mi < 2; mi++)
#pragma unroll
        for (int nt = 0; nt < 8; nt++) {
            int px0 = mrow + mi*16 + (lane >> 2);
            int col = ncol + nt*8 + (lane & 3)*2;
            osm[col*132 + px0]         = acc[mi][nt][0];
            osm[(col+1)*132 + px0]     = acc[mi][nt][1];
            osm[col*132 + px0 + 8]     = acc[mi][nt][2];
            osm[(col+1)*132 + px0 + 8] = acc[mi][nt][3];
        }
    __syncthreads();
    for (int i = tid; i < 128*32; i += 256) {
        int co = i >> 5, p4 = (i & 31)*4;
        float4 v = *reinterpret_cast<const float4*>(osm + co*132 + p4);
        float b = bias_s[co];
        v.x += b; v.y += b; v.z += b; v.w += b;
        int cog = Nt*128 + co;
        *reinterpret_cast<float4*>(out + ((size_t)(n*256 + cog))*1024 + OH0*32 + p4) = v;
    }
}

// ---------------- pre 1x1: 256->64, f32x2 ----------------
__global__ void pre_kernel(const float* __restrict__ in, const float* __restrict__ w,
                           const float* __restrict__ bias, float* __restrict__ out)
{
    __shared__ float w_t[256*32];
    int n = blockIdx.z, coH = blockIdx.y;
    int s = blockIdx.x * 256 + threadIdx.x;
    for (int i = threadIdx.x; i < 256*32; i += 256) {
        int ci = i >> 5, co = i & 31;
        w_t[i] = w[(size_t)(coH*32 + co)*256 + ci];
    }
    __syncthreads();
    u64 acc[16];
#pragma unroll
    for (int k = 0; k < 16; k++) acc[k] = 0ull;
    const float* ip = in + (size_t)n*256*1024 + s;
#pragma unroll 4
    for (int ci = 0; ci < 256; ci++) {
        float v = ip[(size_t)ci*1024];
        u64 pv = pack2(v, v);
        const ulonglong2* wp = reinterpret_cast<const ulonglong2*>(w_t + ci*32);
#pragma unroll
        for (int k = 0; k < 8; k++) {
            ulonglong2 ww = wp[k];
            acc[2*k]   = fma2(ww.x, pv, acc[2*k]);
            acc[2*k+1] = fma2(ww.y, pv, acc[2*k+1]);
        }
    }
    float* op = out + (size_t)n*64*1024 + (size_t)coH*32*1024 + s;
#pragma unroll
    for (int k = 0; k < 16; k++) {
        float2 v = unpack2(acc[k]);
        op[(size_t)(2*k  )*1024] = v.x + bias[coH*32 + 2*k];
        op[(size_t)(2*k+1)*1024] = v.y + bias[coH*32 + 2*k+1];
    }
}

// ---------------- VQ (f32x2) ----------------
__global__ void vq_kernel(const float* __restrict__ z, const float* __restrict__ cb,
                          float* __restrict__ q, float* __restrict__ idx_out,
                          float* __restrict__ losspart)
{
    extern __shared__ float sm[];
    float* cb_s = sm;
    float* csq  = sm + NCODE*VQ_DIM;
    int tid = threadIdx.x;
    for (int i = tid; i < NCODE*VQ_DIM; i += 256) cb_s[i] = cb[i];
    __syncthreads();
    for (int k = tid; k < NCODE; k += 256) {
        float s = 0.f;
#pragma unroll
        for (int d = 0; d < VQ_DIM; d++) { float c = cb_s[k*VQ_DIM + d]; s += c*c; }
        csq[k] = s;
    }
    __syncthreads();

    int sidx = blockIdx.x * 256 + tid;
    int b = sidx >> 10, hw = sidx & 1023;
    const float* zp = z + (size_t)b*64*1024 + hw;
    u64 zv2[32];
    float zsq = 0.f;
#pragma unroll
    for (int u = 0; u < 32; u++) {
        float a = zp[(size_t)(2*u)*1024];
        float bb = zp[(size_t)(2*u+1)*1024];
        zsq += a*a + bb*bb;
        zv2[u] = pack2(a, bb);
    }
    float best = 3.4e38f; int bidx = 0;
    for (int k = 0; k < NCODE; k++) {
        const ulonglong2* cp2 = reinterpret_cast<const ulonglong2*>(cb_s + k*VQ_DIM);
        u64 d0 = 0ull, d1 = 0ull, d2 = 0ull, d3 = 0ull;
#pragma unroll
        for (int u = 0; u < 8; u++) {
            ulonglong2 ca = cp2[2*u], cbv = cp2[2*u+1];
            d0 = fma2(ca.x,  zv2[4*u],   d0);
            d1 = fma2(ca.y,  zv2[4*u+1], d1);
            d2 = fma2(cbv.x, zv2[4*u+2], d2);
            d3 = fma2(cbv.y, zv2[4*u+3], d3);
        }
        float2 dd = unpack2(add2(add2(d0, d1), add2(d2, d3)));
        float dot = dd.x + dd.y;
        float dist = zsq - 2.f*dot + csq[k];
        if (dist < best) { best = dist; bidx = k; }
    }
    float lsum = 0.f;
    float* qp = q + (size_t)b*64*1024 + hw;
#pragma unroll
    for (int u = 0; u < 32; u++) {
        float c0 = cb_s[bidx*VQ_DIM + 2*u];
        float c1 = cb_s[bidx*VQ_DIM + 2*u+1];
        qp[(size_t)(2*u)*1024]   = c0;
        qp[(size_t)(2*u+1)*1024] = c1;
        float2 zz = unpack2(zv2[u]);
        float df0 = zz.x - c0, df1 = zz.y - c1;
        lsum += df0*df0 + df1*df1;
    }
    idx_out[sidx] = (float)bidx;

    __shared__ float red[256];
    red[tid] = lsum; __syncthreads();
    for (int o = 128; o > 0; o >>= 1) {
        if (tid < o) red[tid] += red[tid + o];
        __syncthreads();
    }
    if (tid == 0) losspart[blockIdx.x] = red[0];
}

__global__ void loss_finalize_kernel(const float* __restrict__ losspart,
                                     float* __restrict__ out_losses)
{
    __shared__ float red[256];
    red[threadIdx.x] = losspart[threadIdx.x];
    __syncthreads();
    for (int o = 128; o > 0; o >>= 1) {
        if (threadIdx.x < o) red[threadIdx.x] += red[threadIdx.x + o];
        __syncthreads();
    }
    if (threadIdx.x == 0) {
        float m = red[0] / (65536.f * 64.f);
        out_losses[0] = m;
        out_losses[1] = m;
    }
}

// ---------------- post 1x1: 64->256, f32x2 ----------------
__global__ void post_kernel(const float* __restrict__ in, const float* __restrict__ w,
                            const float* __restrict__ bias, float* __restrict__ out)
{
    __shared__ float w_t[64*64];
    int n = blockIdx.z, coB = blockIdx.y;
    int s = blockIdx.x * 256 + threadIdx.x;
    for (int i = threadIdx.x; i < 64*64; i += 256) {
        int ci = i >> 6, co = i & 63;
        w_t[i] = w[(size_t)(coB*64 + co)*64 + ci];
    }
    __syncthreads();
    u64 acc[32];
#pragma unroll
    for (int k = 0; k < 32; k++) acc[k] = 0ull;
    const float* ip = in + (size_t)n*64*1024 + s;
#pragma unroll 2
    for (int ci = 0; ci < 64; ci++) {
        float v = ip[(size_t)ci*1024];
        u64 pv = pack2(v, v);
        const ulonglong2* wp = reinterpret_cast<const ulonglong2*>(w_t + ci*64);
#pragma unroll
        for (int k = 0; k < 16; k++) {
            ulonglong2 ww = wp[k];
            acc[2*k]   = fma2(ww.x, pv, acc[2*k]);
            acc[2*k+1] = fma2(ww.y, pv, acc[2*k+1]);
        }
    }
    float* op = out + (size_t)n*256*1024 + (size_t)coB*64*1024 + s;
#pragma unroll
    for (int k = 0; k < 32; k++) {
        float2 v = unpack2(acc[k]);
        op[(size_t)(2*k  )*1024] = v.x + bias[coB*64 + 2*k];
        op[(size_t)(2*k+1)*1024] = v.y + bias[coB*64 + 2*k+1];
    }
}

// ---------------- dec1 transpose conv 256->128, cp.async double-buffered, f32x2 ----------------
#define D1_WB 2304
#define D1_IB 864
#define D1_BUF (D1_WB + D1_IB)
__global__ void __launch_bounds__(256, 2) dec1_kernel(
        const float* __restrict__ in, const float* __restrict__ w2,
        const float* __restrict__ bias, float* __restrict__ out)
{
    __shared__ float sm[2*D1_BUF];
    int n = blockIdx.z, coB = blockIdx.x, tile = blockIdx.y;
    int OH0 = (tile >> 2) * 16, OW0 = (tile & 3) * 16;
    int IH0 = OH0 >> 1, IW0 = OW0 >> 1;
    int tid = threadIdx.x;
    int wid = tid >> 5, lane = tid & 31;
    int qy = lane >> 2, qxh = lane & 3;

    uint32_t smaddr = (uint32_t)__cvta_generic_to_shared(sm);

    auto fill = [&](int it, int buf) {
        int ci0 = it * 8;
        uint32_t wdst = smaddr + (buf*D1_BUF)*4;
        const float* wsrc = w2 + ci0*9*128 + coB*32;
        for (int i = tid; i < 576; i += 256) {
            int cit = i >> 3, c4 = i & 7;
            cp16(wdst + (cit*32 + c4*4)*4, wsrc + cit*128 + c4*4);
        }
        uint32_t idst = smaddr + (buf*D1_BUF + D1_WB)*4;
        for (int i = tid; i < D1_IB; i += 256) {
            int ci = i / 108; int rem = i - ci*108; int rr = rem / 12; int cc = rem - rr*12;
            int ih = IH0 + rr, iw = IW0 + cc;
            bool ok = (cc < 9) && (ih < 32) && (iw < 32);
            const float* src = ok ? (in + ((size_t)(n*256 + ci0 + ci)*32 + ih)*32 + iw) : in;
            cp4(idst + i*4, src, ok ? 4 : 0);
        }
    };

    u64 acc[16];
#pragma unroll
    for (int i = 0; i < 16; i++) acc[i] = 0ull;

    fill(0, 0); CP_COMMIT();
    for (int it = 0; it < 32; it++) {
        if (it < 31) { fill(it+1, (it+1)&1); CP_COMMIT(); CP_WAIT(1); }
        else         { CP_WAIT(0); }
        __syncthreads();
        const float* w_s  = sm + (it&1)*D1_BUF;
        const float* in_b = w_s + D1_WB;
#pragma unroll 2
        for (int ci = 0; ci < 8; ci++) {
            const float* ib = in_b + ci*108 + qy*12 + qxh;
            float A00 = ib[0], A01 = ib[1], A10 = ib[12], A11 = ib[13];
            float B00 = ib[4], B01 = ib[5], B10 = ib[16], B11 = ib[17];
            u64 a00 = pack2(A00,A00), a01 = pack2(A01,A01), a10 = pack2(A10,A10), a11 = pack2(A11,A11);
            u64 b00 = pack2(B00,B00), b01 = pack2(B01,B01), b10 = pack2(B10,B10), b11 = pack2(B11,B11);
            const float* wb = w_s + ci*288 + wid*4;
            auto tap = [&](int t, u64 vA, u64 vB, int px) {
                ulonglong2 wv = *reinterpret_cast<const ulonglong2*>(wb + t*32);
                acc[px]      = fma2(wv.x, vA, acc[px]);
                acc[4 + px]  = fma2(wv.x, vB, acc[4 + px]);
                acc[8 + px]  = fma2(wv.y, vA, acc[8 + px]);
                acc[12 + px] = fma2(wv.y, vB, acc[12 + px]);
            };
            tap(4, a00, b00, 0);
            tap(3, a01, b01, 1); tap(5, a00, b00, 1);
            tap(1, a10, b10, 2); tap(7, a00, b00, 2);
            tap(0, a11, b11, 3); tap(2, a10, b10, 3);
            tap(6, a01, b01, 3); tap(8, a00, b00, 3);
        }
        __syncthreads();
    }
    int oh0 = OH0 + qy*2;
#pragma unroll
    for (int cp = 0; cp < 2; cp++) {
        int co0 = coB*32 + wid*4 + cp*2;
        float b0 = bias[co0], b1 = bias[co0+1];
#pragma unroll
        for (int qd = 0; qd < 2; qd++) {
            int ow0 = OW0 + (qxh + qd*4)*2;
            float2 p0 = unpack2(acc[cp*8 + qd*4 + 0]);
            float2 p1 = unpack2(acc[cp*8 + qd*4 + 1]);
            float2 p2 = unpack2(acc[cp*8 + qd*4 + 2]);
            float2 p3 = unpack2(acc[cp*8 + qd*4 + 3]);
            float* o0 = out + ((size_t)(n*128 + co0)*64 + oh0)*64 + ow0;
            float* o1 = out + ((size_t)(n*128 + co0+1)*64 + oh0)*64 + ow0;
            *reinterpret_cast<float2*>(o0)      = make_float2(p0.x + b0, p1.x + b0);
            *reinterpret_cast<float2*>(o0 + 64) = make_float2(p2.x + b0, p3.x + b0);
            *reinterpret_cast<float2*>(o1)      = make_float2(p0.y + b1, p1.y + b1);
            *reinterpret_cast<float2*>(o1 + 64) = make_float2(p2.y + b1, p3.y + b1);
        }
    }
}

// ---------------- dec2 transpose conv 128->3, fused BN+ReLU in, tanh out ----------------
__global__ void dec2_kernel(const float* __restrict__ in, const float* __restrict__ w,
                            const float* __restrict__ bias, const float* __restrict__ scale,
                            const float* __restrict__ shift, float* __restrict__ out)
{
    extern __shared__ float sm[];
    float* w_s  = sm;
    float* in_s = sm + 3456;
    float* sc_s = sm + 17280;
    float* sh_s = sm + 17408;
    int n = blockIdx.y; int tile = blockIdx.x;
    int OH0 = (tile >> 3) * 16, OW0 = (tile & 7) * 16;
    int IH0 = OH0 >> 1, IW0 = OW0 >> 1;
    int tid = threadIdx.x;
    for (int i = tid; i < 3456; i += 256) w_s[i] = w[i];
    for (int i = tid; i < 128; i += 256) { sc_s[i] = scale[i]; sh_s[i] = shift[i]; }
    __syncthreads();
    for (int i = tid; i < 128*108; i += 256) {
        int ci = i / 108; int rem = i - ci*108; int rr = rem / 12; int cc = rem - rr*12;
        int ih = IH0 + rr, iw = IW0 + cc;
        float v = 0.f;
        if (cc < 9 && ih < 64 && iw < 64) {
            float raw = in[((size_t)(n*128 + ci)*64 + ih)*64 + iw];
            v = fmaxf(fmaf(raw, sc_s[ci], sh_s[ci]), 0.f);
        }
        in_s[i] = v;
    }
    __syncthreads();

    int cls = tid >> 6; int pe_h = cls >> 1, pe_w = cls & 1;
    int t3 = tid & 63; int r8 = t3 >> 3, c8 = t3 & 7;
    float acc[3] = {0.f, 0.f, 0.f};
    for (int ci = 0; ci < 128; ci++) {
        const float* base = &in_s[ci*108];
        float v00 = base[r8*12 + c8];
        float v01 = base[r8*12 + c8 + 1];
        float v10 = base[(r8+1)*12 + c8];
        float v11 = base[(r8+1)*12 + c8 + 1];
        const float* wp = &w_s[ci*27];
        if (pe_h == 0) {
            if (pe_w == 0) {
#pragma unroll
                for (int co = 0; co < 3; co++) acc[co] += wp[co*9 + 4] * v00;
            } else {
#pragma unroll
                for (int co = 0; co < 3; co++) acc[co] += wp[co*9 + 3] * v01 + wp[co*9 + 5] * v00;
            }
        } else {
            if (pe_w == 0) {
#pragma unroll
                for (int co = 0; co < 3; co++) acc[co] += wp[co*9 + 1] * v10 + wp[co*9 + 7] * v00;
            } else {
#pragma unroll
                for (int co = 0; co < 3; co++)
                    acc[co] += wp[co*9 + 0]*v11 + wp[co*9 + 2]*v10 + wp[co*9 + 6]*v01 + wp[co*9 + 8]*v00;
            }
        }
    }
    int oh = OH0 + r8*2 + pe_h, ow = OW0 + c8*2 + pe_w;
#pragma unroll
    for (int co = 0; co < 3; co++)
        out[((size_t)(n*3 + co)*128 + oh)*128 + ow] = tanhf(acc[co] + bias[co]);
}

// ---------------- host launch ----------------
static float* sym_addr(const void* sym)
{
    void* p = nullptr;
    cudaGetSymbolAddress(&p, sym);
    return (float*)p;
}

extern "C" void kernel_launch(void* const* d_in, const int* in_sizes, int n_in,
                              void* d_out, int out_size)
{
    const float* x       = (const float*)d_in[0];
    const float* enc1_w  = (const float*)d_in[1];
    const float* enc1_b  = (const float*)d_in[2];
    const float* bn1_g   = (const float*)d_in[3];
    const float* bn1_b   = (const float*)d_in[4];
    const float* enc2_w  = (const float*)d_in[5];
    const float* enc2_b  = (const float*)d_in[6];
    const float* pre_w   = (const float*)d_in[7];
    const float* pre_b   = (const float*)d_in[8];
    const float* codebook= (const float*)d_in[9];
    const float* post_w  = (const float*)d_in[10];
    const float* post_b  = (const float*)d_in[11];
    const float* dec1_w  = (const float*)d_in[12];
    const float* dec1_b  = (const float*)d_in[13];
    const float* dbn1_g  = (const float*)d_in[14];
    const float* dbn1_b  = (const float*)d_in[15];
    const float* dec2_w  = (const float*)d_in[16];
    const float* dec2_b  = (const float*)d_in[17];

    float* out = (float*)d_out;
    float* out_losses = out + RECON_ELEMS;
    float* out_idx    = out + RECON_ELEMS + 2;

    float* h1  = sym_addr(g_h1);
    __nv_bfloat16* h1hi; { void* p; cudaGetSymbolAddress(&p, g_h1hi); h1hi = (__nv_bfloat16*)p; }
    __nv_bfloat16* h1lo; { void* p; cudaGetSymbolAddress(&p, g_h1lo); h1lo = (__nv_bfloat16*)p; }
    __nv_bfloat16* w2chi; { void* p; cudaGetSymbolAddress(&p, g_w2chi); w2chi = (__nv_bfloat16*)p; }
    __nv_bfloat16* w2clo; { void* p; cudaGetSymbolAddress(&p, g_w2clo); w2clo = (__nv_bfloat16*)p; }
    float* h2  = sym_addr(g_h2);
    float* z   = sym_addr(g_z);
    float* q   = sym_addr(g_q);
    float* d   = sym_addr(g_d);
    float* d1  = sym_addr(g_d1);
    float* w2d = sym_addr(g_w2d);
    float* psum = sym_addr(g_psum);
    float* psq  = sym_addr(g_psq);
    float* sc   = sym_addr(g_scale);
    float* sh   = sym_addr(g_shift);
    float* lp   = sym_addr(g_losspart);

    const unsigned MM_SMEM = 2*MM_STAGE + 1024;   // 132096
    cudaFuncSetAttribute(conv2_mma_kernel, cudaFuncAttributeMaxDynamicSharedMemorySize, MM_SMEM);
    cudaFuncSetAttribute(vq_kernel,   cudaFuncAttributeMaxDynamicSharedMemorySize, 133120);
    cudaFuncSetAttribute(dec2_kernel, cudaFuncAttributeMaxDynamicSharedMemorySize, 70144);

    const float inv_cnt = 1.f / 262144.f;

    // weight prep
    wtrans_conv2_bf16<<<1152, 256>>>(enc2_w, w2chi, w2clo);
    wtrans_dec1<<<1152, 256>>>(dec1_w, w2d);

    // encoder
    conv1_kernel<<<dim3(4,4,64), 256>>>(x, enc1_w, enc1_b, h1);       // NHWC fp32
    bn_stats_nhwc<<<256, 256>>>(h1, psum, psq, 256);
    bn_finalize_kernel<<<1,128>>>(psum, psq, bn1_g, bn1_b, sc, sh, 256, inv_cnt);
    bnrelu_split_kernel<<<32768, 256>>>(h1, h1hi, h1lo, sc, sh);
    conv2_mma_kernel<<<dim3(8,2,64), 256, MM_SMEM>>>(h1hi, h1lo, w2chi, w2clo, enc2_b, h2);
    pre_kernel<<<dim3(4,2,64), 256>>>(h2, pre_w, pre_b, z);

    // VQ
    vq_kernel<<<256, 256, 133120>>>(z, codebook, q, out_idx, lp);
    loss_finalize_kernel<<<1,256>>>(lp, out_losses);

    // decoder
    post_kernel<<<dim3(4,4,64), 256>>>(q, post_w, post_b, d);
    dec1_kernel<<<dim3(4,16,64), 256>>>(d, w2d, dec1_b, d1);
    bn_stats_kernel<<<dim3(128,32), 256>>>(d1, psum, psq, 128, 32);
    bn_finalize_kernel<<<1,128>>>(psum, psq, dbn1_g, dbn1_b, sc, sh, 32, inv_cnt);
    dec2_kernel<<<dim3(64,64), 256, 70144>>>(d1, dec2_w, dec2_b, sc, sh, out);

    (void)in_sizes; (void)n_in; (void)out_size;
}

// round 9
// speedup vs baseline: 2.5385x; 1.4031x over previous
#include <cuda_runtime.h>
#include <cuda_bf16.h>
#include <cstdint>

#define H1_ELEMS (64*128*64*64)
#define H2_ELEMS (64*256*32*32)
#define Z_ELEMS  (64*64*32*32)
#define D_ELEMS  (64*256*32*32)
#define D1_ELEMS (64*128*64*64)
#define RECON_ELEMS (64*3*128*128)
#define VQ_DIM 64
#define NCODE 512

__device__ float g_h1[H1_ELEMS];                 // NHWC fp32
__device__ __nv_bfloat16 g_h1hi[H1_ELEMS];       // NHWC bf16 hi
__device__ __nv_bfloat16 g_h1lo[H1_ELEMS];       // NHWC bf16 lo
__device__ float g_h2[H2_ELEMS];
__device__ float g_z[Z_ELEMS];
__device__ float g_q[Z_ELEMS];
__device__ float g_d[D_ELEMS];                   // NCHW fp32
__device__ __nv_bfloat16 g_dhi[D_ELEMS];         // NHWC bf16 hi
__device__ __nv_bfloat16 g_dlo[D_ELEMS];         // NHWC bf16 lo
__device__ float g_d1[D1_ELEMS];
__device__ __nv_bfloat16 g_w2chi[256*1152];      // [co][t][ci] bf16 hi
__device__ __nv_bfloat16 g_w2clo[256*1152];
__device__ __nv_bfloat16 g_wd1hi[128*2304];      // [co][clsk] bf16 hi
__device__ __nv_bfloat16 g_wd1lo[128*2304];
__device__ float g_psum[128*256];
__device__ float g_psq[128*256];
__device__ float g_scale[128];
__device__ float g_shift[128];
__device__ float g_losspart[256];

typedef unsigned long long u64;
__device__ __forceinline__ u64 pack2(float a, float b) {
    u64 r; asm("mov.b64 %0, {%1,%2};" : "=l"(r) : "f"(a), "f"(b)); return r;
}
__device__ __forceinline__ u64 fma2(u64 a, u64 b, u64 c) {
    u64 d; asm("fma.rn.f32x2 %0, %1, %2, %3;" : "=l"(d) : "l"(a), "l"(b), "l"(c)); return d;
}
__device__ __forceinline__ u64 add2(u64 a, u64 b) {
    u64 d; asm("add.rn.f32x2 %0, %1, %2;" : "=l"(d) : "l"(a), "l"(b)); return d;
}
__device__ __forceinline__ float2 unpack2(u64 a) {
    float lo, hi; asm("mov.b64 {%0,%1}, %2;" : "=f"(lo), "=f"(hi) : "l"(a));
    return make_float2(lo, hi);
}
__device__ __forceinline__ void cp16(uint32_t saddr, const void* gaddr) {
    asm volatile("cp.async.cg.shared.global [%0], [%1], 16;" :: "r"(saddr), "l"(gaddr));
}
__device__ __forceinline__ void cp16z(uint32_t saddr, const void* gaddr, bool ok) {
    int sz = ok ? 16 : 0;
    asm volatile("cp.async.cg.shared.global [%0], [%1], 16, %2;" :: "r"(saddr), "l"(gaddr), "r"(sz));
}
#define CP_COMMIT() asm volatile("cp.async.commit_group;")
#define CP_WAIT(n)  asm volatile("cp.async.wait_group %0;" :: "n"(n))

#define SWZ(o) ((o) ^ ((((uint32_t)(o)) >> 3) & 0x70))

__device__ __forceinline__ void ldsm4(uint32_t* r, uint32_t addr) {
    asm volatile("ldmatrix.sync.aligned.m8n8.x4.shared.b16 {%0,%1,%2,%3}, [%4];"
                 : "=r"(r[0]), "=r"(r[1]), "=r"(r[2]), "=r"(r[3]) : "r"(addr));
}
__device__ __forceinline__ void mma16816(float* c, const uint32_t* a, const uint32_t* b) {
    asm volatile(
        "mma.sync.aligned.m16n8k16.row.col.f32.bf16.bf16.f32 "
        "{%0,%1,%2,%3}, {%4,%5,%6,%7}, {%8,%9}, {%0,%1,%2,%3};"
        : "+f"(c[0]), "+f"(c[1]), "+f"(c[2]), "+f"(c[3])
        : "r"(a[0]), "r"(a[1]), "r"(a[2]), "r"(a[3]), "r"(b[0]), "r"(b[1]));
}

// ---------------- weight prep ----------------
__global__ void wtrans_conv2_bf16(const float* __restrict__ w,
                                  __nv_bfloat16* __restrict__ whi, __nv_bfloat16* __restrict__ wlo)
{
    int i = blockIdx.x * 256 + threadIdx.x;
    if (i >= 256*1152) return;
    int co = i / 1152; int rem = i - co*1152; int t = rem >> 7; int ci = rem & 127;
    float v = w[((size_t)co*128 + ci)*9 + t];
    __nv_bfloat16 h = __float2bfloat16(v);
    whi[i] = h;
    wlo[i] = __float2bfloat16(v - __bfloat162float(h));
}

// dec1 weights: [co][clsk], clsk = kofs[cls] + tap*256 + ci; tap->(kh,kw) per class table.
__global__ void wtrans_dec1_bf16(const float* __restrict__ w,
                                 __nv_bfloat16* __restrict__ whi, __nv_bfloat16* __restrict__ wlo)
{
    int i = blockIdx.x * 256 + threadIdx.x;
    if (i >= 128*2304) return;
    int co = i / 2304; int k = i - co*2304;
    int kh, kw, ci;
    if (k < 256)       { kh = 1; kw = 1; ci = k; }
    else if (k < 768)  { int t = (k-256) >> 8; ci = (k-256) & 255; kh = 1; kw = t ? 2 : 0; }
    else if (k < 1280) { int t = (k-768) >> 8; ci = (k-768) & 255; kh = t ? 2 : 0; kw = 1; }
    else               { int t = (k-1280) >> 8; ci = (k-1280) & 255;
                         kh = (t < 2) ? 0 : 2; kw = (t & 1) ? 2 : 0; }
    float v = w[((size_t)ci*128 + co)*9 + kh*3 + kw];
    __nv_bfloat16 h = __float2bfloat16(v);
    whi[i] = h;
    wlo[i] = __float2bfloat16(v - __bfloat162float(h));
}

// ---------------- conv1: 3->128, s2, NHWC output ----------------
__global__ void conv1_kernel(const float* __restrict__ x, const float* __restrict__ w,
                             const float* __restrict__ bias, float* __restrict__ out)
{
    __shared__ float w_s[128*28];
    __shared__ float in_s[3*33*33];
    int n = blockIdx.z;
    int OH0 = blockIdx.y * 16, OW0 = blockIdx.x * 16;
    int tid = threadIdx.x;
    for (int i = tid; i < 128*27; i += 256) { int co = i / 27, t = i - co*27; w_s[co*28 + t] = w[i]; }
    for (int co = tid; co < 128; co += 256) w_s[co*28 + 27] = 0.f;
    int IH0 = OH0*2 - 1, IW0 = OW0*2 - 1;
    for (int i = tid; i < 3*33*33; i += 256) {
        int ci = i / 1089; int r = (i % 1089) / 33; int c = i % 33;
        int ih = IH0 + r, iw = IW0 + c;
        float v = 0.f;
        if (ih >= 0 && ih < 128 && iw >= 0 && iw < 128) v = x[((n*3 + ci)*128 + ih)*128 + iw];
        in_s[i] = v;
    }
    __syncthreads();
    int ty = tid >> 4, tx = tid & 15;
    float in_r[28];
#pragma unroll
    for (int ci = 0; ci < 3; ci++)
#pragma unroll
        for (int kh = 0; kh < 3; kh++)
#pragma unroll
            for (int kw = 0; kw < 3; kw++)
                in_r[ci*9 + kh*3 + kw] = in_s[ci*1089 + (ty*2+kh)*33 + (tx*2+kw)];
    in_r[27] = 0.f;
    int oh = OH0 + ty, ow = OW0 + tx;
    float* outp = out + (((size_t)n*64 + oh)*64 + ow)*128;
    const float4* w4p = reinterpret_cast<const float4*>(w_s);
    for (int cg = 0; cg < 32; cg++) {
        float4 res;
        float* rp = &res.x;
#pragma unroll
        for (int j = 0; j < 4; j++) {
            int co = cg*4 + j;
            float acc = bias[co];
#pragma unroll
            for (int u = 0; u < 7; u++) {
                float4 w4 = w4p[co*7 + u];
                acc += w4.x*in_r[u*4] + w4.y*in_r[u*4+1] + w4.z*in_r[u*4+2] + w4.w*in_r[u*4+3];
            }
            rp[j] = acc;
        }
        reinterpret_cast<float4*>(outp)[cg] = res;
    }
}

// ---------------- BN stats NHWC (for h1) ----------------
__global__ void bn_stats_nhwc(const float* __restrict__ x, float* __restrict__ psum,
                              float* __restrict__ psq, int nblk)
{
    int blk = blockIdx.x;
    int cg = threadIdx.x & 31;
    int rg = threadIdx.x >> 5;
    float4 s = make_float4(0,0,0,0), sq = make_float4(0,0,0,0);
    for (int r = blk*8 + rg; r < 262144; r += nblk*8) {
        float4 v = *reinterpret_cast<const float4*>(x + (size_t)r*128 + cg*4);
        s.x += v.x; s.y += v.y; s.z += v.z; s.w += v.w;
        sq.x += v.x*v.x; sq.y += v.y*v.y; sq.z += v.z*v.z; sq.w += v.w*v.w;
    }
    __shared__ float ss[256*4], qs[256*4];
    reinterpret_cast<float4*>(ss)[threadIdx.x] = s;
    reinterpret_cast<float4*>(qs)[threadIdx.x] = sq;
    __syncthreads();
    if (threadIdx.x < 128) {
        int c = threadIdx.x;
        int cgi = c >> 2, j = c & 3;
        float a = 0.f, b = 0.f;
        for (int g = 0; g < 8; g++) { a += ss[(g*32+cgi)*4 + j]; b += qs[(g*32+cgi)*4 + j]; }
        psum[c*nblk + blk] = a;
        psq[c*nblk + blk] = b;
    }
}

// ---------------- BN stats NCHW (for d1) ----------------
__global__ void bn_stats_kernel(const float* __restrict__ x, float* __restrict__ psum,
                                float* __restrict__ psq, int C, int nblk)
{
    int c = blockIdx.x, blk = blockIdx.y;
    float s = 0.f, sq = 0.f;
    int total4 = 64 * 1024;
    for (int i = blk*256 + threadIdx.x; i < total4; i += nblk*256) {
        int n = i >> 10, off = i & 1023;
        const float4* p = reinterpret_cast<const float4*>(x + ((size_t)(n*C + c))*4096);
        float4 v = p[off];
        s  += v.x + v.y + v.z + v.w;
        sq += v.x*v.x + v.y*v.y + v.z*v.z + v.w*v.w;
    }
    __shared__ float rs[256], rq[256];
    rs[threadIdx.x] = s; rq[threadIdx.x] = sq;
    __syncthreads();
    for (int o = 128; o > 0; o >>= 1) {
        if (threadIdx.x < o) { rs[threadIdx.x] += rs[threadIdx.x+o]; rq[threadIdx.x] += rq[threadIdx.x+o]; }
        __syncthreads();
    }
    if (threadIdx.x == 0) { psum[c*nblk + blk] = rs[0]; psq[c*nblk + blk] = rq[0]; }
}

__global__ void bn_finalize_kernel(const float* __restrict__ psum, const float* __restrict__ psq,
                                   const float* __restrict__ g, const float* __restrict__ b,
                                   float* __restrict__ scale, float* __restrict__ shift,
                                   int nblk, float inv_count)
{
    int c = threadIdx.x;
    float s = 0.f, sq = 0.f;
    for (int i = 0; i < nblk; i++) { s += psum[c*nblk + i]; sq += psq[c*nblk + i]; }
    float mean = s * inv_count;
    float var = sq * inv_count - mean*mean;
    float r = rsqrtf(var + 1e-5f);
    float sc = g[c] * r;
    scale[c] = sc;
    shift[c] = b[c] - mean * sc;
}

// ---------------- BN+ReLU + bf16 split (NHWC fp32 -> NHWC bf16 hi/lo) ----------------
__global__ void bnrelu_split_kernel(const float* __restrict__ x,
                                    __nv_bfloat16* __restrict__ hi, __nv_bfloat16* __restrict__ lo,
                                    const float* __restrict__ sc, const float* __restrict__ sh)
{
    long i = (long)blockIdx.x * 256 + threadIdx.x;   // float4 index
    if (i >= 8388608L) return;
    int c = (int)(i & 31) * 4;
    float4 v = reinterpret_cast<const float4*>(x)[i];
    float r0 = fmaxf(fmaf(v.x, sc[c+0], sh[c+0]), 0.f);
    float r1 = fmaxf(fmaf(v.y, sc[c+1], sh[c+1]), 0.f);
    float r2 = fmaxf(fmaf(v.z, sc[c+2], sh[c+2]), 0.f);
    float r3 = fmaxf(fmaf(v.w, sc[c+3], sh[c+3]), 0.f);
    __nv_bfloat16 h0 = __float2bfloat16(r0), h1 = __float2bfloat16(r1);
    __nv_bfloat16 h2 = __float2bfloat16(r2), h3 = __float2bfloat16(r3);
    __nv_bfloat16 l0 = __float2bfloat16(r0 - __bfloat162float(h0));
    __nv_bfloat16 l1 = __float2bfloat16(r1 - __bfloat162float(h1));
    __nv_bfloat16 l2 = __float2bfloat16(r2 - __bfloat162float(h2));
    __nv_bfloat16 l3 = __float2bfloat16(r3 - __bfloat162float(h3));
    __nv_bfloat162* hp = reinterpret_cast<__nv_bfloat162*>(hi);
    __nv_bfloat162* lp = reinterpret_cast<__nv_bfloat162*>(lo);
    hp[2*i]   = __nv_bfloat162(h0, h1);
    hp[2*i+1] = __nv_bfloat162(h2, h3);
    lp[2*i]   = __nv_bfloat162(l0, l1);
    lp[2*i+1] = __nv_bfloat162(l2, l3);
}

// ---------------- d: NCHW fp32 -> NHWC bf16 hi/lo (tiled transpose + split) ----------------
// grid (cblk=8, pblk=16, n=64); tile 32 ch x 64 px.
__global__ void split_d_nhwc(const float* __restrict__ in,
                             __nv_bfloat16* __restrict__ hi, __nv_bfloat16* __restrict__ lo)
{
    __shared__ float t[32][65];
    int n = blockIdx.z, cb = blockIdx.x, pb = blockIdx.y;
    int c0 = cb*32, p0 = pb*64;
    int tid = threadIdx.x;
    for (int i = tid; i < 512; i += 256) {
        int c = i >> 4, q = (i & 15) * 4;
        float4 v = *reinterpret_cast<const float4*>(in + ((size_t)(n*256 + c0 + c))*1024 + p0 + q);
        t[c][q] = v.x; t[c][q+1] = v.y; t[c][q+2] = v.z; t[c][q+3] = v.w;
    }
    __syncthreads();
    for (int i = tid; i < 1024; i += 256) {
        int p = i >> 4, c = (i & 15) * 2;
        float v0 = t[c][p], v1 = t[c+1][p];
        __nv_bfloat16 h0 = __float2bfloat16(v0), h1 = __float2bfloat16(v1);
        __nv_bfloat16 l0 = __float2bfloat16(v0 - __bfloat162float(h0));
        __nv_bfloat16 l1 = __float2bfloat16(v1 - __bfloat162float(h1));
        size_t o2 = ((size_t)(n*1024 + p0 + p)*256 + c0 + c) >> 1;
        reinterpret_cast<__nv_bfloat162*>(hi)[o2] = __nv_bfloat162(h0, h1);
        reinterpret_cast<__nv_bfloat162*>(lo)[o2] = __nv_bfloat162(l0, l1);
    }
}

// ---------------- conv2 via mma.sync bf16 split ----------------
#define MM_SPLIT 16384u
#define MM_STAGE (4u*MM_SPLIT)
__global__ void __launch_bounds__(256, 1) conv2_mma_kernel(
        const __nv_bfloat16* __restrict__ inhi, const __nv_bfloat16* __restrict__ inlo,
        const __nv_bfloat16* __restrict__ whi, const __nv_bfloat16* __restrict__ wlo,
        const float* __restrict__ bias, float* __restrict__ out)
{
    extern __shared__ char dsm[];
    __shared__ float bias_s[128];
    int mt = blockIdx.x, Nt = blockIdx.y, n = blockIdx.z;
    int OH0 = mt * 4;
    int tid = threadIdx.x, wid = tid >> 5, lane = tid & 31;
    int mrow = (wid >> 1) * 32;
    int ncol = (wid & 1) * 64;

    uint32_t base0 = ((uint32_t)__cvta_generic_to_shared(dsm) + 1023u) & ~1023u;
    for (int i = tid; i < 128; i += 256) bias_s[i] = bias[Nt*128 + i];

    auto fill = [&](int kc, int buf) {
        int t = kc >> 1, ci0 = (kc & 1) << 6;
        int kh = t / 3, kw = t - (t/3)*3;
        uint32_t Ah = base0 + buf*MM_STAGE;
        uint32_t Al = Ah + MM_SPLIT;
        uint32_t Bh = Al + MM_SPLIT;
        uint32_t Bl = Bh + MM_SPLIT;
        for (int i = tid; i < 1024; i += 256) {
            int px = i >> 3, c16 = i & 7;
            int oh = OH0 + (px >> 5), ow = px & 31;
            int ih = 2*oh - 1 + kh, iw = 2*ow - 1 + kw;
            bool ok = (ih >= 0) && (ih < 64) && (iw >= 0) && (iw < 64);
            long off = ((long)(n*64 + (ok ? ih : 0))*64 + (ok ? iw : 0))*128 + ci0 + c16*8;
            uint32_t d = SWZ(px*128 + c16*16);
            cp16z(Ah + d, inhi + off, ok);
            cp16z(Al + d, inlo + off, ok);
        }
        for (int i = tid; i < 1024; i += 256) {
            int co = i >> 3, c16 = i & 7;
            long off = (long)(Nt*128 + co)*1152 + t*128 + ci0 + c16*8;
            uint32_t d = SWZ(co*128 + c16*16);
            cp16(Bh + d, whi + off);
            cp16(Bl + d, wlo + off);
        }
    };

    float acc[2][8][4];
#pragma unroll
    for (int a = 0; a < 2; a++)
#pragma unroll
        for (int b = 0; b < 8; b++)
#pragma unroll
            for (int c = 0; c < 4; c++) acc[a][b][c] = 0.f;

    fill(0, 0); CP_COMMIT();
    for (int s = 0; s < 18; s++) {
        if (s < 17) { fill(s+1, (s+1)&1); CP_COMMIT(); CP_WAIT(1); }
        else        { CP_WAIT(0); }
        __syncthreads();
        uint32_t Ah = base0 + (s&1)*MM_STAGE;
        uint32_t Al = Ah + MM_SPLIT;
        uint32_t Bh = Al + MM_SPLIT;
        uint32_t Bl = Bh + MM_SPLIT;
#pragma unroll
        for (int ks = 0; ks < 4; ks++) {
            uint32_t ah[2][4], al[2][4], bh[4][4], bl[4][4];
#pragma unroll
            for (int mi = 0; mi < 2; mi++) {
                int row = mrow + mi*16 + (lane & 15);
                uint32_t ao = SWZ(row*128 + ks*32 + (lane >> 4)*16);
                ldsm4(ah[mi], Ah + ao);
                ldsm4(al[mi], Al + ao);
            }
#pragma unroll
            for (int nb = 0; nb < 4; nb++) {
                int g = lane >> 3, r = lane & 7;
                int co_l = ncol + nb*16 + ((g >> 1) << 3) + r;
                uint32_t bo = SWZ(co_l*128 + ks*32 + (g & 1)*16);
                ldsm4(bh[nb], Bh + bo);
                ldsm4(bl[nb], Bl + bo);
            }
#pragma unroll
            for (int mi = 0; mi < 2; mi++)
#pragma unroll
                for (int nt = 0; nt < 8; nt++) {
                    const uint32_t* pbh = &bh[nt >> 1][(nt & 1)*2];
                    const uint32_t* pbl = &bl[nt >> 1][(nt & 1)*2];
                    mma16816(acc[mi][nt], ah[mi], pbh);
                    mma16816(acc[mi][nt], ah[mi], pbl);
                    mma16816(acc[mi][nt], al[mi], pbh);
                }
        }
        __syncthreads();
    }

    float* osm = reinterpret_cast<float*>(dsm);
#pragma unroll
    for (int mi = 0; mi < 2; mi++)
#pragma unroll
        for (int nt = 0; nt < 8; nt++) {
            int px0 = mrow + mi*16 + (lane >> 2);
            int col = ncol + nt*8 + (lane & 3)*2;
            osm[col*132 + px0]         = acc[mi][nt][0];
            osm[(col+1)*132 + px0]     = acc[mi][nt][1];
            osm[col*132 + px0 + 8]     = acc[mi][nt][2];
            osm[(col+1)*132 + px0 + 8] = acc[mi][nt][3];
        }
    __syncthreads();
    for (int i = tid; i < 128*32; i += 256) {
        int co = i >> 5, p4 = (i & 31)*4;
        float4 v = *reinterpret_cast<const float4*>(osm + co*132 + p4);
        float b = bias_s[co];
        v.x += b; v.y += b; v.z += b; v.w += b;
        int cog = Nt*128 + co;
        *reinterpret_cast<float4*>(out + ((size_t)(n*256 + cog))*1024 + OH0*32 + p4) = v;
    }
}

// ---------------- dec1 via mma.sync bf16 split (parity-class implicit GEMM) ----------------
// grid (mt=8, cls=4, n=64); block 256 = 8 warps. M=128 class-px, N=128 co, K=ntaps*256.
__global__ void __launch_bounds__(256, 1) dec1_mma_kernel(
        const __nv_bfloat16* __restrict__ inhi, const __nv_bfloat16* __restrict__ inlo,
        const __nv_bfloat16* __restrict__ whi, const __nv_bfloat16* __restrict__ wlo,
        const float* __restrict__ bias, float* __restrict__ out)
{
    extern __shared__ char dsm[];
    __shared__ float bias_s[128];
    const int NKC[4]  = {4, 8, 8, 16};          // k-chunks (ntaps*4)
    const int KOFS[4] = {0, 256, 768, 1280};
    const int DYT[4][4] = {{0,0,0,0},{0,0,0,0},{1,0,0,0},{1,1,0,0}};
    const int DXT[4][4] = {{0,0,0,0},{1,0,0,0},{0,0,0,0},{1,0,1,0}};

    int mt = blockIdx.x, cls = blockIdx.y, n = blockIdx.z;
    int ph = cls >> 1, pw = cls & 1;
    int Y0 = mt * 4;
    int tid = threadIdx.x, wid = tid >> 5, lane = tid & 31;
    int mrow = (wid >> 1) * 32;
    int ncol = (wid & 1) * 64;

    uint32_t base0 = ((uint32_t)__cvta_generic_to_shared(dsm) + 1023u) & ~1023u;
    for (int i = tid; i < 128; i += 256) bias_s[i] = bias[i];

    int kbase = KOFS[cls];
    int nk = NKC[cls];

    auto fill = [&](int kc, int buf) {
        int t = kc >> 2, ci0 = (kc & 3) << 6;
        int dy = DYT[cls][t], dx = DXT[cls][t];
        uint32_t Ah = base0 + buf*MM_STAGE;
        uint32_t Al = Ah + MM_SPLIT;
        uint32_t Bh = Al + MM_SPLIT;
        uint32_t Bl = Bh + MM_SPLIT;
        for (int i = tid; i < 1024; i += 256) {
            int px = i >> 3, c16 = i & 7;
            int y = Y0 + (px >> 5), x = px & 31;
            int iy = y + dy, ix = x + dx;
            bool ok = (iy < 32) && (ix < 32);
            long off = ((long)(n*32 + (ok ? iy : 0))*32 + (ok ? ix : 0))*256 + ci0 + c16*8;
            uint32_t d = SWZ(px*128 + c16*16);
            cp16z(Ah + d, inhi + off, ok);
            cp16z(Al + d, inlo + off, ok);
        }
        for (int i = tid; i < 1024; i += 256) {
            int co = i >> 3, c16 = i & 7;
            long off = (long)co*2304 + kbase + t*256 + ci0 + c16*8;
            uint32_t d = SWZ(co*128 + c16*16);
            cp16(Bh + d, whi + off);
            cp16(Bl + d, wlo + off);
        }
    };

    float acc[2][8][4];
#pragma unroll
    for (int a = 0; a < 2; a++)
#pragma unroll
        for (int b = 0; b < 8; b++)
#pragma unroll
            for (int c = 0; c < 4; c++) acc[a][b][c] = 0.f;

    fill(0, 0); CP_COMMIT();
    for (int s = 0; s < nk; s++) {
        if (s < nk-1) { fill(s+1, (s+1)&1); CP_COMMIT(); CP_WAIT(1); }
        else          { CP_WAIT(0); }
        __syncthreads();
        uint32_t Ah = base0 + (s&1)*MM_STAGE;
        uint32_t Al = Ah + MM_SPLIT;
        uint32_t Bh = Al + MM_SPLIT;
        uint32_t Bl = Bh + MM_SPLIT;
#pragma unroll
        for (int ks = 0; ks < 4; ks++) {
            uint32_t ah[2][4], al[2][4], bh[4][4], bl[4][4];
#pragma unroll
            for (int mi = 0; mi < 2; mi++) {
                int row = mrow + mi*16 + (lane & 15);
                uint32_t ao = SWZ(row*128 + ks*32 + (lane >> 4)*16);
                ldsm4(ah[mi], Ah + ao);
                ldsm4(al[mi], Al + ao);
            }
#pragma unroll
            for (int nb = 0; nb < 4; nb++) {
                int g = lane >> 3, r = lane & 7;
                int co_l = ncol + nb*16 + ((g >> 1) << 3) + r;
                uint32_t bo = SWZ(co_l*128 + ks*32 + (g & 1)*16);
                ldsm4(bh[nb], Bh + bo);
                ldsm4(bl[nb], Bl + bo);
            }
#pragma unroll
            for (int mi = 0; mi < 2; mi++)
#pragma unroll
                for (int nt = 0; nt < 8; nt++) {
                    const uint32_t* pbh = &bh[nt >> 1][(nt & 1)*2];
                    const uint32_t* pbl = &bl[nt >> 1][(nt & 1)*2];
                    mma16816(acc[mi][nt], ah[mi], pbh);
                    mma16816(acc[mi][nt], ah[mi], pbl);
                    mma16816(acc[mi][nt], al[mi], pbh);
                }
        }
        __syncthreads();
    }

    float* osm = reinterpret_cast<float*>(dsm);
#pragma unroll
    for (int mi = 0; mi < 2; mi++)
#pragma unroll
        for (int nt = 0; nt < 8; nt++) {
            int px0 = mrow + mi*16 + (lane >> 2);
            int col = ncol + nt*8 + (lane & 3)*2;
            osm[col*132 + px0]         = acc[mi][nt][0];
            osm[(col+1)*132 + px0]     = acc[mi][nt][1];
            osm[col*132 + px0 + 8]     = acc[mi][nt][2];
            osm[(col+1)*132 + px0 + 8] = acc[mi][nt][3];
        }
    __syncthreads();
    for (int i = tid; i < 128*128; i += 256) {
        int co = i >> 7, p = i & 127;
        int y = Y0 + (p >> 5), x = p & 31;
        int oh = 2*y + ph, ow = 2*x + pw;
        out[((size_t)(n*128 + co)*64 + oh)*64 + ow] = osm[co*132 + p] + bias_s[co];
    }
}

// ---------------- pre 1x1: 256->64, f32x2 ----------------
__global__ void pre_kernel(const float* __restrict__ in, const float* __restrict__ w,
                           const float* __restrict__ bias, float* __restrict__ out)
{
    __shared__ float w_t[256*32];
    int n = blockIdx.z, coH = blockIdx.y;
    int s = blockIdx.x * 256 + threadIdx.x;
    for (int i = threadIdx.x; i < 256*32; i += 256) {
        int ci = i >> 5, co = i & 31;
        w_t[i] = w[(size_t)(coH*32 + co)*256 + ci];
    }
    __syncthreads();
    u64 acc[16];
#pragma unroll
    for (int k = 0; k < 16; k++) acc[k] = 0ull;
    const float* ip = in + (size_t)n*256*1024 + s;
#pragma unroll 4
    for (int ci = 0; ci < 256; ci++) {
        float v = ip[(size_t)ci*1024];
        u64 pv = pack2(v, v);
        const ulonglong2* wp = reinterpret_cast<const ulonglong2*>(w_t + ci*32);
#pragma unroll
        for (int k = 0; k < 8; k++) {
            ulonglong2 ww = wp[k];
            acc[2*k]   = fma2(ww.x, pv, acc[2*k]);
            acc[2*k+1] = fma2(ww.y, pv, acc[2*k+1]);
        }
    }
    float* op = out + (size_t)n*64*1024 + (size_t)coH*32*1024 + s;
#pragma unroll
    for (int k = 0; k < 16; k++) {
        float2 v = unpack2(acc[k]);
        op[(size_t)(2*k  )*1024] = v.x + bias[coH*32 + 2*k];
        op[(size_t)(2*k+1)*1024] = v.y + bias[coH*32 + 2*k+1];
    }
}

// ---------------- VQ (f32x2) ----------------
__global__ void vq_kernel(const float* __restrict__ z, const float* __restrict__ cb,
                          float* __restrict__ q, float* __restrict__ idx_out,
                          float* __restrict__ losspart)
{
    extern __shared__ float sm[];
    float* cb_s = sm;
    float* csq  = sm + NCODE*VQ_DIM;
    int tid = threadIdx.x;
    for (int i = tid; i < NCODE*VQ_DIM; i += 256) cb_s[i] = cb[i];
    __syncthreads();
    for (int k = tid; k < NCODE; k += 256) {
        float s = 0.f;
#pragma unroll
        for (int d = 0; d < VQ_DIM; d++) { float c = cb_s[k*VQ_DIM + d]; s += c*c; }
        csq[k] = s;
    }
    __syncthreads();

    int sidx = blockIdx.x * 256 + tid;
    int b = sidx >> 10, hw = sidx & 1023;
    const float* zp = z + (size_t)b*64*1024 + hw;
    u64 zv2[32];
    float zsq = 0.f;
#pragma unroll
    for (int u = 0; u < 32; u++) {
        float a = zp[(size_t)(2*u)*1024];
        float bb = zp[(size_t)(2*u+1)*1024];
        zsq += a*a + bb*bb;
        zv2[u] = pack2(a, bb);
    }
    float best = 3.4e38f; int bidx = 0;
    for (int k = 0; k < NCODE; k++) {
        const ulonglong2* cp2 = reinterpret_cast<const ulonglong2*>(cb_s + k*VQ_DIM);
        u64 d0 = 0ull, d1 = 0ull, d2 = 0ull, d3 = 0ull;
#pragma unroll
        for (int u = 0; u < 8; u++) {
            ulonglong2 ca = cp2[2*u], cbv = cp2[2*u+1];
            d0 = fma2(ca.x,  zv2[4*u],   d0);
            d1 = fma2(ca.y,  zv2[4*u+1], d1);
            d2 = fma2(cbv.x, zv2[4*u+2], d2);
            d3 = fma2(cbv.y, zv2[4*u+3], d3);
        }
        float2 dd = unpack2(add2(add2(d0, d1), add2(d2, d3)));
        float dot = dd.x + dd.y;
        float dist = zsq - 2.f*dot + csq[k];
        if (dist < best) { best = dist; bidx = k; }
    }
    float lsum = 0.f;
    float* qp = q + (size_t)b*64*1024 + hw;
#pragma unroll
    for (int u = 0; u < 32; u++) {
        float c0 = cb_s[bidx*VQ_DIM + 2*u];
        float c1 = cb_s[bidx*VQ_DIM + 2*u+1];
        qp[(size_t)(2*u)*1024]   = c0;
        qp[(size_t)(2*u+1)*1024] = c1;
        float2 zz = unpack2(zv2[u]);
        float df0 = zz.x - c0, df1 = zz.y - c1;
        lsum += df0*df0 + df1*df1;
    }
    idx_out[sidx] = (float)bidx;

    __shared__ float red[256];
    red[tid] = lsum; __syncthreads();
    for (int o = 128; o > 0; o >>= 1) {
        if (tid < o) red[tid] += red[tid + o];
        __syncthreads();
    }
    if (tid == 0) losspart[blockIdx.x] = red[0];
}

__global__ void loss_finalize_kernel(const float* __restrict__ losspart,
                                     float* __restrict__ out_losses)
{
    __shared__ float red[256];
    red[threadIdx.x] = losspart[threadIdx.x];
    __syncthreads();
    for (int o = 128; o > 0; o >>= 1) {
        if (threadIdx.x < o) red[threadIdx.x] += red[threadIdx.x + o];
        __syncthreads();
    }
    if (threadIdx.x == 0) {
        float m = red[0] / (65536.f * 64.f);
        out_losses[0] = m;
        out_losses[1] = m;
    }
}

// ---------------- post 1x1: 64->256, f32x2 ----------------
__global__ void post_kernel(const float* __restrict__ in, const float* __restrict__ w,
                            const float* __restrict__ bias, float* __restrict__ out)
{
    __shared__ float w_t[64*64];
    int n = blockIdx.z, coB = blockIdx.y;
    int s = blockIdx.x * 256 + threadIdx.x;
    for (int i = threadIdx.x; i < 64*64; i += 256) {
        int ci = i >> 6, co = i & 63;
        w_t[i] = w[(size_t)(coB*64 + co)*64 + ci];
    }
    __syncthreads();
    u64 acc[32];
#pragma unroll
    for (int k = 0; k < 32; k++) acc[k] = 0ull;
    const float* ip = in + (size_t)n*64*1024 + s;
#pragma unroll 2
    for (int ci = 0; ci < 64; ci++) {
        float v = ip[(size_t)ci*1024];
        u64 pv = pack2(v, v);
        const ulonglong2* wp = reinterpret_cast<const ulonglong2*>(w_t + ci*64);
#pragma unroll
        for (int k = 0; k < 16; k++) {
            ulonglong2 ww = wp[k];
            acc[2*k]   = fma2(ww.x, pv, acc[2*k]);
            acc[2*k+1] = fma2(ww.y, pv, acc[2*k+1]);
        }
    }
    float* op = out + (size_t)n*256*1024 + (size_t)coB*64*1024 + s;
#pragma unroll
    for (int k = 0; k < 32; k++) {
        float2 v = unpack2(acc[k]);
        op[(size_t)(2*k  )*1024] = v.x + bias[coB*64 + 2*k];
        op[(size_t)(2*k+1)*1024] = v.y + bias[coB*64 + 2*k+1];
    }
}

// ---------------- dec2 transpose conv 128->3, fused BN+ReLU in, tanh out ----------------
__global__ void dec2_kernel(const float* __restrict__ in, const float* __restrict__ w,
                            const float* __restrict__ bias, const float* __restrict__ scale,
                            const float* __restrict__ shift, float* __restrict__ out)
{
    extern __shared__ float sm[];
    float* w_s  = sm;
    float* in_s = sm + 3456;
    float* sc_s = sm + 17280;
    float* sh_s = sm + 17408;
    int n = blockIdx.y; int tile = blockIdx.x;
    int OH0 = (tile >> 3) * 16, OW0 = (tile & 7) * 16;
    int IH0 = OH0 >> 1, IW0 = OW0 >> 1;
    int tid = threadIdx.x;
    for (int i = tid; i < 3456; i += 256) w_s[i] = w[i];
    for (int i = tid; i < 128; i += 256) { sc_s[i] = scale[i]; sh_s[i] = shift[i]; }
    __syncthreads();
    for (int i = tid; i < 128*108; i += 256) {
        int ci = i / 108; int rem = i - ci*108; int rr = rem / 12; int cc = rem - rr*12;
        int ih = IH0 + rr, iw = IW0 + cc;
        float v = 0.f;
        if (cc < 9 && ih < 64 && iw < 64) {
            float raw = in[((size_t)(n*128 + ci)*64 + ih)*64 + iw];
            v = fmaxf(fmaf(raw, sc_s[ci], sh_s[ci]), 0.f);
        }
        in_s[i] = v;
    }
    __syncthreads();

    int cls = tid >> 6; int pe_h = cls >> 1, pe_w = cls & 1;
    int t3 = tid & 63; int r8 = t3 >> 3, c8 = t3 & 7;
    float acc[3] = {0.f, 0.f, 0.f};
    for (int ci = 0; ci < 128; ci++) {
        const float* base = &in_s[ci*108];
        float v00 = base[r8*12 + c8];
        float v01 = base[r8*12 + c8 + 1];
        float v10 = base[(r8+1)*12 + c8];
        float v11 = base[(r8+1)*12 + c8 + 1];
        const float* wp = &w_s[ci*27];
        if (pe_h == 0) {
            if (pe_w == 0) {
#pragma unroll
                for (int co = 0; co < 3; co++) acc[co] += wp[co*9 + 4] * v00;
            } else {
#pragma unroll
                for (int co = 0; co < 3; co++) acc[co] += wp[co*9 + 3] * v01 + wp[co*9 + 5] * v00;
            }
        } else {
            if (pe_w == 0) {
#pragma unroll
                for (int co = 0; co < 3; co++) acc[co] += wp[co*9 + 1] * v10 + wp[co*9 + 7] * v00;
            } else {
#pragma unroll
                for (int co = 0; co < 3; co++)
                    acc[co] += wp[co*9 + 0]*v11 + wp[co*9 + 2]*v10 + wp[co*9 + 6]*v01 + wp[co*9 + 8]*v00;
            }
        }
    }
    int oh = OH0 + r8*2 + pe_h, ow = OW0 + c8*2 + pe_w;
#pragma unroll
    for (int co = 0; co < 3; co++)
        out[((size_t)(n*3 + co)*128 + oh)*128 + ow] = tanhf(acc[co] + bias[co]);
}

// ---------------- host launch ----------------
static float* sym_addr(const void* sym)
{
    void* p = nullptr;
    cudaGetSymbolAddress(&p, sym);
    return (float*)p;
}

extern "C" void kernel_launch(void* const* d_in, const int* in_sizes, int n_in,
                              void* d_out, int out_size)
{
    const float* x       = (const float*)d_in[0];
    const float* enc1_w  = (const float*)d_in[1];
    const float* enc1_b  = (const float*)d_in[2];
    const float* bn1_g   = (const float*)d_in[3];
    const float* bn1_b   = (const float*)d_in[4];
    const float* enc2_w  = (const float*)d_in[5];
    const float* enc2_b  = (const float*)d_in[6];
    const float* pre_w   = (const float*)d_in[7];
    const float* pre_b   = (const float*)d_in[8];
    const float* codebook= (const float*)d_in[9];
    const float* post_w  = (const float*)d_in[10];
    const float* post_b  = (const float*)d_in[11];
    const float* dec1_w  = (const float*)d_in[12];
    const float* dec1_b  = (const float*)d_in[13];
    const float* dbn1_g  = (const float*)d_in[14];
    const float* dbn1_b  = (const float*)d_in[15];
    const float* dec2_w  = (const float*)d_in[16];
    const float* dec2_b  = (const float*)d_in[17];

    float* out = (float*)d_out;
    float* out_losses = out + RECON_ELEMS;
    float* out_idx    = out + RECON_ELEMS + 2;

    float* h1  = sym_addr(g_h1);
    __nv_bfloat16* h1hi; { void* p; cudaGetSymbolAddress(&p, g_h1hi); h1hi = (__nv_bfloat16*)p; }
    __nv_bfloat16* h1lo; { void* p; cudaGetSymbolAddress(&p, g_h1lo); h1lo = (__nv_bfloat16*)p; }
    __nv_bfloat16* w2chi; { void* p; cudaGetSymbolAddress(&p, g_w2chi); w2chi = (__nv_bfloat16*)p; }
    __nv_bfloat16* w2clo; { void* p; cudaGetSymbolAddress(&p, g_w2clo); w2clo = (__nv_bfloat16*)p; }
    __nv_bfloat16* wd1hi; { void* p; cudaGetSymbolAddress(&p, g_wd1hi); wd1hi = (__nv_bfloat16*)p; }
    __nv_bfloat16* wd1lo; { void* p; cudaGetSymbolAddress(&p, g_wd1lo); wd1lo = (__nv_bfloat16*)p; }
    __nv_bfloat16* dhi; { void* p; cudaGetSymbolAddress(&p, g_dhi); dhi = (__nv_bfloat16*)p; }
    __nv_bfloat16* dlo; { void* p; cudaGetSymbolAddress(&p, g_dlo); dlo = (__nv_bfloat16*)p; }
    float* h2  = sym_addr(g_h2);
    float* z   = sym_addr(g_z);
    float* q   = sym_addr(g_q);
    float* d   = sym_addr(g_d);
    float* d1  = sym_addr(g_d1);
    float* psum = sym_addr(g_psum);
    float* psq  = sym_addr(g_psq);
    float* sc   = sym_addr(g_scale);
    float* sh   = sym_addr(g_shift);
    float* lp   = sym_addr(g_losspart);

    const unsigned MM_SMEM = 2*MM_STAGE + 1024;   // 132096
    cudaFuncSetAttribute(conv2_mma_kernel, cudaFuncAttributeMaxDynamicSharedMemorySize, MM_SMEM);
    cudaFuncSetAttribute(dec1_mma_kernel,  cudaFuncAttributeMaxDynamicSharedMemorySize, MM_SMEM);
    cudaFuncSetAttribute(vq_kernel,   cudaFuncAttributeMaxDynamicSharedMemorySize, 133120);
    cudaFuncSetAttribute(dec2_kernel, cudaFuncAttributeMaxDynamicSharedMemorySize, 70144);

    const float inv_cnt = 1.f / 262144.f;

    // weight prep
    wtrans_conv2_bf16<<<1152, 256>>>(enc2_w, w2chi, w2clo);
    wtrans_dec1_bf16<<<1152, 256>>>(dec1_w, wd1hi, wd1lo);

    // encoder
    conv1_kernel<<<dim3(4,4,64), 256>>>(x, enc1_w, enc1_b, h1);       // NHWC fp32
    bn_stats_nhwc<<<256, 256>>>(h1, psum, psq, 256);
    bn_finalize_kernel<<<1,128>>>(psum, psq, bn1_g, bn1_b, sc, sh, 256, inv_cnt);
    bnrelu_split_kernel<<<32768, 256>>>(h1, h1hi, h1lo, sc, sh);
    conv2_mma_kernel<<<dim3(8,2,64), 256, MM_SMEM>>>(h1hi, h1lo, w2chi, w2clo, enc2_b, h2);
    pre_kernel<<<dim3(4,2,64), 256>>>(h2, pre_w, pre_b, z);

    // VQ
    vq_kernel<<<256, 256, 133120>>>(z, codebook, q, out_idx, lp);
    loss_finalize_kernel<<<1,256>>>(lp, out_losses);

    // decoder
    post_kernel<<<dim3(4,4,64), 256>>>(q, post_w, post_b, d);
    split_d_nhwc<<<dim3(8,16,64), 256>>>(d, dhi, dlo);
    dec1_mma_kernel<<<dim3(8,4,64), 256, MM_SMEM>>>(dhi, dlo, wd1hi, wd1lo, dec1_b, d1);
    bn_stats_kernel<<<dim3(128,32), 256>>>(d1, psum, psq, 128, 32);
    bn_finalize_kernel<<<1,128>>>(psum, psq, dbn1_g, dbn1_b, sc, sh, 32, inv_cnt);
    dec2_kernel<<<dim3(64,64), 256, 70144>>>(d1, dec2_w, dec2_b, sc, sh, out);

    (void)in_sizes; (void)n_in; (void)out_size;
}

// round 10
// speedup vs baseline: 2.6124x; 1.0291x over previous
#include <cuda_runtime.h>
#include <cuda_bf16.h>
#include <cstdint>

#define H1_ELEMS (64*128*64*64)
#define H2_ELEMS (64*256*32*32)
#define Z_ELEMS  (64*64*32*32)
#define D_ELEMS  (64*256*32*32)
#define D1_ELEMS (64*128*64*64)
#define RECON_ELEMS (64*3*128*128)
#define VQ_DIM 64
#define NCODE 512

__device__ float g_h1[H1_ELEMS];                 // NHWC fp32
__device__ __nv_bfloat16 g_h1hi[H1_ELEMS];       // NHWC bf16 hi
__device__ __nv_bfloat16 g_h1lo[H1_ELEMS];       // NHWC bf16 lo
__device__ float g_h2[H2_ELEMS];
__device__ float g_z[Z_ELEMS];
__device__ __nv_bfloat16 g_dhi[D_ELEMS];         // NHWC bf16 hi
__device__ __nv_bfloat16 g_dlo[D_ELEMS];         // NHWC bf16 lo
__device__ float g_d1[D1_ELEMS];
__device__ __nv_bfloat16 g_w2chi[256*1152];      // [co][t][ci] bf16 hi
__device__ __nv_bfloat16 g_w2clo[256*1152];
__device__ __nv_bfloat16 g_wd1hi[128*2304];      // [co][clsk] bf16 hi
__device__ __nv_bfloat16 g_wd1lo[128*2304];
__device__ __nv_bfloat16 g_tabhi[NCODE*256];     // [k][co] bf16 hi of post_w@cb + post_b
__device__ __nv_bfloat16 g_tablo[NCODE*256];
__device__ float g_psum[128*1024];
__device__ float g_psq[128*1024];
__device__ float g_scale[128];
__device__ float g_shift[128];
__device__ float g_losspart[256];

typedef unsigned long long u64;
__device__ __forceinline__ u64 pack2(float a, float b) {
    u64 r; asm("mov.b64 %0, {%1,%2};" : "=l"(r) : "f"(a), "f"(b)); return r;
}
__device__ __forceinline__ u64 fma2(u64 a, u64 b, u64 c) {
    u64 d; asm("fma.rn.f32x2 %0, %1, %2, %3;" : "=l"(d) : "l"(a), "l"(b), "l"(c)); return d;
}
__device__ __forceinline__ u64 add2(u64 a, u64 b) {
    u64 d; asm("add.rn.f32x2 %0, %1, %2;" : "=l"(d) : "l"(a), "l"(b)); return d;
}
__device__ __forceinline__ float2 unpack2(u64 a) {
    float lo, hi; asm("mov.b64 {%0,%1}, %2;" : "=f"(lo), "=f"(hi) : "l"(a));
    return make_float2(lo, hi);
}
__device__ __forceinline__ void cp16(uint32_t saddr, const void* gaddr) {
    asm volatile("cp.async.cg.shared.global [%0], [%1], 16;" :: "r"(saddr), "l"(gaddr));
}
__device__ __forceinline__ void cp16z(uint32_t saddr, const void* gaddr, bool ok) {
    int sz = ok ? 16 : 0;
    asm volatile("cp.async.cg.shared.global [%0], [%1], 16, %2;" :: "r"(saddr), "l"(gaddr), "r"(sz));
}
#define CP_COMMIT() asm volatile("cp.async.commit_group;")
#define CP_WAIT(n)  asm volatile("cp.async.wait_group %0;" :: "n"(n))

#define SWZ(o) ((o) ^ ((((uint32_t)(o)) >> 3) & 0x70))

__device__ __forceinline__ void ldsm4(uint32_t* r, uint32_t addr) {
    asm volatile("ldmatrix.sync.aligned.m8n8.x4.shared.b16 {%0,%1,%2,%3}, [%4];"
                 : "=r"(r[0]), "=r"(r[1]), "=r"(r[2]), "=r"(r[3]) : "r"(addr));
}
__device__ __forceinline__ void mma16816(float* c, const uint32_t* a, const uint32_t* b) {
    asm volatile(
        "mma.sync.aligned.m16n8k16.row.col.f32.bf16.bf16.f32 "
        "{%0,%1,%2,%3}, {%4,%5,%6,%7}, {%8,%9}, {%0,%1,%2,%3};"
        : "+f"(c[0]), "+f"(c[1]), "+f"(c[2]), "+f"(c[3])
        : "r"(a[0]), "r"(a[1]), "r"(a[2]), "r"(a[3]), "r"(b[0]), "r"(b[1]));
}

// ---------------- weight prep ----------------
__global__ void wtrans_conv2_bf16(const float* __restrict__ w,
                                  __nv_bfloat16* __restrict__ whi, __nv_bfloat16* __restrict__ wlo)
{
    int i = blockIdx.x * 256 + threadIdx.x;
    if (i >= 256*1152) return;
    int co = i / 1152; int rem = i - co*1152; int t = rem >> 7; int ci = rem & 127;
    float v = w[((size_t)co*128 + ci)*9 + t];
    __nv_bfloat16 h = __float2bfloat16(v);
    whi[i] = h;
    wlo[i] = __float2bfloat16(v - __bfloat162float(h));
}

__global__ void wtrans_dec1_bf16(const float* __restrict__ w,
                                 __nv_bfloat16* __restrict__ whi, __nv_bfloat16* __restrict__ wlo)
{
    int i = blockIdx.x * 256 + threadIdx.x;
    if (i >= 128*2304) return;
    int co = i / 2304; int k = i - co*2304;
    int kh, kw, ci;
    if (k < 256)       { kh = 1; kw = 1; ci = k; }
    else if (k < 768)  { int t = (k-256) >> 8; ci = (k-256) & 255; kh = 1; kw = t ? 2 : 0; }
    else if (k < 1280) { int t = (k-768) >> 8; ci = (k-768) & 255; kh = t ? 2 : 0; kw = 1; }
    else               { int t = (k-1280) >> 8; ci = (k-1280) & 255;
                         kh = (t < 2) ? 0 : 2; kw = (t & 1) ? 2 : 0; }
    float v = w[((size_t)ci*128 + co)*9 + kh*3 + kw];
    __nv_bfloat16 h = __float2bfloat16(v);
    whi[i] = h;
    wlo[i] = __float2bfloat16(v - __bfloat162float(h));
}

// table[k][co] = sum_ci post_w[co][ci]*cb[k][ci] + post_b[co], bf16 split
__global__ void table_kernel(const float* __restrict__ pw, const float* __restrict__ pb,
                             const float* __restrict__ cb,
                             __nv_bfloat16* __restrict__ thi, __nv_bfloat16* __restrict__ tlo)
{
    __shared__ float c_s[64];
    int k = blockIdx.x, co = threadIdx.x;
    if (co < 64) c_s[co] = cb[k*64 + co];
    __syncthreads();
    float acc = pb[co];
#pragma unroll 8
    for (int ci = 0; ci < 64; ci++) acc += pw[co*64 + ci] * c_s[ci];
    __nv_bfloat16 h = __float2bfloat16(acc);
    thi[k*256 + co] = h;
    tlo[k*256 + co] = __float2bfloat16(acc - __bfloat162float(h));
}

// ---------------- conv1: 3->128, s2, NHWC output ----------------
__global__ void conv1_kernel(const float* __restrict__ x, const float* __restrict__ w,
                             const float* __restrict__ bias, float* __restrict__ out)
{
    __shared__ float w_s[128*28];
    __shared__ float in_s[3*33*33];
    int n = blockIdx.z;
    int OH0 = blockIdx.y * 16, OW0 = blockIdx.x * 16;
    int tid = threadIdx.x;
    for (int i = tid; i < 128*27; i += 256) { int co = i / 27, t = i - co*27; w_s[co*28 + t] = w[i]; }
    for (int co = tid; co < 128; co += 256) w_s[co*28 + 27] = 0.f;
    int IH0 = OH0*2 - 1, IW0 = OW0*2 - 1;
    for (int i = tid; i < 3*33*33; i += 256) {
        int ci = i / 1089; int r = (i % 1089) / 33; int c = i % 33;
        int ih = IH0 + r, iw = IW0 + c;
        float v = 0.f;
        if (ih >= 0 && ih < 128 && iw >= 0 && iw < 128) v = x[((n*3 + ci)*128 + ih)*128 + iw];
        in_s[i] = v;
    }
    __syncthreads();
    int ty = tid >> 4, tx = tid & 15;
    float in_r[28];
#pragma unroll
    for (int ci = 0; ci < 3; ci++)
#pragma unroll
        for (int kh = 0; kh < 3; kh++)
#pragma unroll
            for (int kw = 0; kw < 3; kw++)
                in_r[ci*9 + kh*3 + kw] = in_s[ci*1089 + (ty*2+kh)*33 + (tx*2+kw)];
    in_r[27] = 0.f;
    int oh = OH0 + ty, ow = OW0 + tx;
    float* outp = out + (((size_t)n*64 + oh)*64 + ow)*128;
    const float4* w4p = reinterpret_cast<const float4*>(w_s);
    for (int cg = 0; cg < 32; cg++) {
        float4 res;
        float* rp = &res.x;
#pragma unroll
        for (int j = 0; j < 4; j++) {
            int co = cg*4 + j;
            float acc = bias[co];
#pragma unroll
            for (int u = 0; u < 7; u++) {
                float4 w4 = w4p[co*7 + u];
                acc += w4.x*in_r[u*4] + w4.y*in_r[u*4+1] + w4.z*in_r[u*4+2] + w4.w*in_r[u*4+3];
            }
            rp[j] = acc;
        }
        reinterpret_cast<float4*>(outp)[cg] = res;
    }
}

// ---------------- BN stats NHWC (for h1) ----------------
__global__ void bn_stats_nhwc(const float* __restrict__ x, float* __restrict__ psum,
                              float* __restrict__ psq, int nblk)
{
    int blk = blockIdx.x;
    int cg = threadIdx.x & 31;
    int rg = threadIdx.x >> 5;
    float4 s = make_float4(0,0,0,0), sq = make_float4(0,0,0,0);
    for (int r = blk*8 + rg; r < 262144; r += nblk*8) {
        float4 v = *reinterpret_cast<const float4*>(x + (size_t)r*128 + cg*4);
        s.x += v.x; s.y += v.y; s.z += v.z; s.w += v.w;
        sq.x += v.x*v.x; sq.y += v.y*v.y; sq.z += v.z*v.z; sq.w += v.w*v.w;
    }
    __shared__ float ss[256*4], qs[256*4];
    reinterpret_cast<float4*>(ss)[threadIdx.x] = s;
    reinterpret_cast<float4*>(qs)[threadIdx.x] = sq;
    __syncthreads();
    if (threadIdx.x < 128) {
        int c = threadIdx.x;
        int cgi = c >> 2, j = c & 3;
        float a = 0.f, b = 0.f;
        for (int g = 0; g < 8; g++) { a += ss[(g*32+cgi)*4 + j]; b += qs[(g*32+cgi)*4 + j]; }
        psum[c*nblk + blk] = a;
        psq[c*nblk + blk] = b;
    }
}

// ---------------- BN stats NCHW (for d1) ----------------
__global__ void bn_stats_kernel(const float* __restrict__ x, float* __restrict__ psum,
                                float* __restrict__ psq, int C, int nblk)
{
    int c = blockIdx.x, blk = blockIdx.y;
    float s = 0.f, sq = 0.f;
    int total4 = 64 * 1024;
    for (int i = blk*256 + threadIdx.x; i < total4; i += nblk*256) {
        int n = i >> 10, off = i & 1023;
        const float4* p = reinterpret_cast<const float4*>(x + ((size_t)(n*C + c))*4096);
        float4 v = p[off];
        s  += v.x + v.y + v.z + v.w;
        sq += v.x*v.x + v.y*v.y + v.z*v.z + v.w*v.w;
    }
    __shared__ float rs[256], rq[256];
    rs[threadIdx.x] = s; rq[threadIdx.x] = sq;
    __syncthreads();
    for (int o = 128; o > 0; o >>= 1) {
        if (threadIdx.x < o) { rs[threadIdx.x] += rs[threadIdx.x+o]; rq[threadIdx.x] += rq[threadIdx.x+o]; }
        __syncthreads();
    }
    if (threadIdx.x == 0) { psum[c*nblk + blk] = rs[0]; psq[c*nblk + blk] = rq[0]; }
}

__global__ void bn_finalize_kernel(const float* __restrict__ psum, const float* __restrict__ psq,
                                   const float* __restrict__ g, const float* __restrict__ b,
                                   float* __restrict__ scale, float* __restrict__ shift,
                                   int nblk, float inv_count)
{
    int c = threadIdx.x;
    float s = 0.f, sq = 0.f;
    for (int i = 0; i < nblk; i++) { s += psum[c*nblk + i]; sq += psq[c*nblk + i]; }
    float mean = s * inv_count;
    float var = sq * inv_count - mean*mean;
    float r = rsqrtf(var + 1e-5f);
    float sc = g[c] * r;
    scale[c] = sc;
    shift[c] = b[c] - mean * sc;
}

// ---------------- BN+ReLU + bf16 split (NHWC fp32 -> NHWC bf16 hi/lo) ----------------
__global__ void bnrelu_split_kernel(const float* __restrict__ x,
                                    __nv_bfloat16* __restrict__ hi, __nv_bfloat16* __restrict__ lo,
                                    const float* __restrict__ sc, const float* __restrict__ sh)
{
    long i = (long)blockIdx.x * 256 + threadIdx.x;   // float4 index
    if (i >= 8388608L) return;
    int c = (int)(i & 31) * 4;
    float4 v = reinterpret_cast<const float4*>(x)[i];
    float r0 = fmaxf(fmaf(v.x, sc[c+0], sh[c+0]), 0.f);
    float r1 = fmaxf(fmaf(v.y, sc[c+1], sh[c+1]), 0.f);
    float r2 = fmaxf(fmaf(v.z, sc[c+2], sh[c+2]), 0.f);
    float r3 = fmaxf(fmaf(v.w, sc[c+3], sh[c+3]), 0.f);
    __nv_bfloat16 h0 = __float2bfloat16(r0), h1 = __float2bfloat16(r1);
    __nv_bfloat16 h2 = __float2bfloat16(r2), h3 = __float2bfloat16(r3);
    __nv_bfloat16 l0 = __float2bfloat16(r0 - __bfloat162float(h0));
    __nv_bfloat16 l1 = __float2bfloat16(r1 - __bfloat162float(h1));
    __nv_bfloat16 l2 = __float2bfloat16(r2 - __bfloat162float(h2));
    __nv_bfloat16 l3 = __float2bfloat16(r3 - __bfloat162float(h3));
    __nv_bfloat162* hp = reinterpret_cast<__nv_bfloat162*>(hi);
    __nv_bfloat162* lp = reinterpret_cast<__nv_bfloat162*>(lo);
    hp[2*i]   = __nv_bfloat162(h0, h1);
    hp[2*i+1] = __nv_bfloat162(h2, h3);
    lp[2*i]   = __nv_bfloat162(l0, l1);
    lp[2*i+1] = __nv_bfloat162(l2, l3);
}

// ---------------- gather: dhi/dlo[pos][256] = table[idx[pos]] ----------------
__global__ void gather_d(const float* __restrict__ idx_f,
                         const uint4* __restrict__ thi, const uint4* __restrict__ tlo,
                         uint4* __restrict__ dhi, uint4* __restrict__ dlo)
{
    int tid = threadIdx.x;
    int pos = blockIdx.x*32 + (tid >> 3);
    int c = tid & 7;
    int k = (int)idx_f[pos];
#pragma unroll
    for (int j = 0; j < 4; j++) {
        dhi[(size_t)pos*32 + c + j*8] = thi[k*32 + c + j*8];
        dlo[(size_t)pos*32 + c + j*8] = tlo[k*32 + c + j*8];
    }
}

// ---------------- conv2 via mma.sync bf16 split ----------------
#define MM_SPLIT 16384u
#define MM_STAGE (4u*MM_SPLIT)
__global__ void __launch_bounds__(256, 1) conv2_mma_kernel(
        const __nv_bfloat16* __restrict__ inhi, const __nv_bfloat16* __restrict__ inlo,
        const __nv_bfloat16* __restrict__ whi, const __nv_bfloat16* __restrict__ wlo,
        const float* __restrict__ bias, float* __restrict__ out)
{
    extern __shared__ char dsm[];
    __shared__ float bias_s[128];
    int mt = blockIdx.x, Nt = blockIdx.y, n = blockIdx.z;
    int OH0 = mt * 4;
    int tid = threadIdx.x, wid = tid >> 5, lane = tid & 31;
    int mrow = (wid >> 1) * 32;
    int ncol = (wid & 1) * 64;

    uint32_t base0 = ((uint32_t)__cvta_generic_to_shared(dsm) + 1023u) & ~1023u;
    for (int i = tid; i < 128; i += 256) bias_s[i] = bias[Nt*128 + i];

    auto fill = [&](int kc, int buf) {
        int t = kc >> 1, ci0 = (kc & 1) << 6;
        int kh = t / 3, kw = t - (t/3)*3;
        uint32_t Ah = base0 + buf*MM_STAGE;
        uint32_t Al = Ah + MM_SPLIT;
        uint32_t Bh = Al + MM_SPLIT;
        uint32_t Bl = Bh + MM_SPLIT;
        for (int i = tid; i < 1024; i += 256) {
            int px = i >> 3, c16 = i & 7;
            int oh = OH0 + (px >> 5), ow = px & 31;
            int ih = 2*oh - 1 + kh, iw = 2*ow - 1 + kw;
            bool ok = (ih >= 0) && (ih < 64) && (iw >= 0) && (iw < 64);
            long off = ((long)(n*64 + (ok ? ih : 0))*64 + (ok ? iw : 0))*128 + ci0 + c16*8;
            uint32_t d = SWZ(px*128 + c16*16);
            cp16z(Ah + d, inhi + off, ok);
            cp16z(Al + d, inlo + off, ok);
        }
        for (int i = tid; i < 1024; i += 256) {
            int co = i >> 3, c16 = i & 7;
            long off = (long)(Nt*128 + co)*1152 + t*128 + ci0 + c16*8;
            uint32_t d = SWZ(co*128 + c16*16);
            cp16(Bh + d, whi + off);
            cp16(Bl + d, wlo + off);
        }
    };

    float acc[2][8][4];
#pragma unroll
    for (int a = 0; a < 2; a++)
#pragma unroll
        for (int b = 0; b < 8; b++)
#pragma unroll
            for (int c = 0; c < 4; c++) acc[a][b][c] = 0.f;

    fill(0, 0); CP_COMMIT();
    for (int s = 0; s < 18; s++) {
        if (s < 17) { fill(s+1, (s+1)&1); CP_COMMIT(); CP_WAIT(1); }
        else        { CP_WAIT(0); }
        __syncthreads();
        uint32_t Ah = base0 + (s&1)*MM_STAGE;
        uint32_t Al = Ah + MM_SPLIT;
        uint32_t Bh = Al + MM_SPLIT;
        uint32_t Bl = Bh + MM_SPLIT;
#pragma unroll
        for (int ks = 0; ks < 4; ks++) {
            uint32_t ah[2][4], al[2][4], bh[4][4], bl[4][4];
#pragma unroll
            for (int mi = 0; mi < 2; mi++) {
                int row = mrow + mi*16 + (lane & 15);
                uint32_t ao = SWZ(row*128 + ks*32 + (lane >> 4)*16);
                ldsm4(ah[mi], Ah + ao);
                ldsm4(al[mi], Al + ao);
            }
#pragma unroll
            for (int nb = 0; nb < 4; nb++) {
                int g = lane >> 3, r = lane & 7;
                int co_l = ncol + nb*16 + ((g >> 1) << 3) + r;
                uint32_t bo = SWZ(co_l*128 + ks*32 + (g & 1)*16);
                ldsm4(bh[nb], Bh + bo);
                ldsm4(bl[nb], Bl + bo);
            }
#pragma unroll
            for (int mi = 0; mi < 2; mi++)
#pragma unroll
                for (int nt = 0; nt < 8; nt++) {
                    const uint32_t* pbh = &bh[nt >> 1][(nt & 1)*2];
                    const uint32_t* pbl = &bl[nt >> 1][(nt & 1)*2];
                    mma16816(acc[mi][nt], ah[mi], pbh);
                    mma16816(acc[mi][nt], ah[mi], pbl);
                    mma16816(acc[mi][nt], al[mi], pbh);
                }
        }
        __syncthreads();
    }

    float* osm = reinterpret_cast<float*>(dsm);
#pragma unroll
    for (int mi = 0; mi < 2; mi++)
#pragma unroll
        for (int nt = 0; nt < 8; nt++) {
            int px0 = mrow + mi*16 + (lane >> 2);
            int col = ncol + nt*8 + (lane & 3)*2;
            osm[col*132 + px0]         = acc[mi][nt][0];
            osm[(col+1)*132 + px0]     = acc[mi][nt][1];
            osm[col*132 + px0 + 8]     = acc[mi][nt][2];
            osm[(col+1)*132 + px0 + 8] = acc[mi][nt][3];
        }
    __syncthreads();
    for (int i = tid; i < 128*32; i += 256) {
        int co = i >> 5, p4 = (i & 31)*4;
        float4 v = *reinterpret_cast<const float4*>(osm + co*132 + p4);
        float b = bias_s[co];
        v.x += b; v.y += b; v.z += b; v.w += b;
        int cog = Nt*128 + co;
        *reinterpret_cast<float4*>(out + ((size_t)(n*256 + cog))*1024 + OH0*32 + p4) = v;
    }
}

// ---------------- dec1 via mma.sync bf16 split (parity-class implicit GEMM) ----------------
__global__ void __launch_bounds__(256, 1) dec1_mma_kernel(
        const __nv_bfloat16* __restrict__ inhi, const __nv_bfloat16* __restrict__ inlo,
        const __nv_bfloat16* __restrict__ whi, const __nv_bfloat16* __restrict__ wlo,
        const float* __restrict__ bias, float* __restrict__ out)
{
    extern __shared__ char dsm[];
    __shared__ float bias_s[128];
    const int NKC[4]  = {4, 8, 8, 16};
    const int KOFS[4] = {0, 256, 768, 1280};
    const int DYT[4][4] = {{0,0,0,0},{0,0,0,0},{1,0,0,0},{1,1,0,0}};
    const int DXT[4][4] = {{0,0,0,0},{1,0,0,0},{0,0,0,0},{1,0,1,0}};

    int mt = blockIdx.x, cls = blockIdx.y, n = blockIdx.z;
    int ph = cls >> 1, pw = cls & 1;
    int Y0 = mt * 4;
    int tid = threadIdx.x, wid = tid >> 5, lane = tid & 31;
    int mrow = (wid >> 1) * 32;
    int ncol = (wid & 1) * 64;

    uint32_t base0 = ((uint32_t)__cvta_generic_to_shared(dsm) + 1023u) & ~1023u;
    for (int i = tid; i < 128; i += 256) bias_s[i] = bias[i];

    int kbase = KOFS[cls];
    int nk = NKC[cls];

    auto fill = [&](int kc, int buf) {
        int t = kc >> 2, ci0 = (kc & 3) << 6;
        int dy = DYT[cls][t], dx = DXT[cls][t];
        uint32_t Ah = base0 + buf*MM_STAGE;
        uint32_t Al = Ah + MM_SPLIT;
        uint32_t Bh = Al + MM_SPLIT;
        uint32_t Bl = Bh + MM_SPLIT;
        for (int i = tid; i < 1024; i += 256) {
            int px = i >> 3, c16 = i & 7;
            int y = Y0 + (px >> 5), x = px & 31;
            int iy = y + dy, ix = x + dx;
            bool ok = (iy < 32) && (ix < 32);
            long off = ((long)(n*32 + (ok ? iy : 0))*32 + (ok ? ix : 0))*256 + ci0 + c16*8;
            uint32_t d = SWZ(px*128 + c16*16);
            cp16z(Ah + d, inhi + off, ok);
            cp16z(Al + d, inlo + off, ok);
        }
        for (int i = tid; i < 1024; i += 256) {
            int co = i >> 3, c16 = i & 7;
            long off = (long)co*2304 + kbase + t*256 + ci0 + c16*8;
            uint32_t d = SWZ(co*128 + c16*16);
            cp16(Bh + d, whi + off);
            cp16(Bl + d, wlo + off);
        }
    };

    float acc[2][8][4];
#pragma unroll
    for (int a = 0; a < 2; a++)
#pragma unroll
        for (int b = 0; b < 8; b++)
#pragma unroll
            for (int c = 0; c < 4; c++) acc[a][b][c] = 0.f;

    fill(0, 0); CP_COMMIT();
    for (int s = 0; s < nk; s++) {
        if (s < nk-1) { fill(s+1, (s+1)&1); CP_COMMIT(); CP_WAIT(1); }
        else          { CP_WAIT(0); }
        __syncthreads();
        uint32_t Ah = base0 + (s&1)*MM_STAGE;
        uint32_t Al = Ah + MM_SPLIT;
        uint32_t Bh = Al + MM_SPLIT;
        uint32_t Bl = Bh + MM_SPLIT;
#pragma unroll
        for (int ks = 0; ks < 4; ks++) {
            uint32_t ah[2][4], al[2][4], bh[4][4], bl[4][4];
#pragma unroll
            for (int mi = 0; mi < 2; mi++) {
                int row = mrow + mi*16 + (lane & 15);
                uint32_t ao = SWZ(row*128 + ks*32 + (lane >> 4)*16);
                ldsm4(ah[mi], Ah + ao);
                ldsm4(al[mi], Al + ao);
            }
#pragma unroll
            for (int nb = 0; nb < 4; nb++) {
                int g = lane >> 3, r = lane & 7;
                int co_l = ncol + nb*16 + ((g >> 1) << 3) + r;
                uint32_t bo = SWZ(co_l*128 + ks*32 + (g & 1)*16);
                ldsm4(bh[nb], Bh + bo);
                ldsm4(bl[nb], Bl + bo);
            }
#pragma unroll
            for (int mi = 0; mi < 2; mi++)
#pragma unroll
                for (int nt = 0; nt < 8; nt++) {
                    const uint32_t* pbh = &bh[nt >> 1][(nt & 1)*2];
                    const uint32_t* pbl = &bl[nt >> 1][(nt & 1)*2];
                    mma16816(acc[mi][nt], ah[mi], pbh);
                    mma16816(acc[mi][nt], ah[mi], pbl);
                    mma16816(acc[mi][nt], al[mi], pbh);
                }
        }
        __syncthreads();
    }

    float* osm = reinterpret_cast<float*>(dsm);
#pragma unroll
    for (int mi = 0; mi < 2; mi++)
#pragma unroll
        for (int nt = 0; nt < 8; nt++) {
            int px0 = mrow + mi*16 + (lane >> 2);
            int col = ncol + nt*8 + (lane & 3)*2;
            osm[col*132 + px0]         = acc[mi][nt][0];
            osm[(col+1)*132 + px0]     = acc[mi][nt][1];
            osm[col*132 + px0 + 8]     = acc[mi][nt][2];
            osm[(col+1)*132 + px0 + 8] = acc[mi][nt][3];
        }
    __syncthreads();
    for (int i = tid; i < 128*128; i += 256) {
        int co = i >> 7, p = i & 127;
        int y = Y0 + (p >> 5), x = p & 31;
        int oh = 2*y + ph, ow = 2*x + pw;
        out[((size_t)(n*128 + co)*64 + oh)*64 + ow] = osm[co*132 + p] + bias_s[co];
    }
}

// ---------------- pre 1x1: 256->64, f32x2 ----------------
__global__ void pre_kernel(const float* __restrict__ in, const float* __restrict__ w,
                           const float* __restrict__ bias, float* __restrict__ out)
{
    __shared__ float w_t[256*32];
    int n = blockIdx.z, coH = blockIdx.y;
    int s = blockIdx.x * 256 + threadIdx.x;
    for (int i = threadIdx.x; i < 256*32; i += 256) {
        int ci = i >> 5, co = i & 31;
        w_t[i] = w[(size_t)(coH*32 + co)*256 + ci];
    }
    __syncthreads();
    u64 acc[16];
#pragma unroll
    for (int k = 0; k < 16; k++) acc[k] = 0ull;
    const float* ip = in + (size_t)n*256*1024 + s;
#pragma unroll 4
    for (int ci = 0; ci < 256; ci++) {
        float v = ip[(size_t)ci*1024];
        u64 pv = pack2(v, v);
        const ulonglong2* wp = reinterpret_cast<const ulonglong2*>(w_t + ci*32);
#pragma unroll
        for (int k = 0; k < 8; k++) {
            ulonglong2 ww = wp[k];
            acc[2*k]   = fma2(ww.x, pv, acc[2*k]);
            acc[2*k+1] = fma2(ww.y, pv, acc[2*k+1]);
        }
    }
    float* op = out + (size_t)n*64*1024 + (size_t)coH*32*1024 + s;
#pragma unroll
    for (int k = 0; k < 16; k++) {
        float2 v = unpack2(acc[k]);
        op[(size_t)(2*k  )*1024] = v.x + bias[coH*32 + 2*k];
        op[(size_t)(2*k+1)*1024] = v.y + bias[coH*32 + 2*k+1];
    }
}

// ---------------- VQ: 2 positions per thread, no q writes ----------------
__global__ void vq_kernel(const float* __restrict__ z, const float* __restrict__ cb,
                          float* __restrict__ idx_out, float* __restrict__ losspart)
{
    extern __shared__ float sm[];
    float* cb_s = sm;
    float* csq  = sm + NCODE*VQ_DIM;
    int tid = threadIdx.x;
    for (int i = tid; i < NCODE*VQ_DIM; i += 256) cb_s[i] = cb[i];
    __syncthreads();
    for (int k = tid; k < NCODE; k += 256) {
        float s = 0.f;
#pragma unroll
        for (int d = 0; d < VQ_DIM; d++) { float c = cb_s[k*VQ_DIM + d]; s += c*c; }
        csq[k] = s;
    }
    __syncthreads();

    int s0 = blockIdx.x * 512 + tid;
    int s1 = s0 + 256;
    int bA = s0 >> 10, hwA = s0 & 1023;
    int bB = s1 >> 10, hwB = s1 & 1023;
    const float* zpA = z + (size_t)bA*64*1024 + hwA;
    const float* zpB = z + (size_t)bB*64*1024 + hwB;
    u64 zA[32], zB[32];
    float zsqA = 0.f, zsqB = 0.f;
#pragma unroll
    for (int u = 0; u < 32; u++) {
        float a0 = zpA[(size_t)(2*u)*1024], a1 = zpA[(size_t)(2*u+1)*1024];
        float b0 = zpB[(size_t)(2*u)*1024], b1 = zpB[(size_t)(2*u+1)*1024];
        zsqA += a0*a0 + a1*a1;
        zsqB += b0*b0 + b1*b1;
        zA[u] = pack2(a0, a1);
        zB[u] = pack2(b0, b1);
    }

    float bestA = 3.4e38f, bestB = 3.4e38f;
    int idxA = 0, idxB = 0;
    for (int k = 0; k < NCODE; k++) {
        const ulonglong2* cp2 = reinterpret_cast<const ulonglong2*>(cb_s + k*VQ_DIM);
        u64 dA0 = 0ull, dA1 = 0ull, dB0 = 0ull, dB1 = 0ull;
#pragma unroll
        for (int u = 0; u < 16; u++) {
            ulonglong2 c2 = cp2[u];
            dA0 = fma2(c2.x, zA[2*u],   dA0);
            dA1 = fma2(c2.y, zA[2*u+1], dA1);
            dB0 = fma2(c2.x, zB[2*u],   dB0);
            dB1 = fma2(c2.y, zB[2*u+1], dB1);
        }
        float2 da = unpack2(add2(dA0, dA1));
        float2 db = unpack2(add2(dB0, dB1));
        float cq = csq[k];
        float distA = zsqA - 2.f*(da.x + da.y) + cq;
        float distB = zsqB - 2.f*(db.x + db.y) + cq;
        if (distA < bestA) { bestA = distA; idxA = k; }
        if (distB < bestB) { bestB = distB; idxB = k; }
    }

    float lsum = 0.f;
#pragma unroll
    for (int u = 0; u < 32; u++) {
        float2 za = unpack2(zA[u]);
        float2 zb = unpack2(zB[u]);
        float ca0 = cb_s[idxA*VQ_DIM + 2*u], ca1 = cb_s[idxA*VQ_DIM + 2*u+1];
        float cb0 = cb_s[idxB*VQ_DIM + 2*u], cb1 = cb_s[idxB*VQ_DIM + 2*u+1];
        float dA0 = za.x - ca0, dA1 = za.y - ca1;
        float dB0 = zb.x - cb0, dB1 = zb.y - cb1;
        lsum += dA0*dA0 + dA1*dA1 + dB0*dB0 + dB1*dB1;
    }
    idx_out[s0] = (float)idxA;
    idx_out[s1] = (float)idxB;

    __shared__ float red[256];
    red[tid] = lsum; __syncthreads();
    for (int o = 128; o > 0; o >>= 1) {
        if (tid < o) red[tid] += red[tid + o];
        __syncthreads();
    }
    if (tid == 0) losspart[blockIdx.x] = red[0];
}

__global__ void loss_finalize_kernel(const float* __restrict__ losspart,
                                     float* __restrict__ out_losses)
{
    __shared__ float red[256];
    red[threadIdx.x] = (threadIdx.x < 128) ? losspart[threadIdx.x] : 0.f;
    __syncthreads();
    for (int o = 128; o > 0; o >>= 1) {
        if (threadIdx.x < o) red[threadIdx.x] += red[threadIdx.x + o];
        __syncthreads();
    }
    if (threadIdx.x == 0) {
        float m = red[0] / (65536.f * 64.f);
        out_losses[0] = m;
        out_losses[1] = m;
    }
}

// ---------------- dec2 quad-centric, ci-split x4, fused BN+ReLU in, tanh out ----------------
// grid (64 tiles, 64 n); block 256. Thread: quad = tid&63, cisub = tid>>6.
__global__ void dec2_kernel(const float* __restrict__ in, const float* __restrict__ w,
                            const float* __restrict__ bias, const float* __restrict__ scale,
                            const float* __restrict__ shift, float* __restrict__ out)
{
    extern __shared__ float sm[];
    float* w_s  = sm;                 // 3456
    float* in_s = sm + 3456;          // 13824
    float* sc_s = sm + 17280;         // 128
    float* sh_s = sm + 17408;         // 128
    float* red  = sm + 17536;         // 3072
    int n = blockIdx.y; int tile = blockIdx.x;
    int OH0 = (tile >> 3) * 16, OW0 = (tile & 7) * 16;
    int IH0 = OH0 >> 1, IW0 = OW0 >> 1;
    int tid = threadIdx.x;
    for (int i = tid; i < 3456; i += 256) w_s[i] = w[i];
    for (int i = tid; i < 128; i += 256) { sc_s[i] = scale[i]; sh_s[i] = shift[i]; }
    __syncthreads();
    for (int i = tid; i < 128*108; i += 256) {
        int ci = i / 108; int rem = i - ci*108; int rr = rem / 12; int cc = rem - rr*12;
        int ih = IH0 + rr, iw = IW0 + cc;
        float v = 0.f;
        if (cc < 9 && ih < 64 && iw < 64) {
            float raw = in[((size_t)(n*128 + ci)*64 + ih)*64 + iw];
            v = fmaxf(fmaf(raw, sc_s[ci], sh_s[ci]), 0.f);
        }
        in_s[i] = v;
    }
    __syncthreads();

    int q = tid & 63, qy = q >> 3, qx = q & 7;
    int cisub = tid >> 6;
    float acc[4][3];
#pragma unroll
    for (int p = 0; p < 4; p++)
#pragma unroll
        for (int co = 0; co < 3; co++) acc[p][co] = 0.f;

    int ci0 = cisub * 32;
#pragma unroll 4
    for (int ci = ci0; ci < ci0 + 32; ci++) {
        const float* base = in_s + ci*108 + qy*12 + qx;
        float v00 = base[0], v01 = base[1], v10 = base[12], v11 = base[13];
        const float* wp = w_s + ci*27;
#pragma unroll
        for (int co = 0; co < 3; co++) {
            const float* wc = wp + co*9;
            acc[0][co] += wc[4]*v00;
            acc[1][co] += wc[3]*v01 + wc[5]*v00;
            acc[2][co] += wc[1]*v10 + wc[7]*v00;
            acc[3][co] += wc[0]*v11 + wc[2]*v10 + wc[6]*v01 + wc[8]*v00;
        }
    }
#pragma unroll
    for (int p = 0; p < 4; p++)
#pragma unroll
        for (int co = 0; co < 3; co++)
            red[(p*3 + co)*256 + tid] = acc[p][co];
    __syncthreads();
    if (tid < 64) {
#pragma unroll
        for (int p = 0; p < 4; p++) {
            int ph = p >> 1, pw = p & 1;
            int oh = OH0 + 2*qy + ph, ow = OW0 + 2*qx + pw;
#pragma unroll
            for (int co = 0; co < 3; co++) {
                int j = p*3 + co;
                float s = red[j*256 + tid] + red[j*256 + tid + 64]
                        + red[j*256 + tid + 128] + red[j*256 + tid + 192];
                out[((size_t)(n*3 + co)*128 + oh)*128 + ow] = tanhf(s + bias[co]);
            }
        }
    }
}

// ---------------- host launch ----------------
static float* sym_addr(const void* sym)
{
    void* p = nullptr;
    cudaGetSymbolAddress(&p, sym);
    return (float*)p;
}

extern "C" void kernel_launch(void* const* d_in, const int* in_sizes, int n_in,
                              void* d_out, int out_size)
{
    const float* x       = (const float*)d_in[0];
    const float* enc1_w  = (const float*)d_in[1];
    const float* enc1_b  = (const float*)d_in[2];
    const float* bn1_g   = (const float*)d_in[3];
    const float* bn1_b   = (const float*)d_in[4];
    const float* enc2_w  = (const float*)d_in[5];
    const float* enc2_b  = (const float*)d_in[6];
    const float* pre_w   = (const float*)d_in[7];
    const float* pre_b   = (const float*)d_in[8];
    const float* codebook= (const float*)d_in[9];
    const float* post_w  = (const float*)d_in[10];
    const float* post_b  = (const float*)d_in[11];
    const float* dec1_w  = (const float*)d_in[12];
    const float* dec1_b  = (const float*)d_in[13];
    const float* dbn1_g  = (const float*)d_in[14];
    const float* dbn1_b  = (const float*)d_in[15];
    const float* dec2_w  = (const float*)d_in[16];
    const float* dec2_b  = (const float*)d_in[17];

    float* out = (float*)d_out;
    float* out_losses = out + RECON_ELEMS;
    float* out_idx    = out + RECON_ELEMS + 2;

    float* h1  = sym_addr(g_h1);
    __nv_bfloat16* h1hi; { void* p; cudaGetSymbolAddress(&p, g_h1hi); h1hi = (__nv_bfloat16*)p; }
    __nv_bfloat16* h1lo; { void* p; cudaGetSymbolAddress(&p, g_h1lo); h1lo = (__nv_bfloat16*)p; }
    __nv_bfloat16* w2chi; { void* p; cudaGetSymbolAddress(&p, g_w2chi); w2chi = (__nv_bfloat16*)p; }
    __nv_bfloat16* w2clo; { void* p; cudaGetSymbolAddress(&p, g_w2clo); w2clo = (__nv_bfloat16*)p; }
    __nv_bfloat16* wd1hi; { void* p; cudaGetSymbolAddress(&p, g_wd1hi); wd1hi = (__nv_bfloat16*)p; }
    __nv_bfloat16* wd1lo; { void* p; cudaGetSymbolAddress(&p, g_wd1lo); wd1lo = (__nv_bfloat16*)p; }
    __nv_bfloat16* dhi; { void* p; cudaGetSymbolAddress(&p, g_dhi); dhi = (__nv_bfloat16*)p; }
    __nv_bfloat16* dlo; { void* p; cudaGetSymbolAddress(&p, g_dlo); dlo = (__nv_bfloat16*)p; }
    __nv_bfloat16* tabhi; { void* p; cudaGetSymbolAddress(&p, g_tabhi); tabhi = (__nv_bfloat16*)p; }
    __nv_bfloat16* tablo; { void* p; cudaGetSymbolAddress(&p, g_tablo); tablo = (__nv_bfloat16*)p; }
    float* h2  = sym_addr(g_h2);
    float* z   = sym_addr(g_z);
    float* d1  = sym_addr(g_d1);
    float* psum = sym_addr(g_psum);
    float* psq  = sym_addr(g_psq);
    float* sc   = sym_addr(g_scale);
    float* sh   = sym_addr(g_shift);
    float* lp   = sym_addr(g_losspart);

    const unsigned MM_SMEM = 2*MM_STAGE + 1024;   // 132096
    cudaFuncSetAttribute(conv2_mma_kernel, cudaFuncAttributeMaxDynamicSharedMemorySize, MM_SMEM);
    cudaFuncSetAttribute(dec1_mma_kernel,  cudaFuncAttributeMaxDynamicSharedMemorySize, MM_SMEM);
    cudaFuncSetAttribute(vq_kernel,   cudaFuncAttributeMaxDynamicSharedMemorySize, 133120);
    cudaFuncSetAttribute(dec2_kernel, cudaFuncAttributeMaxDynamicSharedMemorySize, 84480);

    const float inv_cnt = 1.f / 262144.f;

    // weight / table prep
    wtrans_conv2_bf16<<<1152, 256>>>(enc2_w, w2chi, w2clo);
    wtrans_dec1_bf16<<<1152, 256>>>(dec1_w, wd1hi, wd1lo);
    table_kernel<<<512, 256>>>(post_w, post_b, codebook, tabhi, tablo);

    // encoder
    conv1_kernel<<<dim3(4,4,64), 256>>>(x, enc1_w, enc1_b, h1);       // NHWC fp32
    bn_stats_nhwc<<<1024, 256>>>(h1, psum, psq, 1024);
    bn_finalize_kernel<<<1,128>>>(psum, psq, bn1_g, bn1_b, sc, sh, 1024, inv_cnt);
    bnrelu_split_kernel<<<32768, 256>>>(h1, h1hi, h1lo, sc, sh);
    conv2_mma_kernel<<<dim3(8,2,64), 256, MM_SMEM>>>(h1hi, h1lo, w2chi, w2clo, enc2_b, h2);
    pre_kernel<<<dim3(4,2,64), 256>>>(h2, pre_w, pre_b, z);

    // VQ + gather (replaces post + split_d)
    vq_kernel<<<128, 256, 133120>>>(z, codebook, out_idx, lp);
    loss_finalize_kernel<<<1,256>>>(lp, out_losses);
    gather_d<<<2048, 256>>>(out_idx, (const uint4*)tabhi, (const uint4*)tablo,
                            (uint4*)dhi, (uint4*)dlo);

    // decoder
    dec1_mma_kernel<<<dim3(8,4,64), 256, MM_SMEM>>>(dhi, dlo, wd1hi, wd1lo, dec1_b, d1);
    bn_stats_kernel<<<dim3(128,32), 256>>>(d1, psum, psq, 128, 32);
    bn_finalize_kernel<<<1,128>>>(psum, psq, dbn1_g, dbn1_b, sc, sh, 32, inv_cnt);
    dec2_kernel<<<dim3(64,64), 256, 84480>>>(d1, dec2_w, dec2_b, sc, sh, out);

    (void)in_sizes; (void)n_in; (void)out_size;
}

// round 11
// speedup vs baseline: 2.7964x; 1.0704x over previous
#include <cuda_runtime.h>
#include <cuda_bf16.h>
#include <cstdint>

#define H1_ELEMS (64*128*64*64)
#define H2_ELEMS (64*256*32*32)
#define Z_ELEMS  (64*64*32*32)
#define D_ELEMS  (64*256*32*32)
#define D1_ELEMS (64*128*64*64)
#define RECON_ELEMS (64*3*128*128)
#define VQ_DIM 64
#define NCODE 512

__device__ float g_h1[H1_ELEMS];                 // NHWC fp32
__device__ __nv_bfloat16 g_h1hi[H1_ELEMS];
__device__ __nv_bfloat16 g_h1lo[H1_ELEMS];
__device__ float g_h2[H2_ELEMS];
__device__ float g_z[Z_ELEMS];
__device__ __nv_bfloat16 g_dhi[D_ELEMS];
__device__ __nv_bfloat16 g_dlo[D_ELEMS];
__device__ float g_d1[D1_ELEMS];
__device__ __nv_bfloat16 g_w2chi[256*1152];
__device__ __nv_bfloat16 g_w2clo[256*1152];
__device__ __nv_bfloat16 g_wd1hi[128*2304];
__device__ __nv_bfloat16 g_wd1lo[128*2304];
__device__ __nv_bfloat16 g_tabhi[NCODE*256];
__device__ __nv_bfloat16 g_tablo[NCODE*256];
__device__ float g_psum[128*2048];
__device__ float g_psq[128*2048];
__device__ float g_scale[128];
__device__ float g_shift[128];
__device__ float g_losspart[256];

typedef unsigned long long u64;
__device__ __forceinline__ u64 pack2(float a, float b) {
    u64 r; asm("mov.b64 %0, {%1,%2};" : "=l"(r) : "f"(a), "f"(b)); return r;
}
__device__ __forceinline__ u64 fma2(u64 a, u64 b, u64 c) {
    u64 d; asm("fma.rn.f32x2 %0, %1, %2, %3;" : "=l"(d) : "l"(a), "l"(b), "l"(c)); return d;
}
__device__ __forceinline__ u64 add2(u64 a, u64 b) {
    u64 d; asm("add.rn.f32x2 %0, %1, %2;" : "=l"(d) : "l"(a), "l"(b)); return d;
}
__device__ __forceinline__ float2 unpack2(u64 a) {
    float lo, hi; asm("mov.b64 {%0,%1}, %2;" : "=f"(lo), "=f"(hi) : "l"(a));
    return make_float2(lo, hi);
}
__device__ __forceinline__ void cp16(uint32_t saddr, const void* gaddr) {
    asm volatile("cp.async.cg.shared.global [%0], [%1], 16;" :: "r"(saddr), "l"(gaddr));
}
__device__ __forceinline__ void cp16z(uint32_t saddr, const void* gaddr, bool ok) {
    int sz = ok ? 16 : 0;
    asm volatile("cp.async.cg.shared.global [%0], [%1], 16, %2;" :: "r"(saddr), "l"(gaddr), "r"(sz));
}
#define CP_COMMIT() asm volatile("cp.async.commit_group;")
#define CP_WAIT(n)  asm volatile("cp.async.wait_group %0;" :: "n"(n))

#define SWZ(o) ((o) ^ ((((uint32_t)(o)) >> 3) & 0x70))

__device__ __forceinline__ void ldsm4(uint32_t* r, uint32_t addr) {
    asm volatile("ldmatrix.sync.aligned.m8n8.x4.shared.b16 {%0,%1,%2,%3}, [%4];"
                 : "=r"(r[0]), "=r"(r[1]), "=r"(r[2]), "=r"(r[3]) : "r"(addr));
}
__device__ __forceinline__ void mma16816(float* c, const uint32_t* a, const uint32_t* b) {
    asm volatile(
        "mma.sync.aligned.m16n8k16.row.col.f32.bf16.bf16.f32 "
        "{%0,%1,%2,%3}, {%4,%5,%6,%7}, {%8,%9}, {%0,%1,%2,%3};"
        : "+f"(c[0]), "+f"(c[1]), "+f"(c[2]), "+f"(c[3])
        : "r"(a[0]), "r"(a[1]), "r"(a[2]), "r"(a[3]), "r"(b[0]), "r"(b[1]));
}

// ---------------- weight prep ----------------
__global__ void wtrans_conv2_bf16(const float* __restrict__ w,
                                  __nv_bfloat16* __restrict__ whi, __nv_bfloat16* __restrict__ wlo)
{
    int i = blockIdx.x * 256 + threadIdx.x;
    if (i >= 256*1152) return;
    int co = i / 1152; int rem = i - co*1152; int t = rem >> 7; int ci = rem & 127;
    float v = w[((size_t)co*128 + ci)*9 + t];
    __nv_bfloat16 h = __float2bfloat16(v);
    whi[i] = h;
    wlo[i] = __float2bfloat16(v - __bfloat162float(h));
}

__global__ void wtrans_dec1_bf16(const float* __restrict__ w,
                                 __nv_bfloat16* __restrict__ whi, __nv_bfloat16* __restrict__ wlo)
{
    int i = blockIdx.x * 256 + threadIdx.x;
    if (i >= 128*2304) return;
    int co = i / 2304; int k = i - co*2304;
    int kh, kw, ci;
    if (k < 256)       { kh = 1; kw = 1; ci = k; }
    else if (k < 768)  { int t = (k-256) >> 8; ci = (k-256) & 255; kh = 1; kw = t ? 2 : 0; }
    else if (k < 1280) { int t = (k-768) >> 8; ci = (k-768) & 255; kh = t ? 2 : 0; kw = 1; }
    else               { int t = (k-1280) >> 8; ci = (k-1280) & 255;
                         kh = (t < 2) ? 0 : 2; kw = (t & 1) ? 2 : 0; }
    float v = w[((size_t)ci*128 + co)*9 + kh*3 + kw];
    __nv_bfloat16 h = __float2bfloat16(v);
    whi[i] = h;
    wlo[i] = __float2bfloat16(v - __bfloat162float(h));
}

__global__ void table_kernel(const float* __restrict__ pw, const float* __restrict__ pb,
                             const float* __restrict__ cb,
                             __nv_bfloat16* __restrict__ thi, __nv_bfloat16* __restrict__ tlo)
{
    __shared__ float c_s[64];
    int k = blockIdx.x, co = threadIdx.x;
    if (co < 64) c_s[co] = cb[k*64 + co];
    __syncthreads();
    float acc = pb[co];
#pragma unroll 8
    for (int ci = 0; ci < 64; ci++) acc += pw[co*64 + ci] * c_s[ci];
    __nv_bfloat16 h = __float2bfloat16(acc);
    thi[k*256 + co] = h;
    tlo[k*256 + co] = __float2bfloat16(acc - __bfloat162float(h));
}

// ---------------- conv1: 3->128, s2, NHWC output, f32x2 over co ----------------
__global__ void conv1_kernel(const float* __restrict__ x, const float* __restrict__ w,
                             const float* __restrict__ bias, float* __restrict__ out)
{
    __shared__ u64 w2_s[64*28];        // paired weights (co pairs x 28 taps)
    __shared__ float in_s[3*33*33];
    __shared__ float bias_s[128];
    int n = blockIdx.z;
    int OH0 = blockIdx.y * 16, OW0 = blockIdx.x * 16;
    int tid = threadIdx.x;
    for (int e = tid; e < 64*28; e += 256) {
        int cp = e / 28, t = e - cp*28;
        float v0 = (t < 27) ? w[(2*cp)*27 + t] : 0.f;
        float v1 = (t < 27) ? w[(2*cp+1)*27 + t] : 0.f;
        w2_s[e] = pack2(v0, v1);
    }
    for (int i = tid; i < 128; i += 256) bias_s[i] = bias[i];
    int IH0 = OH0*2 - 1, IW0 = OW0*2 - 1;
    for (int i = tid; i < 3*33*33; i += 256) {
        int ci = i / 1089; int r = (i % 1089) / 33; int c = i % 33;
        int ih = IH0 + r, iw = IW0 + c;
        float v = 0.f;
        if (ih >= 0 && ih < 128 && iw >= 0 && iw < 128) v = x[((n*3 + ci)*128 + ih)*128 + iw];
        in_s[i] = v;
    }
    __syncthreads();
    int ty = tid >> 4, tx = tid & 15;
    u64 in2[28];
#pragma unroll
    for (int ci = 0; ci < 3; ci++)
#pragma unroll
        for (int kh = 0; kh < 3; kh++)
#pragma unroll
            for (int kw = 0; kw < 3; kw++) {
                float f = in_s[ci*1089 + (ty*2+kh)*33 + (tx*2+kw)];
                in2[ci*9 + kh*3 + kw] = pack2(f, f);
            }
    in2[27] = 0ull;
    int oh = OH0 + ty, ow = OW0 + tx;
    float* outp = out + (((size_t)n*64 + oh)*64 + ow)*128;
    float4 buf;
    for (int cp = 0; cp < 64; cp++) {
        const ulonglong2* wp = reinterpret_cast<const ulonglong2*>(w2_s + cp*28);
        u64 a0 = 0ull, a1 = 0ull;
#pragma unroll
        for (int u = 0; u < 14; u++) {
            ulonglong2 ww = wp[u];
            a0 = fma2(ww.x, in2[2*u],   a0);
            a1 = fma2(ww.y, in2[2*u+1], a1);
        }
        float2 r = unpack2(add2(a0, a1));
        r.x += bias_s[2*cp]; r.y += bias_s[2*cp+1];
        if (cp & 1) {
            buf.z = r.x; buf.w = r.y;
            *reinterpret_cast<float4*>(outp + (cp-1)*2) = buf;
        } else {
            buf.x = r.x; buf.y = r.y;
        }
    }
}

// ---------------- BN stats NHWC (for h1) ----------------
__global__ void bn_stats_nhwc(const float* __restrict__ x, float* __restrict__ psum,
                              float* __restrict__ psq, int nblk)
{
    int blk = blockIdx.x;
    int cg = threadIdx.x & 31;
    int rg = threadIdx.x >> 5;
    float4 s = make_float4(0,0,0,0), sq = make_float4(0,0,0,0);
    for (int r = blk*8 + rg; r < 262144; r += nblk*8) {
        float4 v = *reinterpret_cast<const float4*>(x + (size_t)r*128 + cg*4);
        s.x += v.x; s.y += v.y; s.z += v.z; s.w += v.w;
        sq.x += v.x*v.x; sq.y += v.y*v.y; sq.z += v.z*v.z; sq.w += v.w*v.w;
    }
    __shared__ float ss[256*4], qs[256*4];
    reinterpret_cast<float4*>(ss)[threadIdx.x] = s;
    reinterpret_cast<float4*>(qs)[threadIdx.x] = sq;
    __syncthreads();
    if (threadIdx.x < 128) {
        int c = threadIdx.x;
        int cgi = c >> 2, j = c & 3;
        float a = 0.f, b = 0.f;
        for (int g = 0; g < 8; g++) { a += ss[(g*32+cgi)*4 + j]; b += qs[(g*32+cgi)*4 + j]; }
        psum[c*nblk + blk] = a;
        psq[c*nblk + blk] = b;
    }
}

// ---------------- parallel BN finalize: one block per channel ----------------
__global__ void bn_finalize_par(const float* __restrict__ psum, const float* __restrict__ psq,
                                const float* __restrict__ g, const float* __restrict__ b,
                                float* __restrict__ scale, float* __restrict__ shift,
                                int nblk, float inv_count)
{
    int c = blockIdx.x;
    int tid = threadIdx.x;
    float s = 0.f, sq = 0.f;
    for (int i = tid; i < nblk; i += 256) { s += psum[c*nblk + i]; sq += psq[c*nblk + i]; }
    __shared__ float rs[256], rq[256];
    rs[tid] = s; rq[tid] = sq;
    __syncthreads();
    for (int o = 128; o > 0; o >>= 1) {
        if (tid < o) { rs[tid] += rs[tid+o]; rq[tid] += rq[tid+o]; }
        __syncthreads();
    }
    if (tid == 0) {
        float mean = rs[0] * inv_count;
        float var = rq[0] * inv_count - mean*mean;
        float r = rsqrtf(var + 1e-5f);
        float sc = g[c] * r;
        scale[c] = sc;
        shift[c] = b[c] - mean * sc;
    }
}

// ---------------- BN+ReLU + bf16 split ----------------
__global__ void bnrelu_split_kernel(const float* __restrict__ x,
                                    __nv_bfloat16* __restrict__ hi, __nv_bfloat16* __restrict__ lo,
                                    const float* __restrict__ sc, const float* __restrict__ sh)
{
    long i = (long)blockIdx.x * 256 + threadIdx.x;
    if (i >= 8388608L) return;
    int c = (int)(i & 31) * 4;
    float4 v = reinterpret_cast<const float4*>(x)[i];
    float r0 = fmaxf(fmaf(v.x, sc[c+0], sh[c+0]), 0.f);
    float r1 = fmaxf(fmaf(v.y, sc[c+1], sh[c+1]), 0.f);
    float r2 = fmaxf(fmaf(v.z, sc[c+2], sh[c+2]), 0.f);
    float r3 = fmaxf(fmaf(v.w, sc[c+3], sh[c+3]), 0.f);
    __nv_bfloat16 h0 = __float2bfloat16(r0), h1 = __float2bfloat16(r1);
    __nv_bfloat16 h2 = __float2bfloat16(r2), h3 = __float2bfloat16(r3);
    __nv_bfloat16 l0 = __float2bfloat16(r0 - __bfloat162float(h0));
    __nv_bfloat16 l1 = __float2bfloat16(r1 - __bfloat162float(h1));
    __nv_bfloat16 l2 = __float2bfloat16(r2 - __bfloat162float(h2));
    __nv_bfloat16 l3 = __float2bfloat16(r3 - __bfloat162float(h3));
    __nv_bfloat162* hp = reinterpret_cast<__nv_bfloat162*>(hi);
    __nv_bfloat162* lp = reinterpret_cast<__nv_bfloat162*>(lo);
    hp[2*i]   = __nv_bfloat162(h0, h1);
    hp[2*i+1] = __nv_bfloat162(h2, h3);
    lp[2*i]   = __nv_bfloat162(l0, l1);
    lp[2*i+1] = __nv_bfloat162(l2, l3);
}

// ---------------- gather: dhi/dlo[pos][256] = table[idx[pos]] ----------------
__global__ void gather_d(const float* __restrict__ idx_f,
                         const uint4* __restrict__ thi, const uint4* __restrict__ tlo,
                         uint4* __restrict__ dhi, uint4* __restrict__ dlo)
{
    int tid = threadIdx.x;
    int pos = blockIdx.x*32 + (tid >> 3);
    int c = tid & 7;
    int k = (int)idx_f[pos];
#pragma unroll
    for (int j = 0; j < 4; j++) {
        dhi[(size_t)pos*32 + c + j*8] = thi[k*32 + c + j*8];
        dlo[(size_t)pos*32 + c + j*8] = tlo[k*32 + c + j*8];
    }
}

// ---------------- conv2 via mma.sync bf16 split ----------------
#define MM_SPLIT 16384u
#define MM_STAGE (4u*MM_SPLIT)
__global__ void __launch_bounds__(256, 1) conv2_mma_kernel(
        const __nv_bfloat16* __restrict__ inhi, const __nv_bfloat16* __restrict__ inlo,
        const __nv_bfloat16* __restrict__ whi, const __nv_bfloat16* __restrict__ wlo,
        const float* __restrict__ bias, float* __restrict__ out)
{
    extern __shared__ char dsm[];
    __shared__ float bias_s[128];
    int mt = blockIdx.x, Nt = blockIdx.y, n = blockIdx.z;
    int OH0 = mt * 4;
    int tid = threadIdx.x, wid = tid >> 5, lane = tid & 31;
    int mrow = (wid >> 1) * 32;
    int ncol = (wid & 1) * 64;

    uint32_t base0 = ((uint32_t)__cvta_generic_to_shared(dsm) + 1023u) & ~1023u;
    for (int i = tid; i < 128; i += 256) bias_s[i] = bias[Nt*128 + i];

    auto fill = [&](int kc, int buf) {
        int t = kc >> 1, ci0 = (kc & 1) << 6;
        int kh = t / 3, kw = t - (t/3)*3;
        uint32_t Ah = base0 + buf*MM_STAGE;
        uint32_t Al = Ah + MM_SPLIT;
        uint32_t Bh = Al + MM_SPLIT;
        uint32_t Bl = Bh + MM_SPLIT;
        for (int i = tid; i < 1024; i += 256) {
            int px = i >> 3, c16 = i & 7;
            int oh = OH0 + (px >> 5), ow = px & 31;
            int ih = 2*oh - 1 + kh, iw = 2*ow - 1 + kw;
            bool ok = (ih >= 0) && (ih < 64) && (iw >= 0) && (iw < 64);
            long off = ((long)(n*64 + (ok ? ih : 0))*64 + (ok ? iw : 0))*128 + ci0 + c16*8;
            uint32_t d = SWZ(px*128 + c16*16);
            cp16z(Ah + d, inhi + off, ok);
            cp16z(Al + d, inlo + off, ok);
        }
        for (int i = tid; i < 1024; i += 256) {
            int co = i >> 3, c16 = i & 7;
            long off = (long)(Nt*128 + co)*1152 + t*128 + ci0 + c16*8;
            uint32_t d = SWZ(co*128 + c16*16);
            cp16(Bh + d, whi + off);
            cp16(Bl + d, wlo + off);
        }
    };

    float acc[2][8][4];
#pragma unroll
    for (int a = 0; a < 2; a++)
#pragma unroll
        for (int b = 0; b < 8; b++)
#pragma unroll
            for (int c = 0; c < 4; c++) acc[a][b][c] = 0.f;

    fill(0, 0); CP_COMMIT();
    for (int s = 0; s < 18; s++) {
        if (s < 17) { fill(s+1, (s+1)&1); CP_COMMIT(); CP_WAIT(1); }
        else        { CP_WAIT(0); }
        __syncthreads();
        uint32_t Ah = base0 + (s&1)*MM_STAGE;
        uint32_t Al = Ah + MM_SPLIT;
        uint32_t Bh = Al + MM_SPLIT;
        uint32_t Bl = Bh + MM_SPLIT;
#pragma unroll
        for (int ks = 0; ks < 4; ks++) {
            uint32_t ah[2][4], al[2][4], bh[4][4], bl[4][4];
#pragma unroll
            for (int mi = 0; mi < 2; mi++) {
                int row = mrow + mi*16 + (lane & 15);
                uint32_t ao = SWZ(row*128 + ks*32 + (lane >> 4)*16);
                ldsm4(ah[mi], Ah + ao);
                ldsm4(al[mi], Al + ao);
            }
#pragma unroll
            for (int nb = 0; nb < 4; nb++) {
                int g = lane >> 3, r = lane & 7;
                int co_l = ncol + nb*16 + ((g >> 1) << 3) + r;
                uint32_t bo = SWZ(co_l*128 + ks*32 + (g & 1)*16);
                ldsm4(bh[nb], Bh + bo);
                ldsm4(bl[nb], Bl + bo);
            }
#pragma unroll
            for (int mi = 0; mi < 2; mi++)
#pragma unroll
                for (int nt = 0; nt < 8; nt++) {
                    const uint32_t* pbh = &bh[nt >> 1][(nt & 1)*2];
                    const uint32_t* pbl = &bl[nt >> 1][(nt & 1)*2];
                    mma16816(acc[mi][nt], ah[mi], pbh);
                    mma16816(acc[mi][nt], ah[mi], pbl);
                    mma16816(acc[mi][nt], al[mi], pbh);
                }
        }
        __syncthreads();
    }

    float* osm = reinterpret_cast<float*>(dsm);
#pragma unroll
    for (int mi = 0; mi < 2; mi++)
#pragma unroll
        for (int nt = 0; nt < 8; nt++) {
            int px0 = mrow + mi*16 + (lane >> 2);
            int col = ncol + nt*8 + (lane & 3)*2;
            osm[col*132 + px0]         = acc[mi][nt][0];
            osm[(col+1)*132 + px0]     = acc[mi][nt][1];
            osm[col*132 + px0 + 8]     = acc[mi][nt][2];
            osm[(col+1)*132 + px0 + 8] = acc[mi][nt][3];
        }
    __syncthreads();
    for (int i = tid; i < 128*32; i += 256) {
        int co = i >> 5, p4 = (i & 31)*4;
        float4 v = *reinterpret_cast<const float4*>(osm + co*132 + p4);
        float b = bias_s[co];
        v.x += b; v.y += b; v.z += b; v.w += b;
        int cog = Nt*128 + co;
        *reinterpret_cast<float4*>(out + ((size_t)(n*256 + cog))*1024 + OH0*32 + p4) = v;
    }
}

// ---------------- dec1 via mma.sync bf16 split + fused BN partial stats ----------------
__global__ void __launch_bounds__(256, 1) dec1_mma_kernel(
        const __nv_bfloat16* __restrict__ inhi, const __nv_bfloat16* __restrict__ inlo,
        const __nv_bfloat16* __restrict__ whi, const __nv_bfloat16* __restrict__ wlo,
        const float* __restrict__ bias, float* __restrict__ out,
        float* __restrict__ psum, float* __restrict__ psq)
{
    extern __shared__ char dsm[];
    __shared__ float bias_s[128];
    __shared__ float sred[256], qred[256];
    const int NKC[4]  = {4, 8, 8, 16};
    const int KOFS[4] = {0, 256, 768, 1280};
    const int DYT[4][4] = {{0,0,0,0},{0,0,0,0},{1,0,0,0},{1,1,0,0}};
    const int DXT[4][4] = {{0,0,0,0},{1,0,0,0},{0,0,0,0},{1,0,1,0}};

    int mt = blockIdx.x, cls = blockIdx.y, n = blockIdx.z;
    int ph = cls >> 1, pw = cls & 1;
    int Y0 = mt * 4;
    int tid = threadIdx.x, wid = tid >> 5, lane = tid & 31;
    int mrow = (wid >> 1) * 32;
    int ncol = (wid & 1) * 64;

    uint32_t base0 = ((uint32_t)__cvta_generic_to_shared(dsm) + 1023u) & ~1023u;
    for (int i = tid; i < 128; i += 256) bias_s[i] = bias[i];

    int kbase = KOFS[cls];
    int nk = NKC[cls];

    auto fill = [&](int kc, int buf) {
        int t = kc >> 2, ci0 = (kc & 3) << 6;
        int dy = DYT[cls][t], dx = DXT[cls][t];
        uint32_t Ah = base0 + buf*MM_STAGE;
        uint32_t Al = Ah + MM_SPLIT;
        uint32_t Bh = Al + MM_SPLIT;
        uint32_t Bl = Bh + MM_SPLIT;
        for (int i = tid; i < 1024; i += 256) {
            int px = i >> 3, c16 = i & 7;
            int y = Y0 + (px >> 5), x = px & 31;
            int iy = y + dy, ix = x + dx;
            bool ok = (iy < 32) && (ix < 32);
            long off = ((long)(n*32 + (ok ? iy : 0))*32 + (ok ? ix : 0))*256 + ci0 + c16*8;
            uint32_t d = SWZ(px*128 + c16*16);
            cp16z(Ah + d, inhi + off, ok);
            cp16z(Al + d, inlo + off, ok);
        }
        for (int i = tid; i < 1024; i += 256) {
            int co = i >> 3, c16 = i & 7;
            long off = (long)co*2304 + kbase + t*256 + ci0 + c16*8;
            uint32_t d = SWZ(co*128 + c16*16);
            cp16(Bh + d, whi + off);
            cp16(Bl + d, wlo + off);
        }
    };

    float acc[2][8][4];
#pragma unroll
    for (int a = 0; a < 2; a++)
#pragma unroll
        for (int b = 0; b < 8; b++)
#pragma unroll
            for (int c = 0; c < 4; c++) acc[a][b][c] = 0.f;

    fill(0, 0); CP_COMMIT();
    for (int s = 0; s < nk; s++) {
        if (s < nk-1) { fill(s+1, (s+1)&1); CP_COMMIT(); CP_WAIT(1); }
        else          { CP_WAIT(0); }
        __syncthreads();
        uint32_t Ah = base0 + (s&1)*MM_STAGE;
        uint32_t Al = Ah + MM_SPLIT;
        uint32_t Bh = Al + MM_SPLIT;
        uint32_t Bl = Bh + MM_SPLIT;
#pragma unroll
        for (int ks = 0; ks < 4; ks++) {
            uint32_t ah[2][4], al[2][4], bh[4][4], bl[4][4];
#pragma unroll
            for (int mi = 0; mi < 2; mi++) {
                int row = mrow + mi*16 + (lane & 15);
                uint32_t ao = SWZ(row*128 + ks*32 + (lane >> 4)*16);
                ldsm4(ah[mi], Ah + ao);
                ldsm4(al[mi], Al + ao);
            }
#pragma unroll
            for (int nb = 0; nb < 4; nb++) {
                int g = lane >> 3, r = lane & 7;
                int co_l = ncol + nb*16 + ((g >> 1) << 3) + r;
                uint32_t bo = SWZ(co_l*128 + ks*32 + (g & 1)*16);
                ldsm4(bh[nb], Bh + bo);
                ldsm4(bl[nb], Bl + bo);
            }
#pragma unroll
            for (int mi = 0; mi < 2; mi++)
#pragma unroll
                for (int nt = 0; nt < 8; nt++) {
                    const uint32_t* pbh = &bh[nt >> 1][(nt & 1)*2];
                    const uint32_t* pbl = &bl[nt >> 1][(nt & 1)*2];
                    mma16816(acc[mi][nt], ah[mi], pbh);
                    mma16816(acc[mi][nt], ah[mi], pbl);
                    mma16816(acc[mi][nt], al[mi], pbh);
                }
        }
        __syncthreads();
    }

    float* osm = reinterpret_cast<float*>(dsm);   // stride 133, conflict-free stats sweep
#pragma unroll
    for (int mi = 0; mi < 2; mi++)
#pragma unroll
        for (int nt = 0; nt < 8; nt++) {
            int px0 = mrow + mi*16 + (lane >> 2);
            int col = ncol + nt*8 + (lane & 3)*2;
            osm[col*133 + px0]         = acc[mi][nt][0];
            osm[(col+1)*133 + px0]     = acc[mi][nt][1];
            osm[col*133 + px0 + 8]     = acc[mi][nt][2];
            osm[(col+1)*133 + px0 + 8] = acc[mi][nt][3];
        }
    __syncthreads();
    for (int i = tid; i < 128*128; i += 256) {
        int co = i >> 7, p = i & 127;
        int y = Y0 + (p >> 5), x = p & 31;
        int oh = 2*y + ph, ow = 2*x + pw;
        out[((size_t)(n*128 + co)*64 + oh)*64 + ow] = osm[co*133 + p] + bias_s[co];
    }
    // fused BN partial stats over this CTA's 128 px (all 128 channels)
    {
        int co = tid & 127, half = tid >> 7;
        float s = 0.f, sq = 0.f;
        const float* op = osm + co*133 + half*64;
        float b = bias_s[co];
#pragma unroll 8
        for (int j = 0; j < 64; j++) {
            float v = op[j] + b;
            s += v; sq += v*v;
        }
        sred[tid] = s; qred[tid] = sq;
        __syncthreads();
        if (tid < 128) {
            int blk = blockIdx.x + 8*blockIdx.y + 32*blockIdx.z;   // 0..2047
            psum[tid*2048 + blk] = sred[tid] + sred[tid + 128];
            psq[tid*2048 + blk]  = qred[tid] + qred[tid + 128];
        }
    }
}

// ---------------- pre 1x1: 256->64, f32x2 ----------------
__global__ void pre_kernel(const float* __restrict__ in, const float* __restrict__ w,
                           const float* __restrict__ bias, float* __restrict__ out)
{
    __shared__ float w_t[256*32];
    int n = blockIdx.z, coH = blockIdx.y;
    int s = blockIdx.x * 256 + threadIdx.x;
    for (int i = threadIdx.x; i < 256*32; i += 256) {
        int ci = i >> 5, co = i & 31;
        w_t[i] = w[(size_t)(coH*32 + co)*256 + ci];
    }
    __syncthreads();
    u64 acc[16];
#pragma unroll
    for (int k = 0; k < 16; k++) acc[k] = 0ull;
    const float* ip = in + (size_t)n*256*1024 + s;
#pragma unroll 4
    for (int ci = 0; ci < 256; ci++) {
        float v = ip[(size_t)ci*1024];
        u64 pv = pack2(v, v);
        const ulonglong2* wp = reinterpret_cast<const ulonglong2*>(w_t + ci*32);
#pragma unroll
        for (int k = 0; k < 8; k++) {
            ulonglong2 ww = wp[k];
            acc[2*k]   = fma2(ww.x, pv, acc[2*k]);
            acc[2*k+1] = fma2(ww.y, pv, acc[2*k+1]);
        }
    }
    float* op = out + (size_t)n*64*1024 + (size_t)coH*32*1024 + s;
#pragma unroll
    for (int k = 0; k < 16; k++) {
        float2 v = unpack2(acc[k]);
        op[(size_t)(2*k  )*1024] = v.x + bias[coH*32 + 2*k];
        op[(size_t)(2*k+1)*1024] = v.y + bias[coH*32 + 2*k+1];
    }
}

// ---------------- VQ: 2 positions per thread ----------------
__global__ void vq_kernel(const float* __restrict__ z, const float* __restrict__ cb,
                          float* __restrict__ idx_out, float* __restrict__ losspart)
{
    extern __shared__ float sm[];
    float* cb_s = sm;
    float* csq  = sm + NCODE*VQ_DIM;
    int tid = threadIdx.x;
    for (int i = tid; i < NCODE*VQ_DIM; i += 256) cb_s[i] = cb[i];
    __syncthreads();
    for (int k = tid; k < NCODE; k += 256) {
        float s = 0.f;
#pragma unroll
        for (int d = 0; d < VQ_DIM; d++) { float c = cb_s[k*VQ_DIM + d]; s += c*c; }
        csq[k] = s;
    }
    __syncthreads();

    int s0 = blockIdx.x * 512 + tid;
    int s1 = s0 + 256;
    int bA = s0 >> 10, hwA = s0 & 1023;
    int bB = s1 >> 10, hwB = s1 & 1023;
    const float* zpA = z + (size_t)bA*64*1024 + hwA;
    const float* zpB = z + (size_t)bB*64*1024 + hwB;
    u64 zA[32], zB[32];
    float zsqA = 0.f, zsqB = 0.f;
#pragma unroll
    for (int u = 0; u < 32; u++) {
        float a0 = zpA[(size_t)(2*u)*1024], a1 = zpA[(size_t)(2*u+1)*1024];
        float b0 = zpB[(size_t)(2*u)*1024], b1 = zpB[(size_t)(2*u+1)*1024];
        zsqA += a0*a0 + a1*a1;
        zsqB += b0*b0 + b1*b1;
        zA[u] = pack2(a0, a1);
        zB[u] = pack2(b0, b1);
    }

    float bestA = 3.4e38f, bestB = 3.4e38f;
    int idxA = 0, idxB = 0;
    for (int k = 0; k < NCODE; k++) {
        const ulonglong2* cp2 = reinterpret_cast<const ulonglong2*>(cb_s + k*VQ_DIM);
        u64 dA0 = 0ull, dA1 = 0ull, dB0 = 0ull, dB1 = 0ull;
#pragma unroll
        for (int u = 0; u < 16; u++) {
            ulonglong2 c2 = cp2[u];
            dA0 = fma2(c2.x, zA[2*u],   dA0);
            dA1 = fma2(c2.y, zA[2*u+1], dA1);
            dB0 = fma2(c2.x, zB[2*u],   dB0);
            dB1 = fma2(c2.y, zB[2*u+1], dB1);
        }
        float2 da = unpack2(add2(dA0, dA1));
        float2 db = unpack2(add2(dB0, dB1));
        float cq = csq[k];
        float distA = zsqA - 2.f*(da.x + da.y) + cq;
        float distB = zsqB - 2.f*(db.x + db.y) + cq;
        if (distA < bestA) { bestA = distA; idxA = k; }
        if (distB < bestB) { bestB = distB; idxB = k; }
    }

    float lsum = 0.f;
#pragma unroll
    for (int u = 0; u < 32; u++) {
        float2 za = unpack2(zA[u]);
        float2 zb = unpack2(zB[u]);
        float ca0 = cb_s[idxA*VQ_DIM + 2*u], ca1 = cb_s[idxA*VQ_DIM + 2*u+1];
        float cb0 = cb_s[idxB*VQ_DIM + 2*u], cb1 = cb_s[idxB*VQ_DIM + 2*u+1];
        float dA0 = za.x - ca0, dA1 = za.y - ca1;
        float dB0 = zb.x - cb0, dB1 = zb.y - cb1;
        lsum += dA0*dA0 + dA1*dA1 + dB0*dB0 + dB1*dB1;
    }
    idx_out[s0] = (float)idxA;
    idx_out[s1] = (float)idxB;

    __shared__ float red[256];
    red[tid] = lsum; __syncthreads();
    for (int o = 128; o > 0; o >>= 1) {
        if (tid < o) red[tid] += red[tid + o];
        __syncthreads();
    }
    if (tid == 0) losspart[blockIdx.x] = red[0];
}

__global__ void loss_finalize_kernel(const float* __restrict__ losspart,
                                     float* __restrict__ out_losses)
{
    __shared__ float red[256];
    red[threadIdx.x] = (threadIdx.x < 128) ? losspart[threadIdx.x] : 0.f;
    __syncthreads();
    for (int o = 128; o > 0; o >>= 1) {
        if (threadIdx.x < o) red[threadIdx.x] += red[threadIdx.x + o];
        __syncthreads();
    }
    if (threadIdx.x == 0) {
        float m = red[0] / (65536.f * 64.f);
        out_losses[0] = m;
        out_losses[1] = m;
    }
}

// ---------------- dec2 quad-centric, ci-split x4 ----------------
__global__ void dec2_kernel(const float* __restrict__ in, const float* __restrict__ w,
                            const float* __restrict__ bias, const float* __restrict__ scale,
                            const float* __restrict__ shift, float* __restrict__ out)
{
    extern __shared__ float sm[];
    float* w_s  = sm;
    float* in_s = sm + 3456;
    float* sc_s = sm + 17280;
    float* sh_s = sm + 17408;
    float* red  = sm + 17536;
    int n = blockIdx.y; int tile = blockIdx.x;
    int OH0 = (tile >> 3) * 16, OW0 = (tile & 7) * 16;
    int IH0 = OH0 >> 1, IW0 = OW0 >> 1;
    int tid = threadIdx.x;
    for (int i = tid; i < 3456; i += 256) w_s[i] = w[i];
    for (int i = tid; i < 128; i += 256) { sc_s[i] = scale[i]; sh_s[i] = shift[i]; }
    __syncthreads();
    for (int i = tid; i < 128*108; i += 256) {
        int ci = i / 108; int rem = i - ci*108; int rr = rem / 12; int cc = rem - rr*12;
        int ih = IH0 + rr, iw = IW0 + cc;
        float v = 0.f;
        if (cc < 9 && ih < 64 && iw < 64) {
            float raw = in[((size_t)(n*128 + ci)*64 + ih)*64 + iw];
            v = fmaxf(fmaf(raw, sc_s[ci], sh_s[ci]), 0.f);
        }
        in_s[i] = v;
    }
    __syncthreads();

    int q = tid & 63, qy = q >> 3, qx = q & 7;
    int cisub = tid >> 6;
    float acc[4][3];
#pragma unroll
    for (int p = 0; p < 4; p++)
#pragma unroll
        for (int co = 0; co < 3; co++) acc[p][co] = 0.f;

    int ci0 = cisub * 32;
#pragma unroll 4
    for (int ci = ci0; ci < ci0 + 32; ci++) {
        const float* base = in_s + ci*108 + qy*12 + qx;
        float v00 = base[0], v01 = base[1], v10 = base[12], v11 = base[13];
        const float* wp = w_s + ci*27;
#pragma unroll
        for (int co = 0; co < 3; co++) {
            const float* wc = wp + co*9;
            acc[0][co] += wc[4]*v00;
            acc[1][co] += wc[3]*v01 + wc[5]*v00;
            acc[2][co] += wc[1]*v10 + wc[7]*v00;
            acc[3][co] += wc[0]*v11 + wc[2]*v10 + wc[6]*v01 + wc[8]*v00;
        }
    }
#pragma unroll
    for (int p = 0; p < 4; p++)
#pragma unroll
        for (int co = 0; co < 3; co++)
            red[(p*3 + co)*256 + tid] = acc[p][co];
    __syncthreads();
    if (tid < 64) {
#pragma unroll
        for (int p = 0; p < 4; p++) {
            int ph = p >> 1, pw = p & 1;
            int oh = OH0 + 2*qy + ph, ow = OW0 + 2*qx + pw;
#pragma unroll
            for (int co = 0; co < 3; co++) {
                int j = p*3 + co;
                float s = red[j*256 + tid] + red[j*256 + tid + 64]
                        + red[j*256 + tid + 128] + red[j*256 + tid + 192];
                out[((size_t)(n*3 + co)*128 + oh)*128 + ow] = tanhf(s + bias[co]);
            }
        }
    }
}

// ---------------- host launch ----------------
static float* sym_addr(const void* sym)
{
    void* p = nullptr;
    cudaGetSymbolAddress(&p, sym);
    return (float*)p;
}

extern "C" void kernel_launch(void* const* d_in, const int* in_sizes, int n_in,
                              void* d_out, int out_size)
{
    const float* x       = (const float*)d_in[0];
    const float* enc1_w  = (const float*)d_in[1];
    const float* enc1_b  = (const float*)d_in[2];
    const float* bn1_g   = (const float*)d_in[3];
    const float* bn1_b   = (const float*)d_in[4];
    const float* enc2_w  = (const float*)d_in[5];
    const float* enc2_b  = (const float*)d_in[6];
    const float* pre_w   = (const float*)d_in[7];
    const float* pre_b   = (const float*)d_in[8];
    const float* codebook= (const float*)d_in[9];
    const float* post_w  = (const float*)d_in[10];
    const float* post_b  = (const float*)d_in[11];
    const float* dec1_w  = (const float*)d_in[12];
    const float* dec1_b  = (const float*)d_in[13];
    const float* dbn1_g  = (const float*)d_in[14];
    const float* dbn1_b  = (const float*)d_in[15];
    const float* dec2_w  = (const float*)d_in[16];
    const float* dec2_b  = (const float*)d_in[17];

    float* out = (float*)d_out;
    float* out_losses = out + RECON_ELEMS;
    float* out_idx    = out + RECON_ELEMS + 2;

    float* h1  = sym_addr(g_h1);
    __nv_bfloat16* h1hi; { void* p; cudaGetSymbolAddress(&p, g_h1hi); h1hi = (__nv_bfloat16*)p; }
    __nv_bfloat16* h1lo; { void* p; cudaGetSymbolAddress(&p, g_h1lo); h1lo = (__nv_bfloat16*)p; }
    __nv_bfloat16* w2chi; { void* p; cudaGetSymbolAddress(&p, g_w2chi); w2chi = (__nv_bfloat16*)p; }
    __nv_bfloat16* w2clo; { void* p; cudaGetSymbolAddress(&p, g_w2clo); w2clo = (__nv_bfloat16*)p; }
    __nv_bfloat16* wd1hi; { void* p; cudaGetSymbolAddress(&p, g_wd1hi); wd1hi = (__nv_bfloat16*)p; }
    __nv_bfloat16* wd1lo; { void* p; cudaGetSymbolAddress(&p, g_wd1lo); wd1lo = (__nv_bfloat16*)p; }
    __nv_bfloat16* dhi; { void* p; cudaGetSymbolAddress(&p, g_dhi); dhi = (__nv_bfloat16*)p; }
    __nv_bfloat16* dlo; { void* p; cudaGetSymbolAddress(&p, g_dlo); dlo = (__nv_bfloat16*)p; }
    __nv_bfloat16* tabhi; { void* p; cudaGetSymbolAddress(&p, g_tabhi); tabhi = (__nv_bfloat16*)p; }
    __nv_bfloat16* tablo; { void* p; cudaGetSymbolAddress(&p, g_tablo); tablo = (__nv_bfloat16*)p; }
    float* h2  = sym_addr(g_h2);
    float* z   = sym_addr(g_z);
    float* d1  = sym_addr(g_d1);
    float* psum = sym_addr(g_psum);
    float* psq  = sym_addr(g_psq);
    float* sc   = sym_addr(g_scale);
    float* sh   = sym_addr(g_shift);
    float* lp   = sym_addr(g_losspart);

    const unsigned MM_SMEM = 2*MM_STAGE + 1024;   // 132096
    cudaFuncSetAttribute(conv2_mma_kernel, cudaFuncAttributeMaxDynamicSharedMemorySize, MM_SMEM);
    cudaFuncSetAttribute(dec1_mma_kernel,  cudaFuncAttributeMaxDynamicSharedMemorySize, MM_SMEM);
    cudaFuncSetAttribute(vq_kernel,   cudaFuncAttributeMaxDynamicSharedMemorySize, 133120);
    cudaFuncSetAttribute(dec2_kernel, cudaFuncAttributeMaxDynamicSharedMemorySize, 84480);

    const float inv_cnt = 1.f / 262144.f;

    // encoder (ordered so launch #6 = conv2_mma gets profiled)
    conv1_kernel<<<dim3(4,4,64), 256>>>(x, enc1_w, enc1_b, h1);            // 1
    bn_stats_nhwc<<<1024, 256>>>(h1, psum, psq, 1024);                     // 2
    bn_finalize_par<<<128, 256>>>(psum, psq, bn1_g, bn1_b, sc, sh, 1024, inv_cnt); // 3
    bnrelu_split_kernel<<<32768, 256>>>(h1, h1hi, h1lo, sc, sh);           // 4
    wtrans_conv2_bf16<<<1152, 256>>>(enc2_w, w2chi, w2clo);                // 5
    conv2_mma_kernel<<<dim3(8,2,64), 256, MM_SMEM>>>(h1hi, h1lo, w2chi, w2clo, enc2_b, h2); // 6 <- ncu
    wtrans_dec1_bf16<<<1152, 256>>>(dec1_w, wd1hi, wd1lo);
    table_kernel<<<512, 256>>>(post_w, post_b, codebook, tabhi, tablo);
    pre_kernel<<<dim3(4,2,64), 256>>>(h2, pre_w, pre_b, z);

    // VQ + gather
    vq_kernel<<<128, 256, 133120>>>(z, codebook, out_idx, lp);
    loss_finalize_kernel<<<1,256>>>(lp, out_losses);
    gather_d<<<2048, 256>>>(out_idx, (const uint4*)tabhi, (const uint4*)tablo,
                            (uint4*)dhi, (uint4*)dlo);

    // decoder (dec1 emits BN partials itself)
    dec1_mma_kernel<<<dim3(8,4,64), 256, MM_SMEM>>>(dhi, dlo, wd1hi, wd1lo, dec1_b, d1, psum, psq);
    bn_finalize_par<<<128, 256>>>(psum, psq, dbn1_g, dbn1_b, sc, sh, 2048, inv_cnt);
    dec2_kernel<<<dim3(64,64), 256, 84480>>>(d1, dec2_w, dec2_b, sc, sh, out);

    (void)in_sizes; (void)n_in; (void)out_size;
}